// round 11
// baseline (speedup 1.0000x reference)
#include <cuda_runtime.h>
#include <cuda_bf16.h>
#include <cuda_fp16.h>
#include <cstdint>

// Problem constants
#define NPOS   32768          // B*L = 8*4096
#define LSEQ   4096
#define EDIM   128
#define HDIM   256
#define DDIM   64
#define KCODE  512
#define VOCAB  4096
#define LN_EPS 1e-5f

typedef __nv_bfloat16 bf16;

#define LO_SCALE   2048.0f
#define LO_INV     (1.0f / 2048.0f)

// ---------------- scratch (static device globals; no allocation) -------------
__device__ float g_h2 [NPOS * HDIM];    // encoder conv2 output (fp32)
__device__ float g_z  [NPOS * DDIM];    // z_e after LN
__device__ int   g_codes[NPOS];
__device__ float g_cnorm[KCODE];
__device__ float g_commit[NPOS / 64];
// encoder fp16 two-split activations (lo scaled by 2048)
__device__ __align__(16) half g_ebh[NPOS * EDIM];
__device__ __align__(16) half g_ebm[NPOS * EDIM];
__device__ __align__(16) half g_e1h[NPOS * HDIM];
__device__ __align__(16) half g_e1m[NPOS * HDIM];
// encoder fp16 two-split packed weights
__device__ __align__(16) half g_w1eh[HDIM * EDIM * 3];
__device__ __align__(16) half g_w1em[HDIM * EDIM * 3];
__device__ __align__(16) half g_w2eh[HDIM * HDIM * 3];
__device__ __align__(16) half g_w2em[HDIM * HDIM * 3];
// decoder bf16 hi/lo split activations
__device__ __align__(16) bf16 g_zqhi[NPOS * DDIM];
__device__ __align__(16) bf16 g_zqlo[NPOS * DDIM];
__device__ __align__(16) bf16 g_d1hi[NPOS * HDIM];
__device__ __align__(16) bf16 g_d1lo[NPOS * HDIM];
__device__ __align__(16) bf16 g_d2hi[NPOS * HDIM];
__device__ __align__(16) bf16 g_d2lo[NPOS * HDIM];
__device__ __align__(16) bf16 g_ahi[NPOS * EDIM];
__device__ __align__(16) bf16 g_alo[NPOS * EDIM];
// decoder bf16 hi/lo split packed weights
__device__ __align__(16) bf16 g_w1hi[HDIM * DDIM];
__device__ __align__(16) bf16 g_w1lo[HDIM * DDIM];
__device__ __align__(16) bf16 g_w2hi[HDIM * HDIM * 3];
__device__ __align__(16) bf16 g_w2lo[HDIM * HDIM * 3];
__device__ __align__(16) bf16 g_w3hi[EDIM * HDIM];
__device__ __align__(16) bf16 g_w3lo[EDIM * HDIM];
__device__ __align__(16) bf16 g_bhi[VOCAB * EDIM];
__device__ __align__(16) bf16 g_blo[VOCAB * EDIM];

__device__ __forceinline__ uint32_t smem_to_u32(const void* smem_ptr) {
    uint32_t addr;
    asm("{ .reg .u64 tmp; cvta.to.shared.u64 tmp, %1; cvt.u32.u64 %0, tmp; }"
        : "=r"(addr) : "l"(smem_ptr));
    return addr;
}

__device__ __forceinline__ void cp_async16(uint32_t saddr, const void* gptr, int src_bytes) {
    asm volatile("cp.async.cg.shared.global [%0], [%1], 16, %2;"
                 :: "r"(saddr), "l"(gptr), "r"(src_bytes));
}

// fp16 two-split: x = h + (m/2048); m kept in normal fp16 range
__device__ __forceinline__ void split2h(float x, half& h, half& m) {
    h = __float2half_rn(x);
    m = __float2half_rn((x - __half2float(h)) * LO_SCALE);
}

// ---------------- embedding lookup with fused fp16 two-split ------------------
__global__ void embed_split2h(const int* __restrict__ x,
                              const float* __restrict__ tok,
                              half* __restrict__ H, half* __restrict__ M)
{
    int idx = blockIdx.x * blockDim.x + threadIdx.x;   // NPOS*32 float4s
    int n = idx >> 5;
    int j = idx & 31;
    int t = x[n];
    float4 v = reinterpret_cast<const float4*>(tok)[t * 32 + j];
    half h0,m0,h1,m1,h2,m2,h3,m3;
    split2h(v.x,h0,m0); split2h(v.y,h1,m1);
    split2h(v.z,h2,m2); split2h(v.w,h3,m3);
    __half2 p;
    p.x=h0; p.y=h1; reinterpret_cast<__half2*>(H)[n*64+j*2+0]=p;
    p.x=h2; p.y=h3; reinterpret_cast<__half2*>(H)[n*64+j*2+1]=p;
    p.x=m0; p.y=m1; reinterpret_cast<__half2*>(M)[n*64+j*2+0]=p;
    p.x=m2; p.y=m3; reinterpret_cast<__half2*>(M)[n*64+j*2+1]=p;
}

// ---------------- weight pack + splits ----------------------------------------
template<int CIN, int KW, int COUT>
__global__ void pack_split(const float* __restrict__ W,
                           bf16* __restrict__ Hi, bf16* __restrict__ Lo)
{
    int idx = blockIdx.x * blockDim.x + threadIdx.x;
    if (idx >= COUT * KW * CIN) return;
    int o   = idx / (KW * CIN);
    int rem = idx - o * (KW * CIN);
    int tap = rem / CIN;
    int ci  = rem - tap * CIN;
    float w = W[(size_t)o * CIN * KW + ci * KW + tap];
    bf16 h = __float2bfloat16(w);
    Hi[idx] = h;
    Lo[idx] = __float2bfloat16(w - __bfloat162float(h));
}

template<int CIN, int KW, int COUT>
__global__ void pack_split2h(const float* __restrict__ W,
                             half* __restrict__ H, half* __restrict__ M)
{
    int idx = blockIdx.x * blockDim.x + threadIdx.x;
    if (idx >= COUT * KW * CIN) return;
    int o   = idx / (KW * CIN);
    int rem = idx - o * (KW * CIN);
    int tap = rem / CIN;
    int ci  = rem - tap * CIN;
    float w = W[(size_t)o * CIN * KW + ci * KW + tap];
    half h, m;
    split2h(w, h, m);
    H[idx] = h; M[idx] = m;
}

// ---------------- encoder head: conv1x1 (256->64) + LayerNorm(D=64) ---------
__global__ void __launch_bounds__(256)
enc_head_ln(const float* __restrict__ X, const float* __restrict__ W,
            const float* __restrict__ Bias,
            const float* __restrict__ G, const float* __restrict__ Bt,
            float* __restrict__ Z)
{
    constexpr int CIN = 256;
    __shared__ float As[32][66];
    __shared__ float Bs[32][66];
    __shared__ float Zs[64][66];

    const int pm0 = blockIdx.x * 64;
    const int tid = threadIdx.x;
    const int tx = tid & 15, ty = tid >> 4;
    const int rr = tid & 31;
    const int mrow = tid >> 5;

    float acc[4][4];
#pragma unroll
    for (int i = 0; i < 4; i++)
#pragma unroll
        for (int j = 0; j < 4; j++) acc[i][j] = 0.f;

    for (int r0 = 0; r0 < CIN; r0 += 32) {
        const int ci = r0 + rr;
#pragma unroll
        for (int i = 0; i < 8; i++) {
            const int m = mrow + i * 8;
            As[rr][m] = X[(size_t)(pm0 + m) * CIN + ci];
        }
#pragma unroll
        for (int i = 0; i < 8; i++) {
            const int n = mrow + i * 8;
            Bs[rr][n] = W[(size_t)n * CIN + ci];
        }
        __syncthreads();
#pragma unroll
        for (int kk = 0; kk < 32; kk++) {
            float a[4], b[4];
#pragma unroll
            for (int i = 0; i < 4; i++) a[i] = As[kk][ty * 4 + i];
#pragma unroll
            for (int j = 0; j < 4; j++) b[j] = Bs[kk][tx * 4 + j];
#pragma unroll
            for (int i = 0; i < 4; i++)
#pragma unroll
                for (int j = 0; j < 4; j++)
                    acc[i][j] = fmaf(a[i], b[j], acc[i][j]);
        }
        __syncthreads();
    }
#pragma unroll
    for (int i = 0; i < 4; i++)
#pragma unroll
        for (int j = 0; j < 4; j++)
            Zs[ty * 4 + i][tx * 4 + j] = acc[i][j] + Bias[tx * 4 + j];
    __syncthreads();

    const int lane = tid & 31, w = tid >> 5;
#pragma unroll
    for (int q = 0; q < 8; q++) {
        const int m = w * 8 + q;
        float v0 = Zs[m][lane];
        float v1 = Zs[m][lane + 32];
        float s = v0 + v1;
#pragma unroll
        for (int off = 16; off > 0; off >>= 1)
            s += __shfl_xor_sync(0xffffffffu, s, off);
        float mu = s * (1.f / 64.f);
        float d0 = v0 - mu, d1 = v1 - mu;
        float sq = __fadd_rn(__fmul_rn(d0, d0), __fmul_rn(d1, d1));
#pragma unroll
        for (int off = 16; off > 0; off >>= 1)
            sq += __shfl_xor_sync(0xffffffffu, sq, off);
        float var = sq * (1.f / 64.f);
        float rs  = rsqrtf(var + LN_EPS);
        const int p = pm0 + m;
        Z[(size_t)p * 64 + lane]      = d0 * rs * G[lane]      + Bt[lane];
        Z[(size_t)p * 64 + lane + 32] = d1 * rs * G[lane + 32] + Bt[lane + 32];
    }
}

// ---------------- codebook norms (no FMA: match sum(c*c)) --------------------
__global__ void cnorm_kernel(const float* __restrict__ CB, float* __restrict__ CN)
{
    int c = blockIdx.x * blockDim.x + threadIdx.x;
    if (c < KCODE) {
        float s = 0.f;
        for (int d = 0; d < DDIM; d++) {
            float v = CB[c * DDIM + d];
            s = __fadd_rn(s, __fmul_rn(v, v));
        }
        CN[c] = s;
    }
}

// ---------------- VQ: argmin over codes + commit-loss partials ---------------
__global__ void __launch_bounds__(256)
vq_kernel(const float* __restrict__ Z, const float* __restrict__ CB,
          const float* __restrict__ CN, int* __restrict__ Codes,
          float* __restrict__ CommitPart)
{
    __shared__ float Zt[64][66];
    __shared__ float Cs[64][66];
    __shared__ float znS[64];
    __shared__ float cvals[64];

    const int pm0 = blockIdx.x * 64;
    const int tid = threadIdx.x;
    const int tx = tid & 15, ty = tid >> 4;

#pragma unroll
    for (int i = 0; i < 16; i++) {
        int idx = tid + i * 256;
        int m = idx >> 6, d = idx & 63;
        Zt[d][m] = Z[(size_t)(pm0 + m) * 64 + d];
    }
    __syncthreads();

    if (tid < 64) {
        const int m = tid;
        float s = 0.f;
        for (int d = 0; d < 64; d++) {
            float v = Zt[d][m];
            s = __fadd_rn(s, __fmul_rn(v, v));
        }
        znS[m] = s;
    }
    __syncthreads();

    float zm[4];
#pragma unroll
    for (int i = 0; i < 4; i++) zm[i] = znS[ty * 4 + i];

    float minv[4]; int mini[4];
#pragma unroll
    for (int i = 0; i < 4; i++) { minv[i] = 3.4e38f; mini[i] = 0; }

    for (int c0 = 0; c0 < KCODE; c0 += 64) {
        __syncthreads();
#pragma unroll
        for (int i = 0; i < 16; i++) {
            int idx = tid + i * 256;
            int c = idx >> 6, d = idx & 63;
            Cs[d][c] = CB[(size_t)(c0 + c) * 64 + d];
        }
        __syncthreads();

        float dot[4][4];
#pragma unroll
        for (int i = 0; i < 4; i++)
#pragma unroll
            for (int j = 0; j < 4; j++) dot[i][j] = 0.f;
#pragma unroll
        for (int kk = 0; kk < 64; kk++) {
            float a[4], b[4];
#pragma unroll
            for (int i = 0; i < 4; i++) a[i] = Zt[kk][ty * 4 + i];
#pragma unroll
            for (int j = 0; j < 4; j++) b[j] = Cs[kk][tx * 4 + j];
#pragma unroll
            for (int i = 0; i < 4; i++)
#pragma unroll
                for (int j = 0; j < 4; j++)
                    dot[i][j] = fmaf(a[i], b[j], dot[i][j]);
        }
#pragma unroll
        for (int j = 0; j < 4; j++) {
            const int c = c0 + tx * 4 + j;
            const float cn = CN[c];
#pragma unroll
            for (int i = 0; i < 4; i++) {
                float t    = __fadd_rn(zm[i], -__fmul_rn(2.f, dot[i][j]));
                float dist = __fadd_rn(t, cn);
                if (dist < minv[i]) { minv[i] = dist; mini[i] = c; }
            }
        }
    }
    __syncthreads();

    float* redv = &Cs[0][0];
    int*   redi = reinterpret_cast<int*>(&Cs[0][0]) + 1024;
#pragma unroll
    for (int i = 0; i < 4; i++) {
        const int m = ty * 4 + i;
        redv[m * 16 + tx] = minv[i];
        redi[m * 16 + tx] = mini[i];
    }
    __syncthreads();
    if (tid < 64) {
        const int m = tid;
        float bv = redv[m * 16];
        int   bi = redi[m * 16];
        for (int t = 1; t < 16; t++) {
            float v = redv[m * 16 + t];
            int  ix = redi[m * 16 + t];
            if (v < bv || (v == bv && ix < bi)) { bv = v; bi = ix; }
        }
        Codes[pm0 + m] = bi;
        cvals[m] = bv;
    }
    __syncthreads();
    if (tid == 0) {
        float s = 0.f;
        for (int m = 0; m < 64; m++) s += cvals[m];
        CommitPart[blockIdx.x] = s;
    }
}

// ---------------- gather z_q with fused bf16 hi/lo split ----------------------
__global__ void gather_zq_split(const int* __restrict__ codes,
                                const float* __restrict__ CB,
                                bf16* __restrict__ Hi, bf16* __restrict__ Lo)
{
    int idx = blockIdx.x * blockDim.x + threadIdx.x;   // NPOS*16 float4s
    int n = idx >> 4;
    int j = idx & 15;
    float4 v = reinterpret_cast<const float4*>(CB)[codes[n] * 16 + j];
    bf16 h0 = __float2bfloat16(v.x), h1 = __float2bfloat16(v.y);
    bf16 h2 = __float2bfloat16(v.z), h3 = __float2bfloat16(v.w);
    __nv_bfloat162 hh0; hh0.x = h0; hh0.y = h1;
    __nv_bfloat162 hh1; hh1.x = h2; hh1.y = h3;
    __nv_bfloat162 ll0; ll0.x = __float2bfloat16(v.x - __bfloat162float(h0));
    ll0.y = __float2bfloat16(v.y - __bfloat162float(h1));
    __nv_bfloat162 ll1; ll1.x = __float2bfloat16(v.z - __bfloat162float(h2));
    ll1.y = __float2bfloat16(v.w - __bfloat162float(h3));
    reinterpret_cast<__nv_bfloat162*>(Hi)[n * 32 + j * 2 + 0] = hh0;
    reinterpret_cast<__nv_bfloat162*>(Hi)[n * 32 + j * 2 + 1] = hh1;
    reinterpret_cast<__nv_bfloat162*>(Lo)[n * 32 + j * 2 + 0] = ll0;
    reinterpret_cast<__nv_bfloat162*>(Lo)[n * 32 + j * 2 + 1] = ll1;
}

// ---------------- mma helpers -------------------------------------------------
__device__ __forceinline__ void ldsm_x4(uint32_t* r, uint32_t addr) {
    asm volatile("ldmatrix.sync.aligned.m8n8.x4.shared.b16 {%0,%1,%2,%3}, [%4];"
                 : "=r"(r[0]), "=r"(r[1]), "=r"(r[2]), "=r"(r[3]) : "r"(addr));
}
__device__ __forceinline__ void mma16816(float* d, const uint32_t* a,
                                         uint32_t b0, uint32_t b1) {
    asm volatile(
        "mma.sync.aligned.m16n8k16.row.col.f32.bf16.bf16.f32 "
        "{%0,%1,%2,%3}, {%4,%5,%6,%7}, {%8,%9}, {%0,%1,%2,%3};"
        : "+f"(d[0]), "+f"(d[1]), "+f"(d[2]), "+f"(d[3])
        : "r"(a[0]), "r"(a[1]), "r"(a[2]), "r"(a[3]), "r"(b0), "r"(b1));
}
__device__ __forceinline__ void mma16816h(float* d, const uint32_t* a,
                                          uint32_t b0, uint32_t b1) {
    asm volatile(
        "mma.sync.aligned.m16n8k16.row.col.f32.f16.f16.f32 "
        "{%0,%1,%2,%3}, {%4,%5,%6,%7}, {%8,%9}, {%0,%1,%2,%3};"
        : "+f"(d[0]), "+f"(d[1]), "+f"(d[2]), "+f"(d[3])
        : "r"(a[0]), "r"(a[1]), "r"(a[2]), "r"(a[3]), "r"(b0), "r"(b1));
}

// ---------------- generic bf16x3 (hi/lo) tensor conv, 3-buffer pipeline ------
// Three 64KB smem buffers; ONE __syncthreads per chunk. Per-nc B fragment load
// (consumed by 4 MMAs immediately) to cut live registers.
// LNF: fuse LayerNorm(COUT=128) + bf16 split into the epilogue.
#define TC_SMEM 196608

template<int CIN, int KW, int COUT, bool RELU, bool WF32, bool WSPLIT, bool LNF>
__global__ void __launch_bounds__(256)
tconv(const bf16* __restrict__ Ahi, const bf16* __restrict__ Alo,
      const bf16* __restrict__ Whi, const bf16* __restrict__ Wlo,
      const float* __restrict__ Bias,
      const float* __restrict__ LG, const float* __restrict__ LB,
      float* __restrict__ Yf, bf16* __restrict__ Yhi, bf16* __restrict__ Ylo)
{
    constexpr int KTOT = CIN * KW;
    constexpr int NCH  = KTOT / 64;
    constexpr int PAD  = (KW == 3) ? 1 : 0;

    extern __shared__ char smem[];
    const int tid = threadIdx.x;
    const int pm0 = blockIdx.x * 128;
    const int nv0 = blockIdx.y * 128;

    const int wid = tid >> 5, lane = tid & 31;
    const int wm = (wid >> 1) * 32;
    const int wn = (wid & 1) * 64;
    const int lr = lane & 7, lq = lane >> 3;

    float acc[2][8][4];
#pragma unroll
    for (int mi = 0; mi < 2; mi++)
#pragma unroll
        for (int ni = 0; ni < 8; ni++)
#pragma unroll
            for (int e = 0; e < 4; e++) acc[mi][ni][e] = 0.f;

    const uint4* A4h = reinterpret_cast<const uint4*>(Ahi);
    const uint4* A4l = reinterpret_cast<const uint4*>(Alo);
    const uint4* B4h = reinterpret_cast<const uint4*>(Whi);
    const uint4* B4l = reinterpret_cast<const uint4*>(Wlo);

    const uint32_t sb = smem_to_u32(smem);

    auto load_chunk = [&](int ch, int buf) {
        const uint32_t bo = (uint32_t)buf * 65536u;
        const int tap = (ch * 64) / CIN;
        const int ci0 = (ch * 64) % CIN;
#pragma unroll
        for (int i = 0; i < 4; i++) {
            int idx = tid + i * 256;
            int row = idx >> 3, c = idx & 7;
            int p = pm0 + row;
            bool ok = true;
            if (KW == 3) {
                int ls = (p & (LSEQ - 1)) + tap - PAD;
                ok = ((unsigned)ls < (unsigned)LSEQ);
            }
            size_t gi = ok ? ((size_t)(p + tap - PAD) * (CIN / 8) + (ci0 / 8) + c) : 0;
            int nb = ok ? 16 : 0;
            int pc = (c ^ row) & 7;
            uint32_t so = (uint32_t)(row * 128 + pc * 16);
            cp_async16(sb + bo + so,          A4h + gi, nb);
            cp_async16(sb + bo + 16384u + so, A4l + gi, nb);
        }
#pragma unroll
        for (int i = 0; i < 4; i++) {
            int idx = tid + i * 256;
            int row = idx >> 3, c = idx & 7;
            size_t gi = (size_t)(nv0 + row) * (KTOT / 8) + ch * 8 + c;
            int pc = (c ^ row) & 7;
            uint32_t so = (uint32_t)(row * 128 + pc * 16);
            cp_async16(sb + bo + 32768u + so, B4h + gi, 16);
            cp_async16(sb + bo + 49152u + so, B4l + gi, 16);
        }
        asm volatile("cp.async.commit_group;");
    };

    load_chunk(0, 0);
    if (1 < NCH) load_chunk(1, 1);

    for (int ch = 0; ch < NCH; ch++) {
        if (ch + 1 < NCH)
            asm volatile("cp.async.wait_group 1;");
        else
            asm volatile("cp.async.wait_group 0;");
        __syncthreads();
        if (ch + 2 < NCH) load_chunk(ch + 2, (ch + 2) % 3);

        const uint32_t bo = (uint32_t)(ch % 3) * 65536u;
        const uint32_t aB3[3] = { sb + bo, sb + bo, sb + bo + 16384u };
        const uint32_t bB3[3] = { sb + bo + 32768u, sb + bo + 49152u, sb + bo + 32768u };
#pragma unroll
        for (int s = 0; s < 3; s++) {
            const uint32_t aB = aB3[s];
            const uint32_t bB = bB3[s];
#pragma unroll
            for (int k16 = 0; k16 < 4; k16++) {
                const int kc0 = k16 * 2;
                uint32_t a[2][4];
#pragma unroll
                for (int mi = 0; mi < 2; mi++) {
                    int row = wm + mi * 16 + lr + (lq & 1) * 8;
                    int kc  = kc0 + (lq >> 1);
                    int pc  = (kc ^ row) & 7;
                    ldsm_x4(a[mi], aB + row * 128 + pc * 16);
                }
#pragma unroll
                for (int nc = 0; nc < 4; nc++) {
                    uint32_t b[4];
                    int row = wn + nc * 16 + lr + (lq >> 1) * 8;
                    int kc  = kc0 + (lq & 1);
                    int pc  = (kc ^ row) & 7;
                    ldsm_x4(b, bB + row * 128 + pc * 16);
                    mma16816(acc[0][nc * 2 + 0], a[0], b[0], b[1]);
                    mma16816(acc[0][nc * 2 + 1], a[0], b[2], b[3]);
                    mma16816(acc[1][nc * 2 + 0], a[1], b[0], b[1]);
                    mma16816(acc[1][nc * 2 + 1], a[1], b[2], b[3]);
                }
            }
        }
    }

    const int gid = lane >> 2, tig = lane & 3;
    // bias (+relu) into acc in place
#pragma unroll
    for (int mi = 0; mi < 2; mi++)
#pragma unroll
        for (int ni = 0; ni < 8; ni++) {
            const int n = nv0 + wn + ni * 8 + tig * 2;
            const float2 bv = *reinterpret_cast<const float2*>(Bias + n);
            acc[mi][ni][0] += bv.x;  acc[mi][ni][1] += bv.y;
            acc[mi][ni][2] += bv.x;  acc[mi][ni][3] += bv.y;
            if (RELU) {
#pragma unroll
                for (int e = 0; e < 4; e++) acc[mi][ni][e] = fmaxf(acc[mi][ni][e], 0.f);
            }
        }

    if (LNF) {
        // fused LayerNorm over COUT=128 (full row within CTA) + bf16 split store
        float* red = reinterpret_cast<float*>(smem);   // [128][2] + [128][2]
        __syncthreads();   // all ldsm on smem buffers done before reuse
        // pass 1: row sums
        float ps[2][2];
#pragma unroll
        for (int mi = 0; mi < 2; mi++) { ps[mi][0] = 0.f; ps[mi][1] = 0.f; }
#pragma unroll
        for (int mi = 0; mi < 2; mi++)
#pragma unroll
            for (int ni = 0; ni < 8; ni++) {
                ps[mi][0] += acc[mi][ni][0] + acc[mi][ni][1];
                ps[mi][1] += acc[mi][ni][2] + acc[mi][ni][3];
            }
#pragma unroll
        for (int mi = 0; mi < 2; mi++)
#pragma unroll
            for (int h = 0; h < 2; h++) {
                ps[mi][h] += __shfl_xor_sync(0xffffffffu, ps[mi][h], 1);
                ps[mi][h] += __shfl_xor_sync(0xffffffffu, ps[mi][h], 2);
            }
        if (tig == 0) {
#pragma unroll
            for (int mi = 0; mi < 2; mi++)
#pragma unroll
                for (int h = 0; h < 2; h++) {
                    int row = wm + mi * 16 + gid + h * 8;
                    red[row * 2 + (wn >> 6)] = ps[mi][h];
                }
        }
        __syncthreads();
        float mu[2][2];
#pragma unroll
        for (int mi = 0; mi < 2; mi++)
#pragma unroll
            for (int h = 0; h < 2; h++) {
                int row = wm + mi * 16 + gid + h * 8;
                mu[mi][h] = (red[row * 2] + red[row * 2 + 1]) * (1.f / 128.f);
            }
        // pass 2: centered sumsq (separate region, no barrier needed before write)
        float q[2][2];
#pragma unroll
        for (int mi = 0; mi < 2; mi++) { q[mi][0] = 0.f; q[mi][1] = 0.f; }
#pragma unroll
        for (int mi = 0; mi < 2; mi++)
#pragma unroll
            for (int ni = 0; ni < 8; ni++) {
                float d0 = acc[mi][ni][0] - mu[mi][0];
                float d1 = acc[mi][ni][1] - mu[mi][0];
                float d2 = acc[mi][ni][2] - mu[mi][1];
                float d3 = acc[mi][ni][3] - mu[mi][1];
                q[mi][0] += d0 * d0 + d1 * d1;
                q[mi][1] += d2 * d2 + d3 * d3;
            }
#pragma unroll
        for (int mi = 0; mi < 2; mi++)
#pragma unroll
            for (int h = 0; h < 2; h++) {
                q[mi][h] += __shfl_xor_sync(0xffffffffu, q[mi][h], 1);
                q[mi][h] += __shfl_xor_sync(0xffffffffu, q[mi][h], 2);
            }
        if (tig == 0) {
#pragma unroll
            for (int mi = 0; mi < 2; mi++)
#pragma unroll
                for (int h = 0; h < 2; h++) {
                    int row = wm + mi * 16 + gid + h * 8;
                    red[256 + row * 2 + (wn >> 6)] = q[mi][h];
                }
        }
        __syncthreads();
        float rs[2][2];
#pragma unroll
        for (int mi = 0; mi < 2; mi++)
#pragma unroll
            for (int h = 0; h < 2; h++) {
                int row = wm + mi * 16 + gid + h * 8;
                float var = (red[256 + row * 2] + red[256 + row * 2 + 1]) * (1.f / 128.f);
                rs[mi][h] = rsqrtf(var + LN_EPS);
            }
        // normalize + split store
#pragma unroll
        for (int mi = 0; mi < 2; mi++) {
            const int m0 = pm0 + wm + mi * 16 + gid;
#pragma unroll
            for (int ni = 0; ni < 8; ni++) {
                const int c = wn + ni * 8 + tig * 2;
                const float2 gv = *reinterpret_cast<const float2*>(LG + c);
                const float2 bb = *reinterpret_cast<const float2*>(LB + c);
                float y0 = (acc[mi][ni][0] - mu[mi][0]) * rs[mi][0] * gv.x + bb.x;
                float y1 = (acc[mi][ni][1] - mu[mi][0]) * rs[mi][0] * gv.y + bb.y;
                float y2 = (acc[mi][ni][2] - mu[mi][1]) * rs[mi][1] * gv.x + bb.x;
                float y3 = (acc[mi][ni][3] - mu[mi][1]) * rs[mi][1] * gv.y + bb.y;
                bf16 h0 = __float2bfloat16(y0), h1 = __float2bfloat16(y1);
                bf16 h2 = __float2bfloat16(y2), h3 = __float2bfloat16(y3);
                __nv_bfloat162 p0; p0.x = h0; p0.y = h1;
                __nv_bfloat162 p1; p1.x = h2; p1.y = h3;
                *reinterpret_cast<__nv_bfloat162*>(Yhi + (size_t)m0 * COUT + c)       = p0;
                *reinterpret_cast<__nv_bfloat162*>(Yhi + (size_t)(m0 + 8) * COUT + c) = p1;
                p0.x = __float2bfloat16(y0 - __bfloat162float(h0));
                p0.y = __float2bfloat16(y1 - __bfloat162float(h1));
                p1.x = __float2bfloat16(y2 - __bfloat162float(h2));
                p1.y = __float2bfloat16(y3 - __bfloat162float(h3));
                *reinterpret_cast<__nv_bfloat162*>(Ylo + (size_t)m0 * COUT + c)       = p0;
                *reinterpret_cast<__nv_bfloat162*>(Ylo + (size_t)(m0 + 8) * COUT + c) = p1;
            }
        }
        return;
    }

#pragma unroll
    for (int mi = 0; mi < 2; mi++) {
        const int m0 = pm0 + wm + mi * 16 + gid;
#pragma unroll
        for (int ni = 0; ni < 8; ni++) {
            const int n = nv0 + wn + ni * 8 + tig * 2;
            float v00 = acc[mi][ni][0];
            float v01 = acc[mi][ni][1];
            float v10 = acc[mi][ni][2];
            float v11 = acc[mi][ni][3];
            if (WF32) {
                float2 a0; a0.x = v00; a0.y = v01;
                float2 a1; a1.x = v10; a1.y = v11;
                *reinterpret_cast<float2*>(Yf + (size_t)m0 * COUT + n)       = a0;
                *reinterpret_cast<float2*>(Yf + (size_t)(m0 + 8) * COUT + n) = a1;
            }
            if (WSPLIT) {
                bf16 h00 = __float2bfloat16(v00), h01 = __float2bfloat16(v01);
                bf16 h10 = __float2bfloat16(v10), h11 = __float2bfloat16(v11);
                __nv_bfloat162 hh0; hh0.x = h00; hh0.y = h01;
                __nv_bfloat162 hh1; hh1.x = h10; hh1.y = h11;
                __nv_bfloat162 ll0;
                ll0.x = __float2bfloat16(v00 - __bfloat162float(h00));
                ll0.y = __float2bfloat16(v01 - __bfloat162float(h01));
                __nv_bfloat162 ll1;
                ll1.x = __float2bfloat16(v10 - __bfloat162float(h10));
                ll1.y = __float2bfloat16(v11 - __bfloat162float(h11));
                *reinterpret_cast<__nv_bfloat162*>(Yhi + (size_t)m0 * COUT + n)       = hh0;
                *reinterpret_cast<__nv_bfloat162*>(Yhi + (size_t)(m0 + 8) * COUT + n) = hh1;
                *reinterpret_cast<__nv_bfloat162*>(Ylo + (size_t)m0 * COUT + n)       = ll0;
                *reinterpret_cast<__nv_bfloat162*>(Ylo + (size_t)(m0 + 8) * COUT + n) = ll1;
            }
        }
    }
}

// ---------------- fp16 two-split tensor conv (encoder), 3-buffer pipeline ----
template<int CIN, int KW, int COUT, bool WF32>
__global__ void __launch_bounds__(256)
tconvh(const half* __restrict__ Ah, const half* __restrict__ Am,
       const half* __restrict__ Wh, const half* __restrict__ Wm,
       const float* __restrict__ Bias, float* __restrict__ Yf,
       half* __restrict__ Yh, half* __restrict__ Ym)
{
    constexpr int KTOT = CIN * KW;
    constexpr int NCH  = KTOT / 64;
    constexpr int PAD  = (KW == 3) ? 1 : 0;

    extern __shared__ char smem[];
    const int tid = threadIdx.x;
    const int pm0 = blockIdx.x * 128;
    const int nv0 = blockIdx.y * 128;

    const int wid = tid >> 5, lane = tid & 31;
    const int wm = (wid >> 1) * 32;
    const int wn = (wid & 1) * 64;
    const int lr = lane & 7, lq = lane >> 3;

    float acc1[2][8][4];
    float acc2[2][8][4];
#pragma unroll
    for (int mi = 0; mi < 2; mi++)
#pragma unroll
        for (int ni = 0; ni < 8; ni++)
#pragma unroll
            for (int e = 0; e < 4; e++) { acc1[mi][ni][e] = 0.f; acc2[mi][ni][e] = 0.f; }

    const uint4* A4h = reinterpret_cast<const uint4*>(Ah);
    const uint4* A4m = reinterpret_cast<const uint4*>(Am);
    const uint4* B4h = reinterpret_cast<const uint4*>(Wh);
    const uint4* B4m = reinterpret_cast<const uint4*>(Wm);

    const uint32_t sb = smem_to_u32(smem);

    auto load_chunk = [&](int ch, int buf) {
        const uint32_t bo = (uint32_t)buf * 65536u;
        const int tap = (ch * 64) / CIN;
        const int ci0 = (ch * 64) % CIN;
#pragma unroll
        for (int i = 0; i < 4; i++) {
            int idx = tid + i * 256;
            int row = idx >> 3, c = idx & 7;
            int p = pm0 + row;
            bool ok = true;
            if (KW == 3) {
                int ls = (p & (LSEQ - 1)) + tap - PAD;
                ok = ((unsigned)ls < (unsigned)LSEQ);
            }
            size_t gi = ok ? ((size_t)(p + tap - PAD) * (CIN / 8) + (ci0 / 8) + c) : 0;
            int nb = ok ? 16 : 0;
            int pc = (c ^ row) & 7;
            uint32_t so = (uint32_t)(row * 128 + pc * 16);
            cp_async16(sb + bo + so,          A4h + gi, nb);
            cp_async16(sb + bo + 16384u + so, A4m + gi, nb);
        }
#pragma unroll
        for (int i = 0; i < 4; i++) {
            int idx = tid + i * 256;
            int row = idx >> 3, c = idx & 7;
            size_t gi = (size_t)(nv0 + row) * (KTOT / 8) + ch * 8 + c;
            int pc = (c ^ row) & 7;
            uint32_t so = (uint32_t)(row * 128 + pc * 16);
            cp_async16(sb + bo + 32768u + so, B4h + gi, 16);
            cp_async16(sb + bo + 49152u + so, B4m + gi, 16);
        }
        asm volatile("cp.async.commit_group;");
    };

    load_chunk(0, 0);
    if (1 < NCH) load_chunk(1, 1);

    for (int ch = 0; ch < NCH; ch++) {
        if (ch + 1 < NCH)
            asm volatile("cp.async.wait_group 1;");
        else
            asm volatile("cp.async.wait_group 0;");
        __syncthreads();
        if (ch + 2 < NCH) load_chunk(ch + 2, (ch + 2) % 3);

        const uint32_t bo = (uint32_t)(ch % 3) * 65536u;
        const uint32_t aB3[3] = { sb + bo, sb + bo, sb + bo + 16384u };
        const uint32_t bB3[3] = { sb + bo + 32768u, sb + bo + 49152u, sb + bo + 32768u };
#pragma unroll
        for (int s = 0; s < 3; s++) {
            const uint32_t aB = aB3[s];
            const uint32_t bB = bB3[s];
#pragma unroll
            for (int k16 = 0; k16 < 4; k16++) {
                const int kc0 = k16 * 2;
                uint32_t a[2][4];
#pragma unroll
                for (int mi = 0; mi < 2; mi++) {
                    int row = wm + mi * 16 + lr + (lq & 1) * 8;
                    int kc  = kc0 + (lq >> 1);
                    int pc  = (kc ^ row) & 7;
                    ldsm_x4(a[mi], aB + row * 128 + pc * 16);
                }
                float (*acc)[8][4] = (s == 0) ? acc1 : acc2;
#pragma unroll
                for (int nc = 0; nc < 4; nc++) {
                    uint32_t b[4];
                    int row = wn + nc * 16 + lr + (lq >> 1) * 8;
                    int kc  = kc0 + (lq & 1);
                    int pc  = (kc ^ row) & 7;
                    ldsm_x4(b, bB + row * 128 + pc * 16);
                    mma16816h(acc[0][nc * 2 + 0], a[0], b[0], b[1]);
                    mma16816h(acc[0][nc * 2 + 1], a[0], b[2], b[3]);
                    mma16816h(acc[1][nc * 2 + 0], a[1], b[0], b[1]);
                    mma16816h(acc[1][nc * 2 + 1], a[1], b[2], b[3]);
                }
            }
        }
    }

    const int gid = lane >> 2, tig = lane & 3;
#pragma unroll
    for (int mi = 0; mi < 2; mi++) {
        const int m0 = pm0 + wm + mi * 16 + gid;
#pragma unroll
        for (int ni = 0; ni < 8; ni++) {
            const int n = nv0 + wn + ni * 8 + tig * 2;
            const float2 bv = *reinterpret_cast<const float2*>(Bias + n);
            float v00 = fmaxf(fmaf(acc2[mi][ni][0], LO_INV, acc1[mi][ni][0]) + bv.x, 0.f);
            float v01 = fmaxf(fmaf(acc2[mi][ni][1], LO_INV, acc1[mi][ni][1]) + bv.y, 0.f);
            float v10 = fmaxf(fmaf(acc2[mi][ni][2], LO_INV, acc1[mi][ni][2]) + bv.x, 0.f);
            float v11 = fmaxf(fmaf(acc2[mi][ni][3], LO_INV, acc1[mi][ni][3]) + bv.y, 0.f);
            if (WF32) {
                float2 a0; a0.x = v00; a0.y = v01;
                float2 a1; a1.x = v10; a1.y = v11;
                *reinterpret_cast<float2*>(Yf + (size_t)m0 * COUT + n)       = a0;
                *reinterpret_cast<float2*>(Yf + (size_t)(m0 + 8) * COUT + n) = a1;
            } else {
                half h00,m00,h01,m01,h10,m10,h11,m11;
                split2h(v00,h00,m00); split2h(v01,h01,m01);
                split2h(v10,h10,m10); split2h(v11,h11,m11);
                __half2 p0, p1;
                p0.x=h00; p0.y=h01; p1.x=h10; p1.y=h11;
                *reinterpret_cast<__half2*>(Yh + (size_t)m0 * COUT + n)       = p0;
                *reinterpret_cast<__half2*>(Yh + (size_t)(m0 + 8) * COUT + n) = p1;
                p0.x=m00; p0.y=m01; p1.x=m10; p1.y=m11;
                *reinterpret_cast<__half2*>(Ym + (size_t)m0 * COUT + n)       = p0;
                *reinterpret_cast<__half2*>(Ym + (size_t)(m0 + 8) * COUT + n) = p1;
            }
        }
    }
}

// ---------------- wide full-K-resident bf16x3 logits GEMM --------------------
// Term-staged cp.async: hi tiles (group0) -> compute hh while lo tiles land.
#define LGW_SMEM 196608

__global__ void __launch_bounds__(256, 1)
logits_wide(const bf16* __restrict__ Ahi, const bf16* __restrict__ Alo,
            const bf16* __restrict__ Bhi, const bf16* __restrict__ Blo,
            const float* __restrict__ Bias, float* __restrict__ Out)
{
    extern __shared__ char smem[];
    const int tid = threadIdx.x;
    const int pm0 = blockIdx.x * 128;
    const int nv0 = blockIdx.y * 256;

    const uint32_t sb = smem_to_u32(smem);

    // group 0: hi tiles
    {
        const uint4* A4h = reinterpret_cast<const uint4*>(Ahi);
#pragma unroll
        for (int i = 0; i < 8; i++) {
            int idx = tid + i * 256;
            int row = idx >> 4, c = idx & 15;
            int pc = (c & 8) | ((c ^ row) & 7);
            cp_async16(sb + (uint32_t)(row * 256 + pc * 16),
                       A4h + (size_t)(pm0 + row) * 16 + c, 16);
        }
        const uint4* B4h = reinterpret_cast<const uint4*>(Bhi);
#pragma unroll
        for (int i = 0; i < 16; i++) {
            int idx = tid + i * 256;
            int row = idx >> 4, c = idx & 15;
            int pc = (c & 8) | ((c ^ row) & 7);
            cp_async16(sb + 65536u + (uint32_t)(row * 256 + pc * 16),
                       B4h + (size_t)(nv0 + row) * 16 + c, 16);
        }
        asm volatile("cp.async.commit_group;");
    }
    // group 1: lo tiles
    {
        const uint4* A4l = reinterpret_cast<const uint4*>(Alo);
#pragma unroll
        for (int i = 0; i < 8; i++) {
            int idx = tid + i * 256;
            int row = idx >> 4, c = idx & 15;
            int pc = (c & 8) | ((c ^ row) & 7);
            cp_async16(sb + 32768u + (uint32_t)(row * 256 + pc * 16),
                       A4l + (size_t)(pm0 + row) * 16 + c, 16);
        }
        const uint4* B4l = reinterpret_cast<const uint4*>(Blo);
#pragma unroll
        for (int i = 0; i < 16; i++) {
            int idx = tid + i * 256;
            int row = idx >> 4, c = idx & 15;
            int pc = (c & 8) | ((c ^ row) & 7);
            cp_async16(sb + 131072u + (uint32_t)(row * 256 + pc * 16),
                       B4l + (size_t)(nv0 + row) * 16 + c, 16);
        }
        asm volatile("cp.async.commit_group;");
    }

    const int wid = tid >> 5, lane = tid & 31;
    const int wm = (wid >> 1) * 32;       // 0,32,64,96
    const int wn = (wid & 1) * 128;       // 0,128
    const int lr = lane & 7, lq = lane >> 3;

    float acc[2][16][4];
#pragma unroll
    for (int mi = 0; mi < 2; mi++)
#pragma unroll
        for (int ni = 0; ni < 16; ni++)
#pragma unroll
            for (int e = 0; e < 4; e++) acc[mi][ni][e] = 0.f;

    const uint32_t aB3[3] = { sb, sb, sb + 32768u };                   // hi, hi, lo
    const uint32_t bB3[3] = { sb + 65536u, sb + 131072u, sb + 65536u };// hi, lo, hi

    asm volatile("cp.async.wait_group 1;");
    __syncthreads();

#pragma unroll
    for (int s = 0; s < 3; s++) {
        if (s == 1) {
            asm volatile("cp.async.wait_group 0;");
            __syncthreads();
        }
        const uint32_t aB = aB3[s];
        const uint32_t bB = bB3[s];
#pragma unroll
        for (int k16 = 0; k16 < 8; k16++) {
            const int kc0 = k16 * 2;
            uint32_t a[2][4];
#pragma unroll
            for (int mi = 0; mi < 2; mi++) {
                int row = wm + mi * 16 + lr + (lq & 1) * 8;
                int kc  = kc0 + (lq >> 1);
                int pc  = (kc & 8) | ((kc ^ row) & 7);
                ldsm_x4(a[mi], aB + row * 256 + pc * 16);
            }
#pragma unroll
            for (int nc = 0; nc < 8; nc++) {
                uint32_t b[4];
                int row = wn + nc * 16 + lr + (lq >> 1) * 8;
                int kc  = kc0 + (lq & 1);
                int pc  = (kc & 8) | ((kc ^ row) & 7);
                ldsm_x4(b, bB + row * 256 + pc * 16);
                mma16816(acc[0][nc * 2 + 0], a[0], b[0], b[1]);
                mma16816(acc[0][nc * 2 + 1], a[0], b[2], b[3]);
                mma16816(acc[1][nc * 2 + 0], a[1], b[0], b[1]);
                mma16816(acc[1][nc * 2 + 1], a[1], b[2], b[3]);
            }
        }
    }

    const int gid = lane >> 2, tig = lane & 3;
#pragma unroll
    for (int mi = 0; mi < 2; mi++) {
        const int m0 = pm0 + wm + mi * 16 + gid;
#pragma unroll
        for (int ni = 0; ni < 16; ni++) {
            const int n = nv0 + wn + ni * 8 + tig * 2;
            const float2 bv = *reinterpret_cast<const float2*>(Bias + n);
            float2 v0, v1;
            v0.x = acc[mi][ni][0] + bv.x;  v0.y = acc[mi][ni][1] + bv.y;
            v1.x = acc[mi][ni][2] + bv.x;  v1.y = acc[mi][ni][3] + bv.y;
            *reinterpret_cast<float2*>(Out + (size_t)m0 * VOCAB + n)       = v0;
            *reinterpret_cast<float2*>(Out + (size_t)(m0 + 8) * VOCAB + n) = v1;
        }
    }
}

// ---------------- tail: loss scalar + codes ----------------------------------
__global__ void commit_final(const float* __restrict__ Part, float* __restrict__ slot)
{
    if (threadIdx.x == 0 && blockIdx.x == 0) {
        float s = 0.f;
        for (int i = 0; i < NPOS / 64; i++) s += Part[i];
        *slot = 0.1f * s / ((float)NPOS * (float)DDIM);
    }
}

__global__ void write_codes(const int* __restrict__ codes, float* __restrict__ out)
{
    int n = blockIdx.x * blockDim.x + threadIdx.x;
    if (n < NPOS) out[n] = (float)codes[n];
}

// ---------------- launch ------------------------------------------------------
extern "C" void kernel_launch(void* const* d_in, const int* in_sizes, int n_in,
                              void* d_out, int out_size)
{
    (void)in_sizes; (void)n_in;
    const int*   x    = (const int*)  d_in[0];
    const float* tok  = (const float*)d_in[1];
    const float* ew1  = (const float*)d_in[2];
    const float* eb1  = (const float*)d_in[3];
    const float* ew2  = (const float*)d_in[4];
    const float* eb2  = (const float*)d_in[5];
    const float* ew3  = (const float*)d_in[6];
    const float* eb3  = (const float*)d_in[7];
    const float* elg  = (const float*)d_in[8];
    const float* elb  = (const float*)d_in[9];
    const float* cb   = (const float*)d_in[10];
    const float* dw1  = (const float*)d_in[11];
    const float* db1  = (const float*)d_in[12];
    const float* dw2  = (const float*)d_in[13];
    const float* db2  = (const float*)d_in[14];
    const float* dw3  = (const float*)d_in[15];
    const float* db3  = (const float*)d_in[16];
    const float* dlg  = (const float*)d_in[17];
    const float* dlb  = (const float*)d_in[18];
    const float* ow   = (const float*)d_in[19];
    const float* ob   = (const float*)d_in[20];
    float* out = (float*)d_out;

    float *h2, *z, *cn, *cp;
    int* codes;
    half *ebh,*ebm,*e1h,*e1m,*w1eh,*w1em,*w2eh,*w2em;
    bf16 *zqhi,*zqlo,*d1hi,*d1lo,*d2hi,*d2lo,*ahi,*alo;
    bf16 *w1hi,*w1lo,*w2hi,*w2lo,*w3hi,*w3lo,*bhi,*blo;
    cudaGetSymbolAddress((void**)&h2,    g_h2);
    cudaGetSymbolAddress((void**)&z,     g_z);
    cudaGetSymbolAddress((void**)&codes, g_codes);
    cudaGetSymbolAddress((void**)&cn,    g_cnorm);
    cudaGetSymbolAddress((void**)&cp,    g_commit);
    cudaGetSymbolAddress((void**)&ebh,   g_ebh);
    cudaGetSymbolAddress((void**)&ebm,   g_ebm);
    cudaGetSymbolAddress((void**)&e1h,   g_e1h);
    cudaGetSymbolAddress((void**)&e1m,   g_e1m);
    cudaGetSymbolAddress((void**)&w1eh,  g_w1eh);
    cudaGetSymbolAddress((void**)&w1em,  g_w1em);
    cudaGetSymbolAddress((void**)&w2eh,  g_w2eh);
    cudaGetSymbolAddress((void**)&w2em,  g_w2em);
    cudaGetSymbolAddress((void**)&zqhi,  g_zqhi);
    cudaGetSymbolAddress((void**)&zqlo,  g_zqlo);
    cudaGetSymbolAddress((void**)&d1hi,  g_d1hi);
    cudaGetSymbolAddress((void**)&d1lo,  g_d1lo);
    cudaGetSymbolAddress((void**)&d2hi,  g_d2hi);
    cudaGetSymbolAddress((void**)&d2lo,  g_d2lo);
    cudaGetSymbolAddress((void**)&ahi,   g_ahi);
    cudaGetSymbolAddress((void**)&alo,   g_alo);
    cudaGetSymbolAddress((void**)&w1hi,  g_w1hi);
    cudaGetSymbolAddress((void**)&w1lo,  g_w1lo);
    cudaGetSymbolAddress((void**)&w2hi,  g_w2hi);
    cudaGetSymbolAddress((void**)&w2lo,  g_w2lo);
    cudaGetSymbolAddress((void**)&w3hi,  g_w3hi);
    cudaGetSymbolAddress((void**)&w3lo,  g_w3lo);
    cudaGetSymbolAddress((void**)&bhi,   g_bhi);
    cudaGetSymbolAddress((void**)&blo,   g_blo);

    cudaFuncSetAttribute((const void*)tconvh<128, 3, 256, false>,
                         cudaFuncAttributeMaxDynamicSharedMemorySize, TC_SMEM);
    cudaFuncSetAttribute((const void*)tconvh<256, 3, 256, true>,
                         cudaFuncAttributeMaxDynamicSharedMemorySize, TC_SMEM);
    cudaFuncSetAttribute((const void*)tconv< 64, 1, 256, true,  false, true,  false>,
                         cudaFuncAttributeMaxDynamicSharedMemorySize, TC_SMEM);
    cudaFuncSetAttribute((const void*)tconv<256, 3, 256, true,  false, true,  false>,
                         cudaFuncAttributeMaxDynamicSharedMemorySize, TC_SMEM);
    cudaFuncSetAttribute((const void*)tconv<256, 1, 128, true,  false, false, true >,
                         cudaFuncAttributeMaxDynamicSharedMemorySize, TC_SMEM);
    cudaFuncSetAttribute((const void*)logits_wide,
                         cudaFuncAttributeMaxDynamicSharedMemorySize, LGW_SMEM);

    // ---- encoder (fp16 two-split tensor cores, pipelined) ----
    pack_split2h<128, 3, 256><<<(256*384)  / 256, 256>>>(ew1, w1eh, w1em);
    pack_split2h<256, 3, 256><<<(256*768)  / 256, 256>>>(ew2, w2eh, w2em);
    embed_split2h<<<NPOS * 32 / 256, 256>>>(x, tok, ebh, ebm);
    tconvh<128, 3, 256, false><<<dim3(NPOS/128, 2), 256, TC_SMEM>>>(
        ebh, ebm, w1eh, w1em, eb1, nullptr, e1h, e1m);
    tconvh<256, 3, 256, true ><<<dim3(NPOS/128, 2), 256, TC_SMEM>>>(
        e1h, e1m, w2eh, w2em, eb2, h2, nullptr, nullptr);
    enc_head_ln<<<NPOS / 64, 256>>>(h2, ew3, eb3, elg, elb, z);

    // ---- vector quantization ----
    cnorm_kernel<<<1, 512>>>(cb, cn);
    vq_kernel<<<NPOS / 64, 256>>>(z, cb, cn, codes, cp);
    gather_zq_split<<<NPOS * 16 / 256, 256>>>(codes, cb, zqhi, zqlo);

    // ---- decoder weight packs + decoder (bf16x3 tensor cores, pipelined) ----
    pack_split< 64, 1, 256>  <<<(256*64)   / 256, 256>>>(dw1, w1hi, w1lo);
    pack_split<256, 3, 256>  <<<(256*768)  / 256, 256>>>(dw2, w2hi, w2lo);
    pack_split<256, 1, 128>  <<<(128*256)  / 256, 256>>>(dw3, w3hi, w3lo);
    pack_split<128, 1, VOCAB><<<(VOCAB*128)/ 256, 256>>>(ow,  bhi,  blo);

    tconv< 64, 1, 256, true,  false, true,  false><<<dim3(NPOS/128, 2), 256, TC_SMEM>>>(
        zqhi, zqlo, w1hi, w1lo, db1, nullptr, nullptr, nullptr, d1hi, d1lo);
    tconv<256, 3, 256, true,  false, true,  false><<<dim3(NPOS/128, 2), 256, TC_SMEM>>>(
        d1hi, d1lo, w2hi, w2lo, db2, nullptr, nullptr, nullptr, d2hi, d2lo);
    // conv3 + fused LayerNorm + bf16 split (COUT=128 = full feature row)
    tconv<256, 1, 128, true,  false, false, true ><<<dim3(NPOS/128, 1), 256, TC_SMEM>>>(
        d2hi, d2lo, w3hi, w3lo, db3, dlg, dlb, nullptr, ahi, alo);

    // ---- vocab projection (wide full-K bf16x3, term-staged) -> d_out ----
    logits_wide<<<dim3(NPOS/128, VOCAB/256), 256, LGW_SMEM>>>(
        ahi, alo, bhi, blo, ob, out);

    // ---- tail: loss scalar + codes ----
    const long long NV = (long long)NPOS * VOCAB;   // 134217728
    if ((long long)out_size >= NV + 1)
        commit_final<<<1, 32>>>(cp, out + NV);
    if ((long long)out_size >= NV + 1 + NPOS)
        write_codes<<<NPOS / 256, 256>>>(codes, out + NV + 1);
}

// round 12
// speedup vs baseline: 1.0153x; 1.0153x over previous
#include <cuda_runtime.h>
#include <cuda_bf16.h>
#include <cuda_fp16.h>
#include <cstdint>

// Problem constants
#define NPOS   32768          // B*L = 8*4096
#define LSEQ   4096
#define EDIM   128
#define HDIM   256
#define DDIM   64
#define KCODE  512
#define VOCAB  4096
#define LN_EPS 1e-5f

typedef __nv_bfloat16 bf16;

#define LO_SCALE   2048.0f
#define LO_INV     (1.0f / 2048.0f)

// ---------------- scratch (static device globals; no allocation) -------------
__device__ float g_h2 [NPOS * HDIM];    // encoder conv2 output (fp32)
__device__ float g_z  [NPOS * DDIM];    // z_e after LN
__device__ int   g_codes[NPOS];
__device__ float g_cnorm[KCODE];
__device__ float g_commit[NPOS / 64];
// encoder fp16 two-split activations (lo scaled by 2048)
__device__ __align__(16) half g_ebh[NPOS * EDIM];
__device__ __align__(16) half g_ebm[NPOS * EDIM];
__device__ __align__(16) half g_e1h[NPOS * HDIM];
__device__ __align__(16) half g_e1m[NPOS * HDIM];
// encoder fp16 two-split packed weights
__device__ __align__(16) half g_w1eh[HDIM * EDIM * 3];
__device__ __align__(16) half g_w1em[HDIM * EDIM * 3];
__device__ __align__(16) half g_w2eh[HDIM * HDIM * 3];
__device__ __align__(16) half g_w2em[HDIM * HDIM * 3];
// decoder bf16 hi/lo split activations
__device__ __align__(16) bf16 g_zqhi[NPOS * DDIM];
__device__ __align__(16) bf16 g_zqlo[NPOS * DDIM];
__device__ __align__(16) bf16 g_d1hi[NPOS * HDIM];
__device__ __align__(16) bf16 g_d1lo[NPOS * HDIM];
__device__ __align__(16) bf16 g_d2hi[NPOS * HDIM];
__device__ __align__(16) bf16 g_d2lo[NPOS * HDIM];
__device__ __align__(16) bf16 g_ahi[NPOS * EDIM];
__device__ __align__(16) bf16 g_alo[NPOS * EDIM];
// decoder bf16 hi/lo split packed weights
__device__ __align__(16) bf16 g_w1hi[HDIM * DDIM];
__device__ __align__(16) bf16 g_w1lo[HDIM * DDIM];
__device__ __align__(16) bf16 g_w2hi[HDIM * HDIM * 3];
__device__ __align__(16) bf16 g_w2lo[HDIM * HDIM * 3];
__device__ __align__(16) bf16 g_w3hi[EDIM * HDIM];
__device__ __align__(16) bf16 g_w3lo[EDIM * HDIM];
__device__ __align__(16) bf16 g_bhi[VOCAB * EDIM];
__device__ __align__(16) bf16 g_blo[VOCAB * EDIM];

__device__ __forceinline__ uint32_t smem_to_u32(const void* smem_ptr) {
    uint32_t addr;
    asm("{ .reg .u64 tmp; cvta.to.shared.u64 tmp, %1; cvt.u32.u64 %0, tmp; }"
        : "=r"(addr) : "l"(smem_ptr));
    return addr;
}

__device__ __forceinline__ void cp_async16(uint32_t saddr, const void* gptr, int src_bytes) {
    asm volatile("cp.async.cg.shared.global [%0], [%1], 16, %2;"
                 :: "r"(saddr), "l"(gptr), "r"(src_bytes));
}

// fp16 two-split: x = h + (m/2048); m kept in normal fp16 range
__device__ __forceinline__ void split2h(float x, half& h, half& m) {
    h = __float2half_rn(x);
    m = __float2half_rn((x - __half2float(h)) * LO_SCALE);
}

// ---------------- embedding lookup with fused fp16 two-split ------------------
__global__ void embed_split2h(const int* __restrict__ x,
                              const float* __restrict__ tok,
                              half* __restrict__ H, half* __restrict__ M)
{
    int idx = blockIdx.x * blockDim.x + threadIdx.x;   // NPOS*32 float4s
    int n = idx >> 5;
    int j = idx & 31;
    int t = x[n];
    float4 v = reinterpret_cast<const float4*>(tok)[t * 32 + j];
    half h0,m0,h1,m1,h2,m2,h3,m3;
    split2h(v.x,h0,m0); split2h(v.y,h1,m1);
    split2h(v.z,h2,m2); split2h(v.w,h3,m3);
    __half2 p;
    p.x=h0; p.y=h1; reinterpret_cast<__half2*>(H)[n*64+j*2+0]=p;
    p.x=h2; p.y=h3; reinterpret_cast<__half2*>(H)[n*64+j*2+1]=p;
    p.x=m0; p.y=m1; reinterpret_cast<__half2*>(M)[n*64+j*2+0]=p;
    p.x=m2; p.y=m3; reinterpret_cast<__half2*>(M)[n*64+j*2+1]=p;
}

// ---------------- weight pack + splits ----------------------------------------
template<int CIN, int KW, int COUT>
__global__ void pack_split(const float* __restrict__ W,
                           bf16* __restrict__ Hi, bf16* __restrict__ Lo)
{
    int idx = blockIdx.x * blockDim.x + threadIdx.x;
    if (idx >= COUT * KW * CIN) return;
    int o   = idx / (KW * CIN);
    int rem = idx - o * (KW * CIN);
    int tap = rem / CIN;
    int ci  = rem - tap * CIN;
    float w = W[(size_t)o * CIN * KW + ci * KW + tap];
    bf16 h = __float2bfloat16(w);
    Hi[idx] = h;
    Lo[idx] = __float2bfloat16(w - __bfloat162float(h));
}

template<int CIN, int KW, int COUT>
__global__ void pack_split2h(const float* __restrict__ W,
                             half* __restrict__ H, half* __restrict__ M)
{
    int idx = blockIdx.x * blockDim.x + threadIdx.x;
    if (idx >= COUT * KW * CIN) return;
    int o   = idx / (KW * CIN);
    int rem = idx - o * (KW * CIN);
    int tap = rem / CIN;
    int ci  = rem - tap * CIN;
    float w = W[(size_t)o * CIN * KW + ci * KW + tap];
    half h, m;
    split2h(w, h, m);
    H[idx] = h; M[idx] = m;
}

// ---------------- encoder head: conv1x1 (256->64) + LayerNorm(D=64) ---------
__global__ void __launch_bounds__(256)
enc_head_ln(const float* __restrict__ X, const float* __restrict__ W,
            const float* __restrict__ Bias,
            const float* __restrict__ G, const float* __restrict__ Bt,
            float* __restrict__ Z)
{
    constexpr int CIN = 256;
    __shared__ float As[32][66];
    __shared__ float Bs[32][66];
    __shared__ float Zs[64][66];

    const int pm0 = blockIdx.x * 64;
    const int tid = threadIdx.x;
    const int tx = tid & 15, ty = tid >> 4;
    const int rr = tid & 31;
    const int mrow = tid >> 5;

    float acc[4][4];
#pragma unroll
    for (int i = 0; i < 4; i++)
#pragma unroll
        for (int j = 0; j < 4; j++) acc[i][j] = 0.f;

    for (int r0 = 0; r0 < CIN; r0 += 32) {
        const int ci = r0 + rr;
#pragma unroll
        for (int i = 0; i < 8; i++) {
            const int m = mrow + i * 8;
            As[rr][m] = X[(size_t)(pm0 + m) * CIN + ci];
        }
#pragma unroll
        for (int i = 0; i < 8; i++) {
            const int n = mrow + i * 8;
            Bs[rr][n] = W[(size_t)n * CIN + ci];
        }
        __syncthreads();
#pragma unroll
        for (int kk = 0; kk < 32; kk++) {
            float a[4], b[4];
#pragma unroll
            for (int i = 0; i < 4; i++) a[i] = As[kk][ty * 4 + i];
#pragma unroll
            for (int j = 0; j < 4; j++) b[j] = Bs[kk][tx * 4 + j];
#pragma unroll
            for (int i = 0; i < 4; i++)
#pragma unroll
                for (int j = 0; j < 4; j++)
                    acc[i][j] = fmaf(a[i], b[j], acc[i][j]);
        }
        __syncthreads();
    }
#pragma unroll
    for (int i = 0; i < 4; i++)
#pragma unroll
        for (int j = 0; j < 4; j++)
            Zs[ty * 4 + i][tx * 4 + j] = acc[i][j] + Bias[tx * 4 + j];
    __syncthreads();

    const int lane = tid & 31, w = tid >> 5;
#pragma unroll
    for (int q = 0; q < 8; q++) {
        const int m = w * 8 + q;
        float v0 = Zs[m][lane];
        float v1 = Zs[m][lane + 32];
        float s = v0 + v1;
#pragma unroll
        for (int off = 16; off > 0; off >>= 1)
            s += __shfl_xor_sync(0xffffffffu, s, off);
        float mu = s * (1.f / 64.f);
        float d0 = v0 - mu, d1 = v1 - mu;
        float sq = __fadd_rn(__fmul_rn(d0, d0), __fmul_rn(d1, d1));
#pragma unroll
        for (int off = 16; off > 0; off >>= 1)
            sq += __shfl_xor_sync(0xffffffffu, sq, off);
        float var = sq * (1.f / 64.f);
        float rs  = rsqrtf(var + LN_EPS);
        const int p = pm0 + m;
        Z[(size_t)p * 64 + lane]      = d0 * rs * G[lane]      + Bt[lane];
        Z[(size_t)p * 64 + lane + 32] = d1 * rs * G[lane + 32] + Bt[lane + 32];
    }
}

// ---------------- codebook norms (no FMA: match sum(c*c)) --------------------
__global__ void cnorm_kernel(const float* __restrict__ CB, float* __restrict__ CN)
{
    int c = blockIdx.x * blockDim.x + threadIdx.x;
    if (c < KCODE) {
        float s = 0.f;
        for (int d = 0; d < DDIM; d++) {
            float v = CB[c * DDIM + d];
            s = __fadd_rn(s, __fmul_rn(v, v));
        }
        CN[c] = s;
    }
}

// ---------------- VQ: argmin over codes + commit-loss partials ---------------
__global__ void __launch_bounds__(256)
vq_kernel(const float* __restrict__ Z, const float* __restrict__ CB,
          const float* __restrict__ CN, int* __restrict__ Codes,
          float* __restrict__ CommitPart)
{
    __shared__ float Zt[64][66];
    __shared__ float Cs[64][66];
    __shared__ float znS[64];
    __shared__ float cvals[64];

    const int pm0 = blockIdx.x * 64;
    const int tid = threadIdx.x;
    const int tx = tid & 15, ty = tid >> 4;

#pragma unroll
    for (int i = 0; i < 16; i++) {
        int idx = tid + i * 256;
        int m = idx >> 6, d = idx & 63;
        Zt[d][m] = Z[(size_t)(pm0 + m) * 64 + d];
    }
    __syncthreads();

    if (tid < 64) {
        const int m = tid;
        float s = 0.f;
        for (int d = 0; d < 64; d++) {
            float v = Zt[d][m];
            s = __fadd_rn(s, __fmul_rn(v, v));
        }
        znS[m] = s;
    }
    __syncthreads();

    float zm[4];
#pragma unroll
    for (int i = 0; i < 4; i++) zm[i] = znS[ty * 4 + i];

    float minv[4]; int mini[4];
#pragma unroll
    for (int i = 0; i < 4; i++) { minv[i] = 3.4e38f; mini[i] = 0; }

    for (int c0 = 0; c0 < KCODE; c0 += 64) {
        __syncthreads();
#pragma unroll
        for (int i = 0; i < 16; i++) {
            int idx = tid + i * 256;
            int c = idx >> 6, d = idx & 63;
            Cs[d][c] = CB[(size_t)(c0 + c) * 64 + d];
        }
        __syncthreads();

        float dot[4][4];
#pragma unroll
        for (int i = 0; i < 4; i++)
#pragma unroll
            for (int j = 0; j < 4; j++) dot[i][j] = 0.f;
#pragma unroll
        for (int kk = 0; kk < 64; kk++) {
            float a[4], b[4];
#pragma unroll
            for (int i = 0; i < 4; i++) a[i] = Zt[kk][ty * 4 + i];
#pragma unroll
            for (int j = 0; j < 4; j++) b[j] = Cs[kk][tx * 4 + j];
#pragma unroll
            for (int i = 0; i < 4; i++)
#pragma unroll
                for (int j = 0; j < 4; j++)
                    dot[i][j] = fmaf(a[i], b[j], dot[i][j]);
        }
#pragma unroll
        for (int j = 0; j < 4; j++) {
            const int c = c0 + tx * 4 + j;
            const float cn = CN[c];
#pragma unroll
            for (int i = 0; i < 4; i++) {
                float t    = __fadd_rn(zm[i], -__fmul_rn(2.f, dot[i][j]));
                float dist = __fadd_rn(t, cn);
                if (dist < minv[i]) { minv[i] = dist; mini[i] = c; }
            }
        }
    }
    __syncthreads();

    float* redv = &Cs[0][0];
    int*   redi = reinterpret_cast<int*>(&Cs[0][0]) + 1024;
#pragma unroll
    for (int i = 0; i < 4; i++) {
        const int m = ty * 4 + i;
        redv[m * 16 + tx] = minv[i];
        redi[m * 16 + tx] = mini[i];
    }
    __syncthreads();
    if (tid < 64) {
        const int m = tid;
        float bv = redv[m * 16];
        int   bi = redi[m * 16];
        for (int t = 1; t < 16; t++) {
            float v = redv[m * 16 + t];
            int  ix = redi[m * 16 + t];
            if (v < bv || (v == bv && ix < bi)) { bv = v; bi = ix; }
        }
        Codes[pm0 + m] = bi;
        cvals[m] = bv;
    }
    __syncthreads();
    if (tid == 0) {
        float s = 0.f;
        for (int m = 0; m < 64; m++) s += cvals[m];
        CommitPart[blockIdx.x] = s;
    }
}

// ---------------- gather z_q with fused bf16 hi/lo split ----------------------
__global__ void gather_zq_split(const int* __restrict__ codes,
                                const float* __restrict__ CB,
                                bf16* __restrict__ Hi, bf16* __restrict__ Lo)
{
    int idx = blockIdx.x * blockDim.x + threadIdx.x;   // NPOS*16 float4s
    int n = idx >> 4;
    int j = idx & 15;
    float4 v = reinterpret_cast<const float4*>(CB)[codes[n] * 16 + j];
    bf16 h0 = __float2bfloat16(v.x), h1 = __float2bfloat16(v.y);
    bf16 h2 = __float2bfloat16(v.z), h3 = __float2bfloat16(v.w);
    __nv_bfloat162 hh0; hh0.x = h0; hh0.y = h1;
    __nv_bfloat162 hh1; hh1.x = h2; hh1.y = h3;
    __nv_bfloat162 ll0; ll0.x = __float2bfloat16(v.x - __bfloat162float(h0));
    ll0.y = __float2bfloat16(v.y - __bfloat162float(h1));
    __nv_bfloat162 ll1; ll1.x = __float2bfloat16(v.z - __bfloat162float(h2));
    ll1.y = __float2bfloat16(v.w - __bfloat162float(h3));
    reinterpret_cast<__nv_bfloat162*>(Hi)[n * 32 + j * 2 + 0] = hh0;
    reinterpret_cast<__nv_bfloat162*>(Hi)[n * 32 + j * 2 + 1] = hh1;
    reinterpret_cast<__nv_bfloat162*>(Lo)[n * 32 + j * 2 + 0] = ll0;
    reinterpret_cast<__nv_bfloat162*>(Lo)[n * 32 + j * 2 + 1] = ll1;
}

// ---------------- mma helpers -------------------------------------------------
__device__ __forceinline__ void ldsm_x4(uint32_t* r, uint32_t addr) {
    asm volatile("ldmatrix.sync.aligned.m8n8.x4.shared.b16 {%0,%1,%2,%3}, [%4];"
                 : "=r"(r[0]), "=r"(r[1]), "=r"(r[2]), "=r"(r[3]) : "r"(addr));
}
__device__ __forceinline__ void mma16816(float* d, const uint32_t* a,
                                         uint32_t b0, uint32_t b1) {
    asm volatile(
        "mma.sync.aligned.m16n8k16.row.col.f32.bf16.bf16.f32 "
        "{%0,%1,%2,%3}, {%4,%5,%6,%7}, {%8,%9}, {%0,%1,%2,%3};"
        : "+f"(d[0]), "+f"(d[1]), "+f"(d[2]), "+f"(d[3])
        : "r"(a[0]), "r"(a[1]), "r"(a[2]), "r"(a[3]), "r"(b0), "r"(b1));
}
__device__ __forceinline__ void mma16816h(float* d, const uint32_t* a,
                                          uint32_t b0, uint32_t b1) {
    asm volatile(
        "mma.sync.aligned.m16n8k16.row.col.f32.f16.f16.f32 "
        "{%0,%1,%2,%3}, {%4,%5,%6,%7}, {%8,%9}, {%0,%1,%2,%3};"
        : "+f"(d[0]), "+f"(d[1]), "+f"(d[2]), "+f"(d[3])
        : "r"(a[0]), "r"(a[1]), "r"(a[2]), "r"(a[3]), "r"(b0), "r"(b1));
}

// ---------------- generic bf16x3 (hi/lo) tensor conv, 3-buffer pipeline ------
// Fused-term inner loop: per k16 load a_hi/a_lo once, per nc load b_hi/b_lo,
// fire 12 MMAs (hh, h*lo, lo*h). LNF: fused LayerNorm(COUT=128)+split epilogue.
#define TC_SMEM 196608

template<int CIN, int KW, int COUT, bool RELU, bool WF32, bool WSPLIT, bool LNF>
__global__ void __launch_bounds__(256)
tconv(const bf16* __restrict__ Ahi, const bf16* __restrict__ Alo,
      const bf16* __restrict__ Whi, const bf16* __restrict__ Wlo,
      const float* __restrict__ Bias,
      const float* __restrict__ LG, const float* __restrict__ LB,
      float* __restrict__ Yf, bf16* __restrict__ Yhi, bf16* __restrict__ Ylo)
{
    constexpr int KTOT = CIN * KW;
    constexpr int NCH  = KTOT / 64;
    constexpr int PAD  = (KW == 3) ? 1 : 0;

    extern __shared__ char smem[];
    const int tid = threadIdx.x;
    const int pm0 = blockIdx.x * 128;
    const int nv0 = blockIdx.y * 128;

    const int wid = tid >> 5, lane = tid & 31;
    const int wm = (wid >> 1) * 32;
    const int wn = (wid & 1) * 64;
    const int lr = lane & 7, lq = lane >> 3;

    float acc[2][8][4];
#pragma unroll
    for (int mi = 0; mi < 2; mi++)
#pragma unroll
        for (int ni = 0; ni < 8; ni++)
#pragma unroll
            for (int e = 0; e < 4; e++) acc[mi][ni][e] = 0.f;

    const uint4* A4h = reinterpret_cast<const uint4*>(Ahi);
    const uint4* A4l = reinterpret_cast<const uint4*>(Alo);
    const uint4* B4h = reinterpret_cast<const uint4*>(Whi);
    const uint4* B4l = reinterpret_cast<const uint4*>(Wlo);

    const uint32_t sb = smem_to_u32(smem);

    auto load_chunk = [&](int ch, int buf) {
        const uint32_t bo = (uint32_t)buf * 65536u;
        const int tap = (ch * 64) / CIN;
        const int ci0 = (ch * 64) % CIN;
#pragma unroll
        for (int i = 0; i < 4; i++) {
            int idx = tid + i * 256;
            int row = idx >> 3, c = idx & 7;
            int p = pm0 + row;
            bool ok = true;
            if (KW == 3) {
                int ls = (p & (LSEQ - 1)) + tap - PAD;
                ok = ((unsigned)ls < (unsigned)LSEQ);
            }
            size_t gi = ok ? ((size_t)(p + tap - PAD) * (CIN / 8) + (ci0 / 8) + c) : 0;
            int nb = ok ? 16 : 0;
            int pc = (c ^ row) & 7;
            uint32_t so = (uint32_t)(row * 128 + pc * 16);
            cp_async16(sb + bo + so,          A4h + gi, nb);
            cp_async16(sb + bo + 16384u + so, A4l + gi, nb);
        }
#pragma unroll
        for (int i = 0; i < 4; i++) {
            int idx = tid + i * 256;
            int row = idx >> 3, c = idx & 7;
            size_t gi = (size_t)(nv0 + row) * (KTOT / 8) + ch * 8 + c;
            int pc = (c ^ row) & 7;
            uint32_t so = (uint32_t)(row * 128 + pc * 16);
            cp_async16(sb + bo + 32768u + so, B4h + gi, 16);
            cp_async16(sb + bo + 49152u + so, B4l + gi, 16);
        }
        asm volatile("cp.async.commit_group;");
    };

    load_chunk(0, 0);
    if (1 < NCH) load_chunk(1, 1);

    for (int ch = 0; ch < NCH; ch++) {
        if (ch + 1 < NCH)
            asm volatile("cp.async.wait_group 1;");
        else
            asm volatile("cp.async.wait_group 0;");
        __syncthreads();
        if (ch + 2 < NCH) load_chunk(ch + 2, (ch + 2) % 3);

        const uint32_t bo = (uint32_t)(ch % 3) * 65536u;
        const uint32_t aHB = sb + bo;
        const uint32_t aLB = sb + bo + 16384u;
        const uint32_t bHB = sb + bo + 32768u;
        const uint32_t bLB = sb + bo + 49152u;
#pragma unroll
        for (int k16 = 0; k16 < 4; k16++) {
            const int kc0 = k16 * 2;
            uint32_t ah[2][4], al[2][4];
#pragma unroll
            for (int mi = 0; mi < 2; mi++) {
                int row = wm + mi * 16 + lr + (lq & 1) * 8;
                int kc  = kc0 + (lq >> 1);
                int pc  = (kc ^ row) & 7;
                ldsm_x4(ah[mi], aHB + row * 128 + pc * 16);
                ldsm_x4(al[mi], aLB + row * 128 + pc * 16);
            }
#pragma unroll
            for (int nc = 0; nc < 4; nc++) {
                uint32_t bh[4], bl[4];
                int row = wn + nc * 16 + lr + (lq >> 1) * 8;
                int kc  = kc0 + (lq & 1);
                int pc  = (kc ^ row) & 7;
                ldsm_x4(bh, bHB + row * 128 + pc * 16);
                ldsm_x4(bl, bLB + row * 128 + pc * 16);
                // hh
                mma16816(acc[0][nc * 2 + 0], ah[0], bh[0], bh[1]);
                mma16816(acc[0][nc * 2 + 1], ah[0], bh[2], bh[3]);
                mma16816(acc[1][nc * 2 + 0], ah[1], bh[0], bh[1]);
                mma16816(acc[1][nc * 2 + 1], ah[1], bh[2], bh[3]);
                // h * lo
                mma16816(acc[0][nc * 2 + 0], ah[0], bl[0], bl[1]);
                mma16816(acc[0][nc * 2 + 1], ah[0], bl[2], bl[3]);
                mma16816(acc[1][nc * 2 + 0], ah[1], bl[0], bl[1]);
                mma16816(acc[1][nc * 2 + 1], ah[1], bl[2], bl[3]);
                // lo * h
                mma16816(acc[0][nc * 2 + 0], al[0], bh[0], bh[1]);
                mma16816(acc[0][nc * 2 + 1], al[0], bh[2], bh[3]);
                mma16816(acc[1][nc * 2 + 0], al[1], bh[0], bh[1]);
                mma16816(acc[1][nc * 2 + 1], al[1], bh[2], bh[3]);
            }
        }
    }

    const int gid = lane >> 2, tig = lane & 3;
    // bias (+relu) into acc in place
#pragma unroll
    for (int mi = 0; mi < 2; mi++)
#pragma unroll
        for (int ni = 0; ni < 8; ni++) {
            const int n = nv0 + wn + ni * 8 + tig * 2;
            const float2 bv = *reinterpret_cast<const float2*>(Bias + n);
            acc[mi][ni][0] += bv.x;  acc[mi][ni][1] += bv.y;
            acc[mi][ni][2] += bv.x;  acc[mi][ni][3] += bv.y;
            if (RELU) {
#pragma unroll
                for (int e = 0; e < 4; e++) acc[mi][ni][e] = fmaxf(acc[mi][ni][e], 0.f);
            }
        }

    if (LNF) {
        float* red = reinterpret_cast<float*>(smem);
        __syncthreads();
        float ps[2][2];
#pragma unroll
        for (int mi = 0; mi < 2; mi++) { ps[mi][0] = 0.f; ps[mi][1] = 0.f; }
#pragma unroll
        for (int mi = 0; mi < 2; mi++)
#pragma unroll
            for (int ni = 0; ni < 8; ni++) {
                ps[mi][0] += acc[mi][ni][0] + acc[mi][ni][1];
                ps[mi][1] += acc[mi][ni][2] + acc[mi][ni][3];
            }
#pragma unroll
        for (int mi = 0; mi < 2; mi++)
#pragma unroll
            for (int h = 0; h < 2; h++) {
                ps[mi][h] += __shfl_xor_sync(0xffffffffu, ps[mi][h], 1);
                ps[mi][h] += __shfl_xor_sync(0xffffffffu, ps[mi][h], 2);
            }
        if (tig == 0) {
#pragma unroll
            for (int mi = 0; mi < 2; mi++)
#pragma unroll
                for (int h = 0; h < 2; h++) {
                    int row = wm + mi * 16 + gid + h * 8;
                    red[row * 2 + (wn >> 6)] = ps[mi][h];
                }
        }
        __syncthreads();
        float mu[2][2];
#pragma unroll
        for (int mi = 0; mi < 2; mi++)
#pragma unroll
            for (int h = 0; h < 2; h++) {
                int row = wm + mi * 16 + gid + h * 8;
                mu[mi][h] = (red[row * 2] + red[row * 2 + 1]) * (1.f / 128.f);
            }
        float q[2][2];
#pragma unroll
        for (int mi = 0; mi < 2; mi++) { q[mi][0] = 0.f; q[mi][1] = 0.f; }
#pragma unroll
        for (int mi = 0; mi < 2; mi++)
#pragma unroll
            for (int ni = 0; ni < 8; ni++) {
                float d0 = acc[mi][ni][0] - mu[mi][0];
                float d1 = acc[mi][ni][1] - mu[mi][0];
                float d2 = acc[mi][ni][2] - mu[mi][1];
                float d3 = acc[mi][ni][3] - mu[mi][1];
                q[mi][0] += d0 * d0 + d1 * d1;
                q[mi][1] += d2 * d2 + d3 * d3;
            }
#pragma unroll
        for (int mi = 0; mi < 2; mi++)
#pragma unroll
            for (int h = 0; h < 2; h++) {
                q[mi][h] += __shfl_xor_sync(0xffffffffu, q[mi][h], 1);
                q[mi][h] += __shfl_xor_sync(0xffffffffu, q[mi][h], 2);
            }
        if (tig == 0) {
#pragma unroll
            for (int mi = 0; mi < 2; mi++)
#pragma unroll
                for (int h = 0; h < 2; h++) {
                    int row = wm + mi * 16 + gid + h * 8;
                    red[256 + row * 2 + (wn >> 6)] = q[mi][h];
                }
        }
        __syncthreads();
        float rs[2][2];
#pragma unroll
        for (int mi = 0; mi < 2; mi++)
#pragma unroll
            for (int h = 0; h < 2; h++) {
                int row = wm + mi * 16 + gid + h * 8;
                float var = (red[256 + row * 2] + red[256 + row * 2 + 1]) * (1.f / 128.f);
                rs[mi][h] = rsqrtf(var + LN_EPS);
            }
#pragma unroll
        for (int mi = 0; mi < 2; mi++) {
            const int m0 = pm0 + wm + mi * 16 + gid;
#pragma unroll
            for (int ni = 0; ni < 8; ni++) {
                const int c = wn + ni * 8 + tig * 2;
                const float2 gv = *reinterpret_cast<const float2*>(LG + c);
                const float2 bb = *reinterpret_cast<const float2*>(LB + c);
                float y0 = (acc[mi][ni][0] - mu[mi][0]) * rs[mi][0] * gv.x + bb.x;
                float y1 = (acc[mi][ni][1] - mu[mi][0]) * rs[mi][0] * gv.y + bb.y;
                float y2 = (acc[mi][ni][2] - mu[mi][1]) * rs[mi][1] * gv.x + bb.x;
                float y3 = (acc[mi][ni][3] - mu[mi][1]) * rs[mi][1] * gv.y + bb.y;
                bf16 h0 = __float2bfloat16(y0), h1 = __float2bfloat16(y1);
                bf16 h2 = __float2bfloat16(y2), h3 = __float2bfloat16(y3);
                __nv_bfloat162 p0; p0.x = h0; p0.y = h1;
                __nv_bfloat162 p1; p1.x = h2; p1.y = h3;
                *reinterpret_cast<__nv_bfloat162*>(Yhi + (size_t)m0 * COUT + c)       = p0;
                *reinterpret_cast<__nv_bfloat162*>(Yhi + (size_t)(m0 + 8) * COUT + c) = p1;
                p0.x = __float2bfloat16(y0 - __bfloat162float(h0));
                p0.y = __float2bfloat16(y1 - __bfloat162float(h1));
                p1.x = __float2bfloat16(y2 - __bfloat162float(h2));
                p1.y = __float2bfloat16(y3 - __bfloat162float(h3));
                *reinterpret_cast<__nv_bfloat162*>(Ylo + (size_t)m0 * COUT + c)       = p0;
                *reinterpret_cast<__nv_bfloat162*>(Ylo + (size_t)(m0 + 8) * COUT + c) = p1;
            }
        }
        return;
    }

#pragma unroll
    for (int mi = 0; mi < 2; mi++) {
        const int m0 = pm0 + wm + mi * 16 + gid;
#pragma unroll
        for (int ni = 0; ni < 8; ni++) {
            const int n = nv0 + wn + ni * 8 + tig * 2;
            float v00 = acc[mi][ni][0];
            float v01 = acc[mi][ni][1];
            float v10 = acc[mi][ni][2];
            float v11 = acc[mi][ni][3];
            if (WF32) {
                float2 a0; a0.x = v00; a0.y = v01;
                float2 a1; a1.x = v10; a1.y = v11;
                *reinterpret_cast<float2*>(Yf + (size_t)m0 * COUT + n)       = a0;
                *reinterpret_cast<float2*>(Yf + (size_t)(m0 + 8) * COUT + n) = a1;
            }
            if (WSPLIT) {
                bf16 h00 = __float2bfloat16(v00), h01 = __float2bfloat16(v01);
                bf16 h10 = __float2bfloat16(v10), h11 = __float2bfloat16(v11);
                __nv_bfloat162 hh0; hh0.x = h00; hh0.y = h01;
                __nv_bfloat162 hh1; hh1.x = h10; hh1.y = h11;
                __nv_bfloat162 ll0;
                ll0.x = __float2bfloat16(v00 - __bfloat162float(h00));
                ll0.y = __float2bfloat16(v01 - __bfloat162float(h01));
                __nv_bfloat162 ll1;
                ll1.x = __float2bfloat16(v10 - __bfloat162float(h10));
                ll1.y = __float2bfloat16(v11 - __bfloat162float(h11));
                *reinterpret_cast<__nv_bfloat162*>(Yhi + (size_t)m0 * COUT + n)       = hh0;
                *reinterpret_cast<__nv_bfloat162*>(Yhi + (size_t)(m0 + 8) * COUT + n) = hh1;
                *reinterpret_cast<__nv_bfloat162*>(Ylo + (size_t)m0 * COUT + n)       = ll0;
                *reinterpret_cast<__nv_bfloat162*>(Ylo + (size_t)(m0 + 8) * COUT + n) = ll1;
            }
        }
    }
}

// ---------------- fp16 two-split tensor conv (encoder), fused-term loop ------
template<int CIN, int KW, int COUT, bool WF32>
__global__ void __launch_bounds__(256)
tconvh(const half* __restrict__ Ah, const half* __restrict__ Am,
       const half* __restrict__ Wh, const half* __restrict__ Wm,
       const float* __restrict__ Bias, float* __restrict__ Yf,
       half* __restrict__ Yh, half* __restrict__ Ym)
{
    constexpr int KTOT = CIN * KW;
    constexpr int NCH  = KTOT / 64;
    constexpr int PAD  = (KW == 3) ? 1 : 0;

    extern __shared__ char smem[];
    const int tid = threadIdx.x;
    const int pm0 = blockIdx.x * 128;
    const int nv0 = blockIdx.y * 128;

    const int wid = tid >> 5, lane = tid & 31;
    const int wm = (wid >> 1) * 32;
    const int wn = (wid & 1) * 64;
    const int lr = lane & 7, lq = lane >> 3;

    float acc1[2][8][4];
    float acc2[2][8][4];
#pragma unroll
    for (int mi = 0; mi < 2; mi++)
#pragma unroll
        for (int ni = 0; ni < 8; ni++)
#pragma unroll
            for (int e = 0; e < 4; e++) { acc1[mi][ni][e] = 0.f; acc2[mi][ni][e] = 0.f; }

    const uint4* A4h = reinterpret_cast<const uint4*>(Ah);
    const uint4* A4m = reinterpret_cast<const uint4*>(Am);
    const uint4* B4h = reinterpret_cast<const uint4*>(Wh);
    const uint4* B4m = reinterpret_cast<const uint4*>(Wm);

    const uint32_t sb = smem_to_u32(smem);

    auto load_chunk = [&](int ch, int buf) {
        const uint32_t bo = (uint32_t)buf * 65536u;
        const int tap = (ch * 64) / CIN;
        const int ci0 = (ch * 64) % CIN;
#pragma unroll
        for (int i = 0; i < 4; i++) {
            int idx = tid + i * 256;
            int row = idx >> 3, c = idx & 7;
            int p = pm0 + row;
            bool ok = true;
            if (KW == 3) {
                int ls = (p & (LSEQ - 1)) + tap - PAD;
                ok = ((unsigned)ls < (unsigned)LSEQ);
            }
            size_t gi = ok ? ((size_t)(p + tap - PAD) * (CIN / 8) + (ci0 / 8) + c) : 0;
            int nb = ok ? 16 : 0;
            int pc = (c ^ row) & 7;
            uint32_t so = (uint32_t)(row * 128 + pc * 16);
            cp_async16(sb + bo + so,          A4h + gi, nb);
            cp_async16(sb + bo + 16384u + so, A4m + gi, nb);
        }
#pragma unroll
        for (int i = 0; i < 4; i++) {
            int idx = tid + i * 256;
            int row = idx >> 3, c = idx & 7;
            size_t gi = (size_t)(nv0 + row) * (KTOT / 8) + ch * 8 + c;
            int pc = (c ^ row) & 7;
            uint32_t so = (uint32_t)(row * 128 + pc * 16);
            cp_async16(sb + bo + 32768u + so, B4h + gi, 16);
            cp_async16(sb + bo + 49152u + so, B4m + gi, 16);
        }
        asm volatile("cp.async.commit_group;");
    };

    load_chunk(0, 0);
    if (1 < NCH) load_chunk(1, 1);

    for (int ch = 0; ch < NCH; ch++) {
        if (ch + 1 < NCH)
            asm volatile("cp.async.wait_group 1;");
        else
            asm volatile("cp.async.wait_group 0;");
        __syncthreads();
        if (ch + 2 < NCH) load_chunk(ch + 2, (ch + 2) % 3);

        const uint32_t bo = (uint32_t)(ch % 3) * 65536u;
        const uint32_t aHB = sb + bo;
        const uint32_t aMB = sb + bo + 16384u;
        const uint32_t bHB = sb + bo + 32768u;
        const uint32_t bMB = sb + bo + 49152u;
#pragma unroll
        for (int k16 = 0; k16 < 4; k16++) {
            const int kc0 = k16 * 2;
            uint32_t ah[2][4], am[2][4];
#pragma unroll
            for (int mi = 0; mi < 2; mi++) {
                int row = wm + mi * 16 + lr + (lq & 1) * 8;
                int kc  = kc0 + (lq >> 1);
                int pc  = (kc ^ row) & 7;
                ldsm_x4(ah[mi], aHB + row * 128 + pc * 16);
                ldsm_x4(am[mi], aMB + row * 128 + pc * 16);
            }
#pragma unroll
            for (int nc = 0; nc < 4; nc++) {
                uint32_t bh[4], bm[4];
                int row = wn + nc * 16 + lr + (lq >> 1) * 8;
                int kc  = kc0 + (lq & 1);
                int pc  = (kc ^ row) & 7;
                ldsm_x4(bh, bHB + row * 128 + pc * 16);
                ldsm_x4(bm, bMB + row * 128 + pc * 16);
                // hh -> acc1
                mma16816h(acc1[0][nc * 2 + 0], ah[0], bh[0], bh[1]);
                mma16816h(acc1[0][nc * 2 + 1], ah[0], bh[2], bh[3]);
                mma16816h(acc1[1][nc * 2 + 0], ah[1], bh[0], bh[1]);
                mma16816h(acc1[1][nc * 2 + 1], ah[1], bh[2], bh[3]);
                // h*m -> acc2
                mma16816h(acc2[0][nc * 2 + 0], ah[0], bm[0], bm[1]);
                mma16816h(acc2[0][nc * 2 + 1], ah[0], bm[2], bm[3]);
                mma16816h(acc2[1][nc * 2 + 0], ah[1], bm[0], bm[1]);
                mma16816h(acc2[1][nc * 2 + 1], ah[1], bm[2], bm[3]);
                // m*h -> acc2
                mma16816h(acc2[0][nc * 2 + 0], am[0], bh[0], bh[1]);
                mma16816h(acc2[0][nc * 2 + 1], am[0], bh[2], bh[3]);
                mma16816h(acc2[1][nc * 2 + 0], am[1], bh[0], bh[1]);
                mma16816h(acc2[1][nc * 2 + 1], am[1], bh[2], bh[3]);
            }
        }
    }

    const int gid = lane >> 2, tig = lane & 3;
#pragma unroll
    for (int mi = 0; mi < 2; mi++) {
        const int m0 = pm0 + wm + mi * 16 + gid;
#pragma unroll
        for (int ni = 0; ni < 8; ni++) {
            const int n = nv0 + wn + ni * 8 + tig * 2;
            const float2 bv = *reinterpret_cast<const float2*>(Bias + n);
            float v00 = fmaxf(fmaf(acc2[mi][ni][0], LO_INV, acc1[mi][ni][0]) + bv.x, 0.f);
            float v01 = fmaxf(fmaf(acc2[mi][ni][1], LO_INV, acc1[mi][ni][1]) + bv.y, 0.f);
            float v10 = fmaxf(fmaf(acc2[mi][ni][2], LO_INV, acc1[mi][ni][2]) + bv.x, 0.f);
            float v11 = fmaxf(fmaf(acc2[mi][ni][3], LO_INV, acc1[mi][ni][3]) + bv.y, 0.f);
            if (WF32) {
                float2 a0; a0.x = v00; a0.y = v01;
                float2 a1; a1.x = v10; a1.y = v11;
                *reinterpret_cast<float2*>(Yf + (size_t)m0 * COUT + n)       = a0;
                *reinterpret_cast<float2*>(Yf + (size_t)(m0 + 8) * COUT + n) = a1;
            } else {
                half h00,m00,h01,m01,h10,m10,h11,m11;
                split2h(v00,h00,m00); split2h(v01,h01,m01);
                split2h(v10,h10,m10); split2h(v11,h11,m11);
                __half2 p0, p1;
                p0.x=h00; p0.y=h01; p1.x=h10; p1.y=h11;
                *reinterpret_cast<__half2*>(Yh + (size_t)m0 * COUT + n)       = p0;
                *reinterpret_cast<__half2*>(Yh + (size_t)(m0 + 8) * COUT + n) = p1;
                p0.x=m00; p0.y=m01; p1.x=m10; p1.y=m11;
                *reinterpret_cast<__half2*>(Ym + (size_t)m0 * COUT + n)       = p0;
                *reinterpret_cast<__half2*>(Ym + (size_t)(m0 + 8) * COUT + n) = p1;
            }
        }
    }
}

// ---------------- wide full-K-resident bf16x3 logits GEMM, fused-term --------
#define LGW_SMEM 196608

__global__ void __launch_bounds__(256, 1)
logits_wide(const bf16* __restrict__ Ahi, const bf16* __restrict__ Alo,
            const bf16* __restrict__ Bhi, const bf16* __restrict__ Blo,
            const float* __restrict__ Bias, float* __restrict__ Out)
{
    extern __shared__ char smem[];
    const int tid = threadIdx.x;
    const int pm0 = blockIdx.x * 128;
    const int nv0 = blockIdx.y * 256;

    const uint32_t sb = smem_to_u32(smem);

    {
        const uint4* A4h = reinterpret_cast<const uint4*>(Ahi);
        const uint4* A4l = reinterpret_cast<const uint4*>(Alo);
#pragma unroll
        for (int i = 0; i < 8; i++) {
            int idx = tid + i * 256;
            int row = idx >> 4, c = idx & 15;
            int pc = (c & 8) | ((c ^ row) & 7);
            cp_async16(sb + (uint32_t)(row * 256 + pc * 16),
                       A4h + (size_t)(pm0 + row) * 16 + c, 16);
            cp_async16(sb + 32768u + (uint32_t)(row * 256 + pc * 16),
                       A4l + (size_t)(pm0 + row) * 16 + c, 16);
        }
        const uint4* B4h = reinterpret_cast<const uint4*>(Bhi);
        const uint4* B4l = reinterpret_cast<const uint4*>(Blo);
#pragma unroll
        for (int i = 0; i < 16; i++) {
            int idx = tid + i * 256;
            int row = idx >> 4, c = idx & 15;
            int pc = (c & 8) | ((c ^ row) & 7);
            cp_async16(sb + 65536u + (uint32_t)(row * 256 + pc * 16),
                       B4h + (size_t)(nv0 + row) * 16 + c, 16);
            cp_async16(sb + 131072u + (uint32_t)(row * 256 + pc * 16),
                       B4l + (size_t)(nv0 + row) * 16 + c, 16);
        }
        asm volatile("cp.async.commit_group;");
    }

    const int wid = tid >> 5, lane = tid & 31;
    const int wm = (wid >> 1) * 32;       // 0,32,64,96
    const int wn = (wid & 1) * 128;       // 0,128
    const int lr = lane & 7, lq = lane >> 3;

    float acc[2][16][4];
#pragma unroll
    for (int mi = 0; mi < 2; mi++)
#pragma unroll
        for (int ni = 0; ni < 16; ni++)
#pragma unroll
            for (int e = 0; e < 4; e++) acc[mi][ni][e] = 0.f;

    asm volatile("cp.async.wait_group 0;");
    __syncthreads();

#pragma unroll
    for (int k16 = 0; k16 < 8; k16++) {
        const int kc0 = k16 * 2;
        uint32_t ah[2][4], al[2][4];
#pragma unroll
        for (int mi = 0; mi < 2; mi++) {
            int row = wm + mi * 16 + lr + (lq & 1) * 8;
            int kc  = kc0 + (lq >> 1);
            int pc  = (kc & 8) | ((kc ^ row) & 7);
            ldsm_x4(ah[mi], sb + row * 256 + pc * 16);
            ldsm_x4(al[mi], sb + 32768u + row * 256 + pc * 16);
        }
#pragma unroll
        for (int nc = 0; nc < 8; nc++) {
            uint32_t bh[4], bl[4];
            int row = wn + nc * 16 + lr + (lq >> 1) * 8;
            int kc  = kc0 + (lq & 1);
            int pc  = (kc & 8) | ((kc ^ row) & 7);
            ldsm_x4(bh, sb + 65536u + row * 256 + pc * 16);
            ldsm_x4(bl, sb + 131072u + row * 256 + pc * 16);
            // hh
            mma16816(acc[0][nc * 2 + 0], ah[0], bh[0], bh[1]);
            mma16816(acc[0][nc * 2 + 1], ah[0], bh[2], bh[3]);
            mma16816(acc[1][nc * 2 + 0], ah[1], bh[0], bh[1]);
            mma16816(acc[1][nc * 2 + 1], ah[1], bh[2], bh[3]);
            // h * lo
            mma16816(acc[0][nc * 2 + 0], ah[0], bl[0], bl[1]);
            mma16816(acc[0][nc * 2 + 1], ah[0], bl[2], bl[3]);
            mma16816(acc[1][nc * 2 + 0], ah[1], bl[0], bl[1]);
            mma16816(acc[1][nc * 2 + 1], ah[1], bl[2], bl[3]);
            // lo * h
            mma16816(acc[0][nc * 2 + 0], al[0], bh[0], bh[1]);
            mma16816(acc[0][nc * 2 + 1], al[0], bh[2], bh[3]);
            mma16816(acc[1][nc * 2 + 0], al[1], bh[0], bh[1]);
            mma16816(acc[1][nc * 2 + 1], al[1], bh[2], bh[3]);
        }
    }

    const int gid = lane >> 2, tig = lane & 3;
#pragma unroll
    for (int mi = 0; mi < 2; mi++) {
        const int m0 = pm0 + wm + mi * 16 + gid;
#pragma unroll
        for (int ni = 0; ni < 16; ni++) {
            const int n = nv0 + wn + ni * 8 + tig * 2;
            const float2 bv = *reinterpret_cast<const float2*>(Bias + n);
            float2 v0, v1;
            v0.x = acc[mi][ni][0] + bv.x;  v0.y = acc[mi][ni][1] + bv.y;
            v1.x = acc[mi][ni][2] + bv.x;  v1.y = acc[mi][ni][3] + bv.y;
            *reinterpret_cast<float2*>(Out + (size_t)m0 * VOCAB + n)       = v0;
            *reinterpret_cast<float2*>(Out + (size_t)(m0 + 8) * VOCAB + n) = v1;
        }
    }
}

// ---------------- tail: loss scalar + codes ----------------------------------
__global__ void commit_final(const float* __restrict__ Part, float* __restrict__ slot)
{
    if (threadIdx.x == 0 && blockIdx.x == 0) {
        float s = 0.f;
        for (int i = 0; i < NPOS / 64; i++) s += Part[i];
        *slot = 0.1f * s / ((float)NPOS * (float)DDIM);
    }
}

__global__ void write_codes(const int* __restrict__ codes, float* __restrict__ out)
{
    int n = blockIdx.x * blockDim.x + threadIdx.x;
    if (n < NPOS) out[n] = (float)codes[n];
}

// ---------------- launch ------------------------------------------------------
extern "C" void kernel_launch(void* const* d_in, const int* in_sizes, int n_in,
                              void* d_out, int out_size)
{
    (void)in_sizes; (void)n_in;
    const int*   x    = (const int*)  d_in[0];
    const float* tok  = (const float*)d_in[1];
    const float* ew1  = (const float*)d_in[2];
    const float* eb1  = (const float*)d_in[3];
    const float* ew2  = (const float*)d_in[4];
    const float* eb2  = (const float*)d_in[5];
    const float* ew3  = (const float*)d_in[6];
    const float* eb3  = (const float*)d_in[7];
    const float* elg  = (const float*)d_in[8];
    const float* elb  = (const float*)d_in[9];
    const float* cb   = (const float*)d_in[10];
    const float* dw1  = (const float*)d_in[11];
    const float* db1  = (const float*)d_in[12];
    const float* dw2  = (const float*)d_in[13];
    const float* db2  = (const float*)d_in[14];
    const float* dw3  = (const float*)d_in[15];
    const float* db3  = (const float*)d_in[16];
    const float* dlg  = (const float*)d_in[17];
    const float* dlb  = (const float*)d_in[18];
    const float* ow   = (const float*)d_in[19];
    const float* ob   = (const float*)d_in[20];
    float* out = (float*)d_out;

    float *h2, *z, *cn, *cp;
    int* codes;
    half *ebh,*ebm,*e1h,*e1m,*w1eh,*w1em,*w2eh,*w2em;
    bf16 *zqhi,*zqlo,*d1hi,*d1lo,*d2hi,*d2lo,*ahi,*alo;
    bf16 *w1hi,*w1lo,*w2hi,*w2lo,*w3hi,*w3lo,*bhi,*blo;
    cudaGetSymbolAddress((void**)&h2,    g_h2);
    cudaGetSymbolAddress((void**)&z,     g_z);
    cudaGetSymbolAddress((void**)&codes, g_codes);
    cudaGetSymbolAddress((void**)&cn,    g_cnorm);
    cudaGetSymbolAddress((void**)&cp,    g_commit);
    cudaGetSymbolAddress((void**)&ebh,   g_ebh);
    cudaGetSymbolAddress((void**)&ebm,   g_ebm);
    cudaGetSymbolAddress((void**)&e1h,   g_e1h);
    cudaGetSymbolAddress((void**)&e1m,   g_e1m);
    cudaGetSymbolAddress((void**)&w1eh,  g_w1eh);
    cudaGetSymbolAddress((void**)&w1em,  g_w1em);
    cudaGetSymbolAddress((void**)&w2eh,  g_w2eh);
    cudaGetSymbolAddress((void**)&w2em,  g_w2em);
    cudaGetSymbolAddress((void**)&zqhi,  g_zqhi);
    cudaGetSymbolAddress((void**)&zqlo,  g_zqlo);
    cudaGetSymbolAddress((void**)&d1hi,  g_d1hi);
    cudaGetSymbolAddress((void**)&d1lo,  g_d1lo);
    cudaGetSymbolAddress((void**)&d2hi,  g_d2hi);
    cudaGetSymbolAddress((void**)&d2lo,  g_d2lo);
    cudaGetSymbolAddress((void**)&ahi,   g_ahi);
    cudaGetSymbolAddress((void**)&alo,   g_alo);
    cudaGetSymbolAddress((void**)&w1hi,  g_w1hi);
    cudaGetSymbolAddress((void**)&w1lo,  g_w1lo);
    cudaGetSymbolAddress((void**)&w2hi,  g_w2hi);
    cudaGetSymbolAddress((void**)&w2lo,  g_w2lo);
    cudaGetSymbolAddress((void**)&w3hi,  g_w3hi);
    cudaGetSymbolAddress((void**)&w3lo,  g_w3lo);
    cudaGetSymbolAddress((void**)&bhi,   g_bhi);
    cudaGetSymbolAddress((void**)&blo,   g_blo);

    cudaFuncSetAttribute((const void*)tconvh<128, 3, 256, false>,
                         cudaFuncAttributeMaxDynamicSharedMemorySize, TC_SMEM);
    cudaFuncSetAttribute((const void*)tconvh<256, 3, 256, true>,
                         cudaFuncAttributeMaxDynamicSharedMemorySize, TC_SMEM);
    cudaFuncSetAttribute((const void*)tconv< 64, 1, 256, true,  false, true,  false>,
                         cudaFuncAttributeMaxDynamicSharedMemorySize, TC_SMEM);
    cudaFuncSetAttribute((const void*)tconv<256, 3, 256, true,  false, true,  false>,
                         cudaFuncAttributeMaxDynamicSharedMemorySize, TC_SMEM);
    cudaFuncSetAttribute((const void*)tconv<256, 1, 128, true,  false, false, true >,
                         cudaFuncAttributeMaxDynamicSharedMemorySize, TC_SMEM);
    cudaFuncSetAttribute((const void*)logits_wide,
                         cudaFuncAttributeMaxDynamicSharedMemorySize, LGW_SMEM);

    // ---- encoder (fp16 two-split tensor cores, pipelined, fused-term) ----
    pack_split2h<128, 3, 256><<<(256*384)  / 256, 256>>>(ew1, w1eh, w1em);
    pack_split2h<256, 3, 256><<<(256*768)  / 256, 256>>>(ew2, w2eh, w2em);
    embed_split2h<<<NPOS * 32 / 256, 256>>>(x, tok, ebh, ebm);
    tconvh<128, 3, 256, false><<<dim3(NPOS/128, 2), 256, TC_SMEM>>>(
        ebh, ebm, w1eh, w1em, eb1, nullptr, e1h, e1m);
    tconvh<256, 3, 256, true ><<<dim3(NPOS/128, 2), 256, TC_SMEM>>>(
        e1h, e1m, w2eh, w2em, eb2, h2, nullptr, nullptr);
    enc_head_ln<<<NPOS / 64, 256>>>(h2, ew3, eb3, elg, elb, z);

    // ---- vector quantization ----
    cnorm_kernel<<<1, 512>>>(cb, cn);
    vq_kernel<<<NPOS / 64, 256>>>(z, cb, cn, codes, cp);
    gather_zq_split<<<NPOS * 16 / 256, 256>>>(codes, cb, zqhi, zqlo);

    // ---- decoder weight packs + decoder (bf16x3 tensor cores, fused-term) ----
    pack_split< 64, 1, 256>  <<<(256*64)   / 256, 256>>>(dw1, w1hi, w1lo);
    pack_split<256, 3, 256>  <<<(256*768)  / 256, 256>>>(dw2, w2hi, w2lo);
    pack_split<256, 1, 128>  <<<(128*256)  / 256, 256>>>(dw3, w3hi, w3lo);
    pack_split<128, 1, VOCAB><<<(VOCAB*128)/ 256, 256>>>(ow,  bhi,  blo);

    tconv< 64, 1, 256, true,  false, true,  false><<<dim3(NPOS/128, 2), 256, TC_SMEM>>>(
        zqhi, zqlo, w1hi, w1lo, db1, nullptr, nullptr, nullptr, d1hi, d1lo);
    tconv<256, 3, 256, true,  false, true,  false><<<dim3(NPOS/128, 2), 256, TC_SMEM>>>(
        d1hi, d1lo, w2hi, w2lo, db2, nullptr, nullptr, nullptr, d2hi, d2lo);
    // conv3 + fused LayerNorm + bf16 split (COUT=128 = full feature row)
    tconv<256, 1, 128, true,  false, false, true ><<<dim3(NPOS/128, 1), 256, TC_SMEM>>>(
        d2hi, d2lo, w3hi, w3lo, db3, dlg, dlb, nullptr, ahi, alo);

    // ---- vocab projection (wide full-K bf16x3, fused-term) -> d_out ----
    logits_wide<<<dim3(NPOS/128, VOCAB/256), 256, LGW_SMEM>>>(
        ahi, alo, bhi, blo, ob, out);

    // ---- tail: loss scalar + codes ----
    const long long NV = (long long)NPOS * VOCAB;   // 134217728
    if ((long long)out_size >= NV + 1)
        commit_final<<<1, 32>>>(cp, out + NV);
    if ((long long)out_size >= NV + 1 + NPOS)
        write_codes<<<NPOS / 256, 256>>>(codes, out + NV + 1);
}

// round 13
// speedup vs baseline: 1.0258x; 1.0103x over previous
#include <cuda_runtime.h>
#include <cuda_bf16.h>
#include <cuda_fp16.h>
#include <cstdint>

// Problem constants
#define NPOS   32768          // B*L = 8*4096
#define LSEQ   4096
#define EDIM   128
#define HDIM   256
#define DDIM   64
#define KCODE  512
#define VOCAB  4096
#define LN_EPS 1e-5f

typedef __nv_bfloat16 bf16;

#define LO_SCALE   2048.0f
#define LO_INV     (1.0f / 2048.0f)

// ---------------- scratch (static device globals; no allocation) -------------
__device__ float g_h2 [NPOS * HDIM];    // encoder conv2 output (fp32)
__device__ float g_z  [NPOS * DDIM];    // z_e after LN
__device__ int   g_codes[NPOS];
__device__ float g_cnorm[KCODE];
__device__ float g_commit[NPOS / 64];
// encoder fp16 two-split activations (lo scaled by 2048)
__device__ __align__(16) half g_ebh[NPOS * EDIM];
__device__ __align__(16) half g_ebm[NPOS * EDIM];
__device__ __align__(16) half g_e1h[NPOS * HDIM];
__device__ __align__(16) half g_e1m[NPOS * HDIM];
// encoder fp16 two-split packed weights
__device__ __align__(16) half g_w1eh[HDIM * EDIM * 3];
__device__ __align__(16) half g_w1em[HDIM * EDIM * 3];
__device__ __align__(16) half g_w2eh[HDIM * HDIM * 3];
__device__ __align__(16) half g_w2em[HDIM * HDIM * 3];
// decoder bf16 hi/lo split activations
__device__ __align__(16) bf16 g_zqhi[NPOS * DDIM];
__device__ __align__(16) bf16 g_zqlo[NPOS * DDIM];
__device__ __align__(16) bf16 g_d1hi[NPOS * HDIM];
__device__ __align__(16) bf16 g_d1lo[NPOS * HDIM];
__device__ __align__(16) bf16 g_d2hi[NPOS * HDIM];
__device__ __align__(16) bf16 g_d2lo[NPOS * HDIM];
__device__ __align__(16) bf16 g_ahi[NPOS * EDIM];
__device__ __align__(16) bf16 g_alo[NPOS * EDIM];
// decoder bf16 hi/lo split packed weights
__device__ __align__(16) bf16 g_w1hi[HDIM * DDIM];
__device__ __align__(16) bf16 g_w1lo[HDIM * DDIM];
__device__ __align__(16) bf16 g_w2hi[HDIM * HDIM * 3];
__device__ __align__(16) bf16 g_w2lo[HDIM * HDIM * 3];
__device__ __align__(16) bf16 g_w3hi[EDIM * HDIM];
__device__ __align__(16) bf16 g_w3lo[EDIM * HDIM];
__device__ __align__(16) bf16 g_bhi[VOCAB * EDIM];
__device__ __align__(16) bf16 g_blo[VOCAB * EDIM];

__device__ __forceinline__ uint32_t smem_to_u32(const void* smem_ptr) {
    uint32_t addr;
    asm("{ .reg .u64 tmp; cvta.to.shared.u64 tmp, %1; cvt.u32.u64 %0, tmp; }"
        : "=r"(addr) : "l"(smem_ptr));
    return addr;
}

__device__ __forceinline__ void cp_async16(uint32_t saddr, const void* gptr, int src_bytes) {
    asm volatile("cp.async.cg.shared.global [%0], [%1], 16, %2;"
                 :: "r"(saddr), "l"(gptr), "r"(src_bytes));
}

// fp16 two-split: x = h + (m/2048); m kept in normal fp16 range
__device__ __forceinline__ void split2h(float x, half& h, half& m) {
    h = __float2half_rn(x);
    m = __float2half_rn((x - __half2float(h)) * LO_SCALE);
}

// ---------------- embedding lookup with fused fp16 two-split ------------------
__global__ void embed_split2h(const int* __restrict__ x,
                              const float* __restrict__ tok,
                              half* __restrict__ H, half* __restrict__ M)
{
    int idx = blockIdx.x * blockDim.x + threadIdx.x;   // NPOS*32 float4s
    int n = idx >> 5;
    int j = idx & 31;
    int t = x[n];
    float4 v = reinterpret_cast<const float4*>(tok)[t * 32 + j];
    half h0,m0,h1,m1,h2,m2,h3,m3;
    split2h(v.x,h0,m0); split2h(v.y,h1,m1);
    split2h(v.z,h2,m2); split2h(v.w,h3,m3);
    __half2 p;
    p.x=h0; p.y=h1; reinterpret_cast<__half2*>(H)[n*64+j*2+0]=p;
    p.x=h2; p.y=h3; reinterpret_cast<__half2*>(H)[n*64+j*2+1]=p;
    p.x=m0; p.y=m1; reinterpret_cast<__half2*>(M)[n*64+j*2+0]=p;
    p.x=m2; p.y=m3; reinterpret_cast<__half2*>(M)[n*64+j*2+1]=p;
}

// ---------------- weight pack + splits ----------------------------------------
template<int CIN, int KW, int COUT>
__global__ void pack_split(const float* __restrict__ W,
                           bf16* __restrict__ Hi, bf16* __restrict__ Lo)
{
    int idx = blockIdx.x * blockDim.x + threadIdx.x;
    if (idx >= COUT * KW * CIN) return;
    int o   = idx / (KW * CIN);
    int rem = idx - o * (KW * CIN);
    int tap = rem / CIN;
    int ci  = rem - tap * CIN;
    float w = W[(size_t)o * CIN * KW + ci * KW + tap];
    bf16 h = __float2bfloat16(w);
    Hi[idx] = h;
    Lo[idx] = __float2bfloat16(w - __bfloat162float(h));
}

template<int CIN, int KW, int COUT>
__global__ void pack_split2h(const float* __restrict__ W,
                             half* __restrict__ H, half* __restrict__ M)
{
    int idx = blockIdx.x * blockDim.x + threadIdx.x;
    if (idx >= COUT * KW * CIN) return;
    int o   = idx / (KW * CIN);
    int rem = idx - o * (KW * CIN);
    int tap = rem / CIN;
    int ci  = rem - tap * CIN;
    float w = W[(size_t)o * CIN * KW + ci * KW + tap];
    half h, m;
    split2h(w, h, m);
    H[idx] = h; M[idx] = m;
}

// ---------------- encoder head: conv1x1 (256->64) + LayerNorm(D=64) ---------
__global__ void __launch_bounds__(256)
enc_head_ln(const float* __restrict__ X, const float* __restrict__ W,
            const float* __restrict__ Bias,
            const float* __restrict__ G, const float* __restrict__ Bt,
            float* __restrict__ Z)
{
    constexpr int CIN = 256;
    __shared__ float As[32][66];
    __shared__ float Bs[32][66];
    __shared__ float Zs[64][66];

    const int pm0 = blockIdx.x * 64;
    const int tid = threadIdx.x;
    const int tx = tid & 15, ty = tid >> 4;
    const int rr = tid & 31;
    const int mrow = tid >> 5;

    float acc[4][4];
#pragma unroll
    for (int i = 0; i < 4; i++)
#pragma unroll
        for (int j = 0; j < 4; j++) acc[i][j] = 0.f;

    for (int r0 = 0; r0 < CIN; r0 += 32) {
        const int ci = r0 + rr;
#pragma unroll
        for (int i = 0; i < 8; i++) {
            const int m = mrow + i * 8;
            As[rr][m] = X[(size_t)(pm0 + m) * CIN + ci];
        }
#pragma unroll
        for (int i = 0; i < 8; i++) {
            const int n = mrow + i * 8;
            Bs[rr][n] = W[(size_t)n * CIN + ci];
        }
        __syncthreads();
#pragma unroll
        for (int kk = 0; kk < 32; kk++) {
            float a[4], b[4];
#pragma unroll
            for (int i = 0; i < 4; i++) a[i] = As[kk][ty * 4 + i];
#pragma unroll
            for (int j = 0; j < 4; j++) b[j] = Bs[kk][tx * 4 + j];
#pragma unroll
            for (int i = 0; i < 4; i++)
#pragma unroll
                for (int j = 0; j < 4; j++)
                    acc[i][j] = fmaf(a[i], b[j], acc[i][j]);
        }
        __syncthreads();
    }
#pragma unroll
    for (int i = 0; i < 4; i++)
#pragma unroll
        for (int j = 0; j < 4; j++)
            Zs[ty * 4 + i][tx * 4 + j] = acc[i][j] + Bias[tx * 4 + j];
    __syncthreads();

    const int lane = tid & 31, w = tid >> 5;
#pragma unroll
    for (int q = 0; q < 8; q++) {
        const int m = w * 8 + q;
        float v0 = Zs[m][lane];
        float v1 = Zs[m][lane + 32];
        float s = v0 + v1;
#pragma unroll
        for (int off = 16; off > 0; off >>= 1)
            s += __shfl_xor_sync(0xffffffffu, s, off);
        float mu = s * (1.f / 64.f);
        float d0 = v0 - mu, d1 = v1 - mu;
        float sq = __fadd_rn(__fmul_rn(d0, d0), __fmul_rn(d1, d1));
#pragma unroll
        for (int off = 16; off > 0; off >>= 1)
            sq += __shfl_xor_sync(0xffffffffu, sq, off);
        float var = sq * (1.f / 64.f);
        float rs  = rsqrtf(var + LN_EPS);
        const int p = pm0 + m;
        Z[(size_t)p * 64 + lane]      = d0 * rs * G[lane]      + Bt[lane];
        Z[(size_t)p * 64 + lane + 32] = d1 * rs * G[lane + 32] + Bt[lane + 32];
    }
}

// ---------------- codebook norms (no FMA: match sum(c*c)) --------------------
__global__ void cnorm_kernel(const float* __restrict__ CB, float* __restrict__ CN)
{
    int c = blockIdx.x * blockDim.x + threadIdx.x;
    if (c < KCODE) {
        float s = 0.f;
        for (int d = 0; d < DDIM; d++) {
            float v = CB[c * DDIM + d];
            s = __fadd_rn(s, __fmul_rn(v, v));
        }
        CN[c] = s;
    }
}

// ---------------- VQ: argmin over codes + commit-loss partials ---------------
__global__ void __launch_bounds__(256)
vq_kernel(const float* __restrict__ Z, const float* __restrict__ CB,
          const float* __restrict__ CN, int* __restrict__ Codes,
          float* __restrict__ CommitPart)
{
    __shared__ float Zt[64][66];
    __shared__ float Cs[64][66];
    __shared__ float znS[64];
    __shared__ float cvals[64];

    const int pm0 = blockIdx.x * 64;
    const int tid = threadIdx.x;
    const int tx = tid & 15, ty = tid >> 4;

#pragma unroll
    for (int i = 0; i < 16; i++) {
        int idx = tid + i * 256;
        int m = idx >> 6, d = idx & 63;
        Zt[d][m] = Z[(size_t)(pm0 + m) * 64 + d];
    }
    __syncthreads();

    if (tid < 64) {
        const int m = tid;
        float s = 0.f;
        for (int d = 0; d < 64; d++) {
            float v = Zt[d][m];
            s = __fadd_rn(s, __fmul_rn(v, v));
        }
        znS[m] = s;
    }
    __syncthreads();

    float zm[4];
#pragma unroll
    for (int i = 0; i < 4; i++) zm[i] = znS[ty * 4 + i];

    float minv[4]; int mini[4];
#pragma unroll
    for (int i = 0; i < 4; i++) { minv[i] = 3.4e38f; mini[i] = 0; }

    for (int c0 = 0; c0 < KCODE; c0 += 64) {
        __syncthreads();
#pragma unroll
        for (int i = 0; i < 16; i++) {
            int idx = tid + i * 256;
            int c = idx >> 6, d = idx & 63;
            Cs[d][c] = CB[(size_t)(c0 + c) * 64 + d];
        }
        __syncthreads();

        float dot[4][4];
#pragma unroll
        for (int i = 0; i < 4; i++)
#pragma unroll
            for (int j = 0; j < 4; j++) dot[i][j] = 0.f;
#pragma unroll
        for (int kk = 0; kk < 64; kk++) {
            float a[4], b[4];
#pragma unroll
            for (int i = 0; i < 4; i++) a[i] = Zt[kk][ty * 4 + i];
#pragma unroll
            for (int j = 0; j < 4; j++) b[j] = Cs[kk][tx * 4 + j];
#pragma unroll
            for (int i = 0; i < 4; i++)
#pragma unroll
                for (int j = 0; j < 4; j++)
                    dot[i][j] = fmaf(a[i], b[j], dot[i][j]);
        }
#pragma unroll
        for (int j = 0; j < 4; j++) {
            const int c = c0 + tx * 4 + j;
            const float cn = CN[c];
#pragma unroll
            for (int i = 0; i < 4; i++) {
                float t    = __fadd_rn(zm[i], -__fmul_rn(2.f, dot[i][j]));
                float dist = __fadd_rn(t, cn);
                if (dist < minv[i]) { minv[i] = dist; mini[i] = c; }
            }
        }
    }
    __syncthreads();

    float* redv = &Cs[0][0];
    int*   redi = reinterpret_cast<int*>(&Cs[0][0]) + 1024;
#pragma unroll
    for (int i = 0; i < 4; i++) {
        const int m = ty * 4 + i;
        redv[m * 16 + tx] = minv[i];
        redi[m * 16 + tx] = mini[i];
    }
    __syncthreads();
    if (tid < 64) {
        const int m = tid;
        float bv = redv[m * 16];
        int   bi = redi[m * 16];
        for (int t = 1; t < 16; t++) {
            float v = redv[m * 16 + t];
            int  ix = redi[m * 16 + t];
            if (v < bv || (v == bv && ix < bi)) { bv = v; bi = ix; }
        }
        Codes[pm0 + m] = bi;
        cvals[m] = bv;
    }
    __syncthreads();
    if (tid == 0) {
        float s = 0.f;
        for (int m = 0; m < 64; m++) s += cvals[m];
        CommitPart[blockIdx.x] = s;
    }
}

// ---------------- gather z_q with fused bf16 hi/lo split ----------------------
__global__ void gather_zq_split(const int* __restrict__ codes,
                                const float* __restrict__ CB,
                                bf16* __restrict__ Hi, bf16* __restrict__ Lo)
{
    int idx = blockIdx.x * blockDim.x + threadIdx.x;   // NPOS*16 float4s
    int n = idx >> 4;
    int j = idx & 15;
    float4 v = reinterpret_cast<const float4*>(CB)[codes[n] * 16 + j];
    bf16 h0 = __float2bfloat16(v.x), h1 = __float2bfloat16(v.y);
    bf16 h2 = __float2bfloat16(v.z), h3 = __float2bfloat16(v.w);
    __nv_bfloat162 hh0; hh0.x = h0; hh0.y = h1;
    __nv_bfloat162 hh1; hh1.x = h2; hh1.y = h3;
    __nv_bfloat162 ll0; ll0.x = __float2bfloat16(v.x - __bfloat162float(h0));
    ll0.y = __float2bfloat16(v.y - __bfloat162float(h1));
    __nv_bfloat162 ll1; ll1.x = __float2bfloat16(v.z - __bfloat162float(h2));
    ll1.y = __float2bfloat16(v.w - __bfloat162float(h3));
    reinterpret_cast<__nv_bfloat162*>(Hi)[n * 32 + j * 2 + 0] = hh0;
    reinterpret_cast<__nv_bfloat162*>(Hi)[n * 32 + j * 2 + 1] = hh1;
    reinterpret_cast<__nv_bfloat162*>(Lo)[n * 32 + j * 2 + 0] = ll0;
    reinterpret_cast<__nv_bfloat162*>(Lo)[n * 32 + j * 2 + 1] = ll1;
}

// ---------------- mma helpers -------------------------------------------------
__device__ __forceinline__ void ldsm_x4(uint32_t* r, uint32_t addr) {
    asm volatile("ldmatrix.sync.aligned.m8n8.x4.shared.b16 {%0,%1,%2,%3}, [%4];"
                 : "=r"(r[0]), "=r"(r[1]), "=r"(r[2]), "=r"(r[3]) : "r"(addr));
}
__device__ __forceinline__ void mma16816(float* d, const uint32_t* a,
                                         uint32_t b0, uint32_t b1) {
    asm volatile(
        "mma.sync.aligned.m16n8k16.row.col.f32.bf16.bf16.f32 "
        "{%0,%1,%2,%3}, {%4,%5,%6,%7}, {%8,%9}, {%0,%1,%2,%3};"
        : "+f"(d[0]), "+f"(d[1]), "+f"(d[2]), "+f"(d[3])
        : "r"(a[0]), "r"(a[1]), "r"(a[2]), "r"(a[3]), "r"(b0), "r"(b1));
}
__device__ __forceinline__ void mma16816h(float* d, const uint32_t* a,
                                          uint32_t b0, uint32_t b1) {
    asm volatile(
        "mma.sync.aligned.m16n8k16.row.col.f32.f16.f16.f32 "
        "{%0,%1,%2,%3}, {%4,%5,%6,%7}, {%8,%9}, {%0,%1,%2,%3};"
        : "+f"(d[0]), "+f"(d[1]), "+f"(d[2]), "+f"(d[3])
        : "r"(a[0]), "r"(a[1]), "r"(a[2]), "r"(a[3]), "r"(b0), "r"(b1));
}

// ---------------- generic bf16x3 (hi/lo) tensor conv, 16-warp version --------
// 512 threads, warp grid 4x4, warp tile 32x32. 3-buffer K64 pipeline,
// fused-term inner loop. LNF: fused LayerNorm(COUT=128)+split epilogue.
#define TC_SMEM 196608

template<int CIN, int KW, int COUT, bool RELU, bool WF32, bool WSPLIT, bool LNF>
__global__ void __launch_bounds__(512)
tconv(const bf16* __restrict__ Ahi, const bf16* __restrict__ Alo,
      const bf16* __restrict__ Whi, const bf16* __restrict__ Wlo,
      const float* __restrict__ Bias,
      const float* __restrict__ LG, const float* __restrict__ LB,
      float* __restrict__ Yf, bf16* __restrict__ Yhi, bf16* __restrict__ Ylo)
{
    constexpr int KTOT = CIN * KW;
    constexpr int NCH  = KTOT / 64;
    constexpr int PAD  = (KW == 3) ? 1 : 0;

    extern __shared__ char smem[];
    const int tid = threadIdx.x;
    const int pm0 = blockIdx.x * 128;
    const int nv0 = blockIdx.y * 128;

    const int wid = tid >> 5, lane = tid & 31;
    const int wm = (wid >> 2) * 32;
    const int wn = (wid & 3) * 32;
    const int lr = lane & 7, lq = lane >> 3;

    float acc[2][4][4];
#pragma unroll
    for (int mi = 0; mi < 2; mi++)
#pragma unroll
        for (int ni = 0; ni < 4; ni++)
#pragma unroll
            for (int e = 0; e < 4; e++) acc[mi][ni][e] = 0.f;

    const uint4* A4h = reinterpret_cast<const uint4*>(Ahi);
    const uint4* A4l = reinterpret_cast<const uint4*>(Alo);
    const uint4* B4h = reinterpret_cast<const uint4*>(Whi);
    const uint4* B4l = reinterpret_cast<const uint4*>(Wlo);

    const uint32_t sb = smem_to_u32(smem);

    auto load_chunk = [&](int ch, int buf) {
        const uint32_t bo = (uint32_t)buf * 65536u;
        const int tap = (ch * 64) / CIN;
        const int ci0 = (ch * 64) % CIN;
#pragma unroll
        for (int i = 0; i < 2; i++) {
            int idx = tid + i * 512;
            int row = idx >> 3, c = idx & 7;
            int p = pm0 + row;
            bool ok = true;
            if (KW == 3) {
                int ls = (p & (LSEQ - 1)) + tap - PAD;
                ok = ((unsigned)ls < (unsigned)LSEQ);
            }
            size_t gi = ok ? ((size_t)(p + tap - PAD) * (CIN / 8) + (ci0 / 8) + c) : 0;
            int nb = ok ? 16 : 0;
            int pc = (c ^ row) & 7;
            uint32_t so = (uint32_t)(row * 128 + pc * 16);
            cp_async16(sb + bo + so,          A4h + gi, nb);
            cp_async16(sb + bo + 16384u + so, A4l + gi, nb);
        }
#pragma unroll
        for (int i = 0; i < 2; i++) {
            int idx = tid + i * 512;
            int row = idx >> 3, c = idx & 7;
            size_t gi = (size_t)(nv0 + row) * (KTOT / 8) + ch * 8 + c;
            int pc = (c ^ row) & 7;
            uint32_t so = (uint32_t)(row * 128 + pc * 16);
            cp_async16(sb + bo + 32768u + so, B4h + gi, 16);
            cp_async16(sb + bo + 49152u + so, B4l + gi, 16);
        }
        asm volatile("cp.async.commit_group;");
    };

    load_chunk(0, 0);
    if (1 < NCH) load_chunk(1, 1);

    for (int ch = 0; ch < NCH; ch++) {
        if (ch + 1 < NCH)
            asm volatile("cp.async.wait_group 1;");
        else
            asm volatile("cp.async.wait_group 0;");
        __syncthreads();
        if (ch + 2 < NCH) load_chunk(ch + 2, (ch + 2) % 3);

        const uint32_t bo = (uint32_t)(ch % 3) * 65536u;
        const uint32_t aHB = sb + bo;
        const uint32_t aLB = sb + bo + 16384u;
        const uint32_t bHB = sb + bo + 32768u;
        const uint32_t bLB = sb + bo + 49152u;
#pragma unroll
        for (int k16 = 0; k16 < 4; k16++) {
            const int kc0 = k16 * 2;
            uint32_t ah[2][4], al[2][4];
#pragma unroll
            for (int mi = 0; mi < 2; mi++) {
                int row = wm + mi * 16 + lr + (lq & 1) * 8;
                int kc  = kc0 + (lq >> 1);
                int pc  = (kc ^ row) & 7;
                ldsm_x4(ah[mi], aHB + row * 128 + pc * 16);
                ldsm_x4(al[mi], aLB + row * 128 + pc * 16);
            }
#pragma unroll
            for (int nc = 0; nc < 2; nc++) {
                uint32_t bh[4], bl[4];
                int row = wn + nc * 16 + lr + (lq >> 1) * 8;
                int kc  = kc0 + (lq & 1);
                int pc  = (kc ^ row) & 7;
                ldsm_x4(bh, bHB + row * 128 + pc * 16);
                ldsm_x4(bl, bLB + row * 128 + pc * 16);
                // hh
                mma16816(acc[0][nc * 2 + 0], ah[0], bh[0], bh[1]);
                mma16816(acc[0][nc * 2 + 1], ah[0], bh[2], bh[3]);
                mma16816(acc[1][nc * 2 + 0], ah[1], bh[0], bh[1]);
                mma16816(acc[1][nc * 2 + 1], ah[1], bh[2], bh[3]);
                // h * lo
                mma16816(acc[0][nc * 2 + 0], ah[0], bl[0], bl[1]);
                mma16816(acc[0][nc * 2 + 1], ah[0], bl[2], bl[3]);
                mma16816(acc[1][nc * 2 + 0], ah[1], bl[0], bl[1]);
                mma16816(acc[1][nc * 2 + 1], ah[1], bl[2], bl[3]);
                // lo * h
                mma16816(acc[0][nc * 2 + 0], al[0], bh[0], bh[1]);
                mma16816(acc[0][nc * 2 + 1], al[0], bh[2], bh[3]);
                mma16816(acc[1][nc * 2 + 0], al[1], bh[0], bh[1]);
                mma16816(acc[1][nc * 2 + 1], al[1], bh[2], bh[3]);
            }
        }
    }

    const int gid = lane >> 2, tig = lane & 3;
    // bias (+relu) into acc in place
#pragma unroll
    for (int mi = 0; mi < 2; mi++)
#pragma unroll
        for (int ni = 0; ni < 4; ni++) {
            const int n = nv0 + wn + ni * 8 + tig * 2;
            const float2 bv = *reinterpret_cast<const float2*>(Bias + n);
            acc[mi][ni][0] += bv.x;  acc[mi][ni][1] += bv.y;
            acc[mi][ni][2] += bv.x;  acc[mi][ni][3] += bv.y;
            if (RELU) {
#pragma unroll
                for (int e = 0; e < 4; e++) acc[mi][ni][e] = fmaxf(acc[mi][ni][e], 0.f);
            }
        }

    if (LNF) {
        // fused LayerNorm over COUT=128 + bf16 split store; 4 col-groups/row
        float* red = reinterpret_cast<float*>(smem);
        __syncthreads();
        float ps[2][2];
#pragma unroll
        for (int mi = 0; mi < 2; mi++) { ps[mi][0] = 0.f; ps[mi][1] = 0.f; }
#pragma unroll
        for (int mi = 0; mi < 2; mi++)
#pragma unroll
            for (int ni = 0; ni < 4; ni++) {
                ps[mi][0] += acc[mi][ni][0] + acc[mi][ni][1];
                ps[mi][1] += acc[mi][ni][2] + acc[mi][ni][3];
            }
#pragma unroll
        for (int mi = 0; mi < 2; mi++)
#pragma unroll
            for (int h = 0; h < 2; h++) {
                ps[mi][h] += __shfl_xor_sync(0xffffffffu, ps[mi][h], 1);
                ps[mi][h] += __shfl_xor_sync(0xffffffffu, ps[mi][h], 2);
            }
        if (tig == 0) {
#pragma unroll
            for (int mi = 0; mi < 2; mi++)
#pragma unroll
                for (int h = 0; h < 2; h++) {
                    int row = wm + mi * 16 + gid + h * 8;
                    red[row * 4 + (wn >> 5)] = ps[mi][h];
                }
        }
        __syncthreads();
        float mu[2][2];
#pragma unroll
        for (int mi = 0; mi < 2; mi++)
#pragma unroll
            for (int h = 0; h < 2; h++) {
                int row = wm + mi * 16 + gid + h * 8;
                mu[mi][h] = (red[row * 4] + red[row * 4 + 1] +
                             red[row * 4 + 2] + red[row * 4 + 3]) * (1.f / 128.f);
            }
        float q[2][2];
#pragma unroll
        for (int mi = 0; mi < 2; mi++) { q[mi][0] = 0.f; q[mi][1] = 0.f; }
#pragma unroll
        for (int mi = 0; mi < 2; mi++)
#pragma unroll
            for (int ni = 0; ni < 4; ni++) {
                float d0 = acc[mi][ni][0] - mu[mi][0];
                float d1 = acc[mi][ni][1] - mu[mi][0];
                float d2 = acc[mi][ni][2] - mu[mi][1];
                float d3 = acc[mi][ni][3] - mu[mi][1];
                q[mi][0] += d0 * d0 + d1 * d1;
                q[mi][1] += d2 * d2 + d3 * d3;
            }
#pragma unroll
        for (int mi = 0; mi < 2; mi++)
#pragma unroll
            for (int h = 0; h < 2; h++) {
                q[mi][h] += __shfl_xor_sync(0xffffffffu, q[mi][h], 1);
                q[mi][h] += __shfl_xor_sync(0xffffffffu, q[mi][h], 2);
            }
        if (tig == 0) {
#pragma unroll
            for (int mi = 0; mi < 2; mi++)
#pragma unroll
                for (int h = 0; h < 2; h++) {
                    int row = wm + mi * 16 + gid + h * 8;
                    red[512 + row * 4 + (wn >> 5)] = q[mi][h];
                }
        }
        __syncthreads();
        float rs[2][2];
#pragma unroll
        for (int mi = 0; mi < 2; mi++)
#pragma unroll
            for (int h = 0; h < 2; h++) {
                int row = wm + mi * 16 + gid + h * 8;
                float var = (red[512 + row * 4] + red[512 + row * 4 + 1] +
                             red[512 + row * 4 + 2] + red[512 + row * 4 + 3]) * (1.f / 128.f);
                rs[mi][h] = rsqrtf(var + LN_EPS);
            }
#pragma unroll
        for (int mi = 0; mi < 2; mi++) {
            const int m0 = pm0 + wm + mi * 16 + gid;
#pragma unroll
            for (int ni = 0; ni < 4; ni++) {
                const int c = wn + ni * 8 + tig * 2;
                const float2 gv = *reinterpret_cast<const float2*>(LG + c);
                const float2 bb = *reinterpret_cast<const float2*>(LB + c);
                float y0 = (acc[mi][ni][0] - mu[mi][0]) * rs[mi][0] * gv.x + bb.x;
                float y1 = (acc[mi][ni][1] - mu[mi][0]) * rs[mi][0] * gv.y + bb.y;
                float y2 = (acc[mi][ni][2] - mu[mi][1]) * rs[mi][1] * gv.x + bb.x;
                float y3 = (acc[mi][ni][3] - mu[mi][1]) * rs[mi][1] * gv.y + bb.y;
                bf16 h0 = __float2bfloat16(y0), h1 = __float2bfloat16(y1);
                bf16 h2 = __float2bfloat16(y2), h3 = __float2bfloat16(y3);
                __nv_bfloat162 p0; p0.x = h0; p0.y = h1;
                __nv_bfloat162 p1; p1.x = h2; p1.y = h3;
                *reinterpret_cast<__nv_bfloat162*>(Yhi + (size_t)m0 * COUT + c)       = p0;
                *reinterpret_cast<__nv_bfloat162*>(Yhi + (size_t)(m0 + 8) * COUT + c) = p1;
                p0.x = __float2bfloat16(y0 - __bfloat162float(h0));
                p0.y = __float2bfloat16(y1 - __bfloat162float(h1));
                p1.x = __float2bfloat16(y2 - __bfloat162float(h2));
                p1.y = __float2bfloat16(y3 - __bfloat162float(h3));
                *reinterpret_cast<__nv_bfloat162*>(Ylo + (size_t)m0 * COUT + c)       = p0;
                *reinterpret_cast<__nv_bfloat162*>(Ylo + (size_t)(m0 + 8) * COUT + c) = p1;
            }
        }
        return;
    }

#pragma unroll
    for (int mi = 0; mi < 2; mi++) {
        const int m0 = pm0 + wm + mi * 16 + gid;
#pragma unroll
        for (int ni = 0; ni < 4; ni++) {
            const int n = nv0 + wn + ni * 8 + tig * 2;
            float v00 = acc[mi][ni][0];
            float v01 = acc[mi][ni][1];
            float v10 = acc[mi][ni][2];
            float v11 = acc[mi][ni][3];
            if (WF32) {
                float2 a0; a0.x = v00; a0.y = v01;
                float2 a1; a1.x = v10; a1.y = v11;
                *reinterpret_cast<float2*>(Yf + (size_t)m0 * COUT + n)       = a0;
                *reinterpret_cast<float2*>(Yf + (size_t)(m0 + 8) * COUT + n) = a1;
            }
            if (WSPLIT) {
                bf16 h00 = __float2bfloat16(v00), h01 = __float2bfloat16(v01);
                bf16 h10 = __float2bfloat16(v10), h11 = __float2bfloat16(v11);
                __nv_bfloat162 hh0; hh0.x = h00; hh0.y = h01;
                __nv_bfloat162 hh1; hh1.x = h10; hh1.y = h11;
                __nv_bfloat162 ll0;
                ll0.x = __float2bfloat16(v00 - __bfloat162float(h00));
                ll0.y = __float2bfloat16(v01 - __bfloat162float(h01));
                __nv_bfloat162 ll1;
                ll1.x = __float2bfloat16(v10 - __bfloat162float(h10));
                ll1.y = __float2bfloat16(v11 - __bfloat162float(h11));
                *reinterpret_cast<__nv_bfloat162*>(Yhi + (size_t)m0 * COUT + n)       = hh0;
                *reinterpret_cast<__nv_bfloat162*>(Yhi + (size_t)(m0 + 8) * COUT + n) = hh1;
                *reinterpret_cast<__nv_bfloat162*>(Ylo + (size_t)m0 * COUT + n)       = ll0;
                *reinterpret_cast<__nv_bfloat162*>(Ylo + (size_t)(m0 + 8) * COUT + n) = ll1;
            }
        }
    }
}

// ---------------- fp16 two-split tensor conv (encoder), 16-warp version ------
template<int CIN, int KW, int COUT, bool WF32>
__global__ void __launch_bounds__(512)
tconvh(const half* __restrict__ Ah, const half* __restrict__ Am,
       const half* __restrict__ Wh, const half* __restrict__ Wm,
       const float* __restrict__ Bias, float* __restrict__ Yf,
       half* __restrict__ Yh, half* __restrict__ Ym)
{
    constexpr int KTOT = CIN * KW;
    constexpr int NCH  = KTOT / 64;
    constexpr int PAD  = (KW == 3) ? 1 : 0;

    extern __shared__ char smem[];
    const int tid = threadIdx.x;
    const int pm0 = blockIdx.x * 128;
    const int nv0 = blockIdx.y * 128;

    const int wid = tid >> 5, lane = tid & 31;
    const int wm = (wid >> 2) * 32;
    const int wn = (wid & 3) * 32;
    const int lr = lane & 7, lq = lane >> 3;

    float acc1[2][4][4];
    float acc2[2][4][4];
#pragma unroll
    for (int mi = 0; mi < 2; mi++)
#pragma unroll
        for (int ni = 0; ni < 4; ni++)
#pragma unroll
            for (int e = 0; e < 4; e++) { acc1[mi][ni][e] = 0.f; acc2[mi][ni][e] = 0.f; }

    const uint4* A4h = reinterpret_cast<const uint4*>(Ah);
    const uint4* A4m = reinterpret_cast<const uint4*>(Am);
    const uint4* B4h = reinterpret_cast<const uint4*>(Wh);
    const uint4* B4m = reinterpret_cast<const uint4*>(Wm);

    const uint32_t sb = smem_to_u32(smem);

    auto load_chunk = [&](int ch, int buf) {
        const uint32_t bo = (uint32_t)buf * 65536u;
        const int tap = (ch * 64) / CIN;
        const int ci0 = (ch * 64) % CIN;
#pragma unroll
        for (int i = 0; i < 2; i++) {
            int idx = tid + i * 512;
            int row = idx >> 3, c = idx & 7;
            int p = pm0 + row;
            bool ok = true;
            if (KW == 3) {
                int ls = (p & (LSEQ - 1)) + tap - PAD;
                ok = ((unsigned)ls < (unsigned)LSEQ);
            }
            size_t gi = ok ? ((size_t)(p + tap - PAD) * (CIN / 8) + (ci0 / 8) + c) : 0;
            int nb = ok ? 16 : 0;
            int pc = (c ^ row) & 7;
            uint32_t so = (uint32_t)(row * 128 + pc * 16);
            cp_async16(sb + bo + so,          A4h + gi, nb);
            cp_async16(sb + bo + 16384u + so, A4m + gi, nb);
        }
#pragma unroll
        for (int i = 0; i < 2; i++) {
            int idx = tid + i * 512;
            int row = idx >> 3, c = idx & 7;
            size_t gi = (size_t)(nv0 + row) * (KTOT / 8) + ch * 8 + c;
            int pc = (c ^ row) & 7;
            uint32_t so = (uint32_t)(row * 128 + pc * 16);
            cp_async16(sb + bo + 32768u + so, B4h + gi, 16);
            cp_async16(sb + bo + 49152u + so, B4m + gi, 16);
        }
        asm volatile("cp.async.commit_group;");
    };

    load_chunk(0, 0);
    if (1 < NCH) load_chunk(1, 1);

    for (int ch = 0; ch < NCH; ch++) {
        if (ch + 1 < NCH)
            asm volatile("cp.async.wait_group 1;");
        else
            asm volatile("cp.async.wait_group 0;");
        __syncthreads();
        if (ch + 2 < NCH) load_chunk(ch + 2, (ch + 2) % 3);

        const uint32_t bo = (uint32_t)(ch % 3) * 65536u;
        const uint32_t aHB = sb + bo;
        const uint32_t aMB = sb + bo + 16384u;
        const uint32_t bHB = sb + bo + 32768u;
        const uint32_t bMB = sb + bo + 49152u;
#pragma unroll
        for (int k16 = 0; k16 < 4; k16++) {
            const int kc0 = k16 * 2;
            uint32_t ah[2][4], am[2][4];
#pragma unroll
            for (int mi = 0; mi < 2; mi++) {
                int row = wm + mi * 16 + lr + (lq & 1) * 8;
                int kc  = kc0 + (lq >> 1);
                int pc  = (kc ^ row) & 7;
                ldsm_x4(ah[mi], aHB + row * 128 + pc * 16);
                ldsm_x4(am[mi], aMB + row * 128 + pc * 16);
            }
#pragma unroll
            for (int nc = 0; nc < 2; nc++) {
                uint32_t bh[4], bm[4];
                int row = wn + nc * 16 + lr + (lq >> 1) * 8;
                int kc  = kc0 + (lq & 1);
                int pc  = (kc ^ row) & 7;
                ldsm_x4(bh, bHB + row * 128 + pc * 16);
                ldsm_x4(bm, bMB + row * 128 + pc * 16);
                // hh -> acc1
                mma16816h(acc1[0][nc * 2 + 0], ah[0], bh[0], bh[1]);
                mma16816h(acc1[0][nc * 2 + 1], ah[0], bh[2], bh[3]);
                mma16816h(acc1[1][nc * 2 + 0], ah[1], bh[0], bh[1]);
                mma16816h(acc1[1][nc * 2 + 1], ah[1], bh[2], bh[3]);
                // h*m -> acc2
                mma16816h(acc2[0][nc * 2 + 0], ah[0], bm[0], bm[1]);
                mma16816h(acc2[0][nc * 2 + 1], ah[0], bm[2], bm[3]);
                mma16816h(acc2[1][nc * 2 + 0], ah[1], bm[0], bm[1]);
                mma16816h(acc2[1][nc * 2 + 1], ah[1], bm[2], bm[3]);
                // m*h -> acc2
                mma16816h(acc2[0][nc * 2 + 0], am[0], bh[0], bh[1]);
                mma16816h(acc2[0][nc * 2 + 1], am[0], bh[2], bh[3]);
                mma16816h(acc2[1][nc * 2 + 0], am[1], bh[0], bh[1]);
                mma16816h(acc2[1][nc * 2 + 1], am[1], bh[2], bh[3]);
            }
        }
    }

    const int gid = lane >> 2, tig = lane & 3;
#pragma unroll
    for (int mi = 0; mi < 2; mi++) {
        const int m0 = pm0 + wm + mi * 16 + gid;
#pragma unroll
        for (int ni = 0; ni < 4; ni++) {
            const int n = nv0 + wn + ni * 8 + tig * 2;
            const float2 bv = *reinterpret_cast<const float2*>(Bias + n);
            float v00 = fmaxf(fmaf(acc2[mi][ni][0], LO_INV, acc1[mi][ni][0]) + bv.x, 0.f);
            float v01 = fmaxf(fmaf(acc2[mi][ni][1], LO_INV, acc1[mi][ni][1]) + bv.y, 0.f);
            float v10 = fmaxf(fmaf(acc2[mi][ni][2], LO_INV, acc1[mi][ni][2]) + bv.x, 0.f);
            float v11 = fmaxf(fmaf(acc2[mi][ni][3], LO_INV, acc1[mi][ni][3]) + bv.y, 0.f);
            if (WF32) {
                float2 a0; a0.x = v00; a0.y = v01;
                float2 a1; a1.x = v10; a1.y = v11;
                *reinterpret_cast<float2*>(Yf + (size_t)m0 * COUT + n)       = a0;
                *reinterpret_cast<float2*>(Yf + (size_t)(m0 + 8) * COUT + n) = a1;
            } else {
                half h00,m00,h01,m01,h10,m10,h11,m11;
                split2h(v00,h00,m00); split2h(v01,h01,m01);
                split2h(v10,h10,m10); split2h(v11,h11,m11);
                __half2 p0, p1;
                p0.x=h00; p0.y=h01; p1.x=h10; p1.y=h11;
                *reinterpret_cast<__half2*>(Yh + (size_t)m0 * COUT + n)       = p0;
                *reinterpret_cast<__half2*>(Yh + (size_t)(m0 + 8) * COUT + n) = p1;
                p0.x=m00; p0.y=m01; p1.x=m10; p1.y=m11;
                *reinterpret_cast<__half2*>(Ym + (size_t)m0 * COUT + n)       = p0;
                *reinterpret_cast<__half2*>(Ym + (size_t)(m0 + 8) * COUT + n) = p1;
            }
        }
    }
}

// ---------------- wide full-K-resident bf16x3 logits GEMM, fused-term --------
#define LGW_SMEM 196608

__global__ void __launch_bounds__(256, 1)
logits_wide(const bf16* __restrict__ Ahi, const bf16* __restrict__ Alo,
            const bf16* __restrict__ Bhi, const bf16* __restrict__ Blo,
            const float* __restrict__ Bias, float* __restrict__ Out)
{
    extern __shared__ char smem[];
    const int tid = threadIdx.x;
    const int pm0 = blockIdx.x * 128;
    const int nv0 = blockIdx.y * 256;

    const uint32_t sb = smem_to_u32(smem);

    {
        const uint4* A4h = reinterpret_cast<const uint4*>(Ahi);
        const uint4* A4l = reinterpret_cast<const uint4*>(Alo);
#pragma unroll
        for (int i = 0; i < 8; i++) {
            int idx = tid + i * 256;
            int row = idx >> 4, c = idx & 15;
            int pc = (c & 8) | ((c ^ row) & 7);
            cp_async16(sb + (uint32_t)(row * 256 + pc * 16),
                       A4h + (size_t)(pm0 + row) * 16 + c, 16);
            cp_async16(sb + 32768u + (uint32_t)(row * 256 + pc * 16),
                       A4l + (size_t)(pm0 + row) * 16 + c, 16);
        }
        const uint4* B4h = reinterpret_cast<const uint4*>(Bhi);
        const uint4* B4l = reinterpret_cast<const uint4*>(Blo);
#pragma unroll
        for (int i = 0; i < 16; i++) {
            int idx = tid + i * 256;
            int row = idx >> 4, c = idx & 15;
            int pc = (c & 8) | ((c ^ row) & 7);
            cp_async16(sb + 65536u + (uint32_t)(row * 256 + pc * 16),
                       B4h + (size_t)(nv0 + row) * 16 + c, 16);
            cp_async16(sb + 131072u + (uint32_t)(row * 256 + pc * 16),
                       B4l + (size_t)(nv0 + row) * 16 + c, 16);
        }
        asm volatile("cp.async.commit_group;");
    }

    const int wid = tid >> 5, lane = tid & 31;
    const int wm = (wid >> 1) * 32;       // 0,32,64,96
    const int wn = (wid & 1) * 128;       // 0,128
    const int lr = lane & 7, lq = lane >> 3;

    float acc[2][16][4];
#pragma unroll
    for (int mi = 0; mi < 2; mi++)
#pragma unroll
        for (int ni = 0; ni < 16; ni++)
#pragma unroll
            for (int e = 0; e < 4; e++) acc[mi][ni][e] = 0.f;

    asm volatile("cp.async.wait_group 0;");
    __syncthreads();

#pragma unroll
    for (int k16 = 0; k16 < 8; k16++) {
        const int kc0 = k16 * 2;
        uint32_t ah[2][4], al[2][4];
#pragma unroll
        for (int mi = 0; mi < 2; mi++) {
            int row = wm + mi * 16 + lr + (lq & 1) * 8;
            int kc  = kc0 + (lq >> 1);
            int pc  = (kc & 8) | ((kc ^ row) & 7);
            ldsm_x4(ah[mi], sb + row * 256 + pc * 16);
            ldsm_x4(al[mi], sb + 32768u + row * 256 + pc * 16);
        }
#pragma unroll
        for (int nc = 0; nc < 8; nc++) {
            uint32_t bh[4], bl[4];
            int row = wn + nc * 16 + lr + (lq >> 1) * 8;
            int kc  = kc0 + (lq & 1);
            int pc  = (kc & 8) | ((kc ^ row) & 7);
            ldsm_x4(bh, sb + 65536u + row * 256 + pc * 16);
            ldsm_x4(bl, sb + 131072u + row * 256 + pc * 16);
            // hh
            mma16816(acc[0][nc * 2 + 0], ah[0], bh[0], bh[1]);
            mma16816(acc[0][nc * 2 + 1], ah[0], bh[2], bh[3]);
            mma16816(acc[1][nc * 2 + 0], ah[1], bh[0], bh[1]);
            mma16816(acc[1][nc * 2 + 1], ah[1], bh[2], bh[3]);
            // h * lo
            mma16816(acc[0][nc * 2 + 0], ah[0], bl[0], bl[1]);
            mma16816(acc[0][nc * 2 + 1], ah[0], bl[2], bl[3]);
            mma16816(acc[1][nc * 2 + 0], ah[1], bl[0], bl[1]);
            mma16816(acc[1][nc * 2 + 1], ah[1], bl[2], bl[3]);
            // lo * h
            mma16816(acc[0][nc * 2 + 0], al[0], bh[0], bh[1]);
            mma16816(acc[0][nc * 2 + 1], al[0], bh[2], bh[3]);
            mma16816(acc[1][nc * 2 + 0], al[1], bh[0], bh[1]);
            mma16816(acc[1][nc * 2 + 1], al[1], bh[2], bh[3]);
        }
    }

    const int gid = lane >> 2, tig = lane & 3;
#pragma unroll
    for (int mi = 0; mi < 2; mi++) {
        const int m0 = pm0 + wm + mi * 16 + gid;
#pragma unroll
        for (int ni = 0; ni < 16; ni++) {
            const int n = nv0 + wn + ni * 8 + tig * 2;
            const float2 bv = *reinterpret_cast<const float2*>(Bias + n);
            float2 v0, v1;
            v0.x = acc[mi][ni][0] + bv.x;  v0.y = acc[mi][ni][1] + bv.y;
            v1.x = acc[mi][ni][2] + bv.x;  v1.y = acc[mi][ni][3] + bv.y;
            *reinterpret_cast<float2*>(Out + (size_t)m0 * VOCAB + n)       = v0;
            *reinterpret_cast<float2*>(Out + (size_t)(m0 + 8) * VOCAB + n) = v1;
        }
    }
}

// ---------------- tail: loss scalar + codes ----------------------------------
__global__ void commit_final(const float* __restrict__ Part, float* __restrict__ slot)
{
    if (threadIdx.x == 0 && blockIdx.x == 0) {
        float s = 0.f;
        for (int i = 0; i < NPOS / 64; i++) s += Part[i];
        *slot = 0.1f * s / ((float)NPOS * (float)DDIM);
    }
}

__global__ void write_codes(const int* __restrict__ codes, float* __restrict__ out)
{
    int n = blockIdx.x * blockDim.x + threadIdx.x;
    if (n < NPOS) out[n] = (float)codes[n];
}

// ---------------- launch ------------------------------------------------------
extern "C" void kernel_launch(void* const* d_in, const int* in_sizes, int n_in,
                              void* d_out, int out_size)
{
    (void)in_sizes; (void)n_in;
    const int*   x    = (const int*)  d_in[0];
    const float* tok  = (const float*)d_in[1];
    const float* ew1  = (const float*)d_in[2];
    const float* eb1  = (const float*)d_in[3];
    const float* ew2  = (const float*)d_in[4];
    const float* eb2  = (const float*)d_in[5];
    const float* ew3  = (const float*)d_in[6];
    const float* eb3  = (const float*)d_in[7];
    const float* elg  = (const float*)d_in[8];
    const float* elb  = (const float*)d_in[9];
    const float* cb   = (const float*)d_in[10];
    const float* dw1  = (const float*)d_in[11];
    const float* db1  = (const float*)d_in[12];
    const float* dw2  = (const float*)d_in[13];
    const float* db2  = (const float*)d_in[14];
    const float* dw3  = (const float*)d_in[15];
    const float* db3  = (const float*)d_in[16];
    const float* dlg  = (const float*)d_in[17];
    const float* dlb  = (const float*)d_in[18];
    const float* ow   = (const float*)d_in[19];
    const float* ob   = (const float*)d_in[20];
    float* out = (float*)d_out;

    float *h2, *z, *cn, *cp;
    int* codes;
    half *ebh,*ebm,*e1h,*e1m,*w1eh,*w1em,*w2eh,*w2em;
    bf16 *zqhi,*zqlo,*d1hi,*d1lo,*d2hi,*d2lo,*ahi,*alo;
    bf16 *w1hi,*w1lo,*w2hi,*w2lo,*w3hi,*w3lo,*bhi,*blo;
    cudaGetSymbolAddress((void**)&h2,    g_h2);
    cudaGetSymbolAddress((void**)&z,     g_z);
    cudaGetSymbolAddress((void**)&codes, g_codes);
    cudaGetSymbolAddress((void**)&cn,    g_cnorm);
    cudaGetSymbolAddress((void**)&cp,    g_commit);
    cudaGetSymbolAddress((void**)&ebh,   g_ebh);
    cudaGetSymbolAddress((void**)&ebm,   g_ebm);
    cudaGetSymbolAddress((void**)&e1h,   g_e1h);
    cudaGetSymbolAddress((void**)&e1m,   g_e1m);
    cudaGetSymbolAddress((void**)&w1eh,  g_w1eh);
    cudaGetSymbolAddress((void**)&w1em,  g_w1em);
    cudaGetSymbolAddress((void**)&w2eh,  g_w2eh);
    cudaGetSymbolAddress((void**)&w2em,  g_w2em);
    cudaGetSymbolAddress((void**)&zqhi,  g_zqhi);
    cudaGetSymbolAddress((void**)&zqlo,  g_zqlo);
    cudaGetSymbolAddress((void**)&d1hi,  g_d1hi);
    cudaGetSymbolAddress((void**)&d1lo,  g_d1lo);
    cudaGetSymbolAddress((void**)&d2hi,  g_d2hi);
    cudaGetSymbolAddress((void**)&d2lo,  g_d2lo);
    cudaGetSymbolAddress((void**)&ahi,   g_ahi);
    cudaGetSymbolAddress((void**)&alo,   g_alo);
    cudaGetSymbolAddress((void**)&w1hi,  g_w1hi);
    cudaGetSymbolAddress((void**)&w1lo,  g_w1lo);
    cudaGetSymbolAddress((void**)&w2hi,  g_w2hi);
    cudaGetSymbolAddress((void**)&w2lo,  g_w2lo);
    cudaGetSymbolAddress((void**)&w3hi,  g_w3hi);
    cudaGetSymbolAddress((void**)&w3lo,  g_w3lo);
    cudaGetSymbolAddress((void**)&bhi,   g_bhi);
    cudaGetSymbolAddress((void**)&blo,   g_blo);

    cudaFuncSetAttribute((const void*)tconvh<128, 3, 256, false>,
                         cudaFuncAttributeMaxDynamicSharedMemorySize, TC_SMEM);
    cudaFuncSetAttribute((const void*)tconvh<256, 3, 256, true>,
                         cudaFuncAttributeMaxDynamicSharedMemorySize, TC_SMEM);
    cudaFuncSetAttribute((const void*)tconv< 64, 1, 256, true,  false, true,  false>,
                         cudaFuncAttributeMaxDynamicSharedMemorySize, TC_SMEM);
    cudaFuncSetAttribute((const void*)tconv<256, 3, 256, true,  false, true,  false>,
                         cudaFuncAttributeMaxDynamicSharedMemorySize, TC_SMEM);
    cudaFuncSetAttribute((const void*)tconv<256, 1, 128, true,  false, false, true >,
                         cudaFuncAttributeMaxDynamicSharedMemorySize, TC_SMEM);
    cudaFuncSetAttribute((const void*)logits_wide,
                         cudaFuncAttributeMaxDynamicSharedMemorySize, LGW_SMEM);

    // ---- encoder (fp16 two-split tensor cores, 16-warp pipelined) ----
    pack_split2h<128, 3, 256><<<(256*384)  / 256, 256>>>(ew1, w1eh, w1em);
    pack_split2h<256, 3, 256><<<(256*768)  / 256, 256>>>(ew2, w2eh, w2em);
    embed_split2h<<<NPOS * 32 / 256, 256>>>(x, tok, ebh, ebm);
    tconvh<128, 3, 256, false><<<dim3(NPOS/128, 2), 512, TC_SMEM>>>(
        ebh, ebm, w1eh, w1em, eb1, nullptr, e1h, e1m);
    tconvh<256, 3, 256, true ><<<dim3(NPOS/128, 2), 512, TC_SMEM>>>(
        e1h, e1m, w2eh, w2em, eb2, h2, nullptr, nullptr);
    enc_head_ln<<<NPOS / 64, 256>>>(h2, ew3, eb3, elg, elb, z);

    // ---- vector quantization ----
    cnorm_kernel<<<1, 512>>>(cb, cn);
    vq_kernel<<<NPOS / 64, 256>>>(z, cb, cn, codes, cp);
    gather_zq_split<<<NPOS * 16 / 256, 256>>>(codes, cb, zqhi, zqlo);

    // ---- decoder weight packs + decoder (bf16x3, 16-warp pipelined) ----
    pack_split< 64, 1, 256>  <<<(256*64)   / 256, 256>>>(dw1, w1hi, w1lo);
    pack_split<256, 3, 256>  <<<(256*768)  / 256, 256>>>(dw2, w2hi, w2lo);
    pack_split<256, 1, 128>  <<<(128*256)  / 256, 256>>>(dw3, w3hi, w3lo);
    pack_split<128, 1, VOCAB><<<(VOCAB*128)/ 256, 256>>>(ow,  bhi,  blo);

    tconv< 64, 1, 256, true,  false, true,  false><<<dim3(NPOS/128, 2), 512, TC_SMEM>>>(
        zqhi, zqlo, w1hi, w1lo, db1, nullptr, nullptr, nullptr, d1hi, d1lo);
    tconv<256, 3, 256, true,  false, true,  false><<<dim3(NPOS/128, 2), 512, TC_SMEM>>>(
        d1hi, d1lo, w2hi, w2lo, db2, nullptr, nullptr, nullptr, d2hi, d2lo);
    // conv3 + fused LayerNorm + bf16 split (COUT=128 = full feature row)
    tconv<256, 1, 128, true,  false, false, true ><<<dim3(NPOS/128, 1), 512, TC_SMEM>>>(
        d2hi, d2lo, w3hi, w3lo, db3, dlg, dlb, nullptr, ahi, alo);

    // ---- vocab projection (wide full-K bf16x3, fused-term) -> d_out ----
    logits_wide<<<dim3(NPOS/128, VOCAB/256), 256, LGW_SMEM>>>(
        ahi, alo, bhi, blo, ob, out);

    // ---- tail: loss scalar + codes ----
    const long long NV = (long long)NPOS * VOCAB;   // 134217728
    if ((long long)out_size >= NV + 1)
        commit_final<<<1, 32>>>(cp, out + NV);
    if ((long long)out_size >= NV + 1 + NPOS)
        write_codes<<<NPOS / 256, 256>>>(codes, out + NV + 1);
}

// round 14
// speedup vs baseline: 1.0662x; 1.0394x over previous
#include <cuda_runtime.h>
#include <cuda_bf16.h>
#include <cuda_fp16.h>
#include <cstdint>

// Problem constants
#define NPOS   32768          // B*L = 8*4096
#define LSEQ   4096
#define EDIM   128
#define HDIM   256
#define DDIM   64
#define KCODE  512
#define VOCAB  4096
#define LN_EPS 1e-5f

typedef __nv_bfloat16 bf16;

#define LO_SCALE   2048.0f
#define LO_INV     (1.0f / 2048.0f)

// ---------------- scratch (static device globals; no allocation) -------------
__device__ float g_z  [NPOS * DDIM];    // z_e after LN
__device__ int   g_codes[NPOS];
__device__ float g_cnorm[KCODE];
__device__ float g_commit[NPOS / 64];
// encoder fp16 two-split activations (lo scaled by 2048)
__device__ __align__(16) half g_ebh[NPOS * EDIM];
__device__ __align__(16) half g_ebm[NPOS * EDIM];
__device__ __align__(16) half g_e1h[NPOS * HDIM];
__device__ __align__(16) half g_e1m[NPOS * HDIM];
__device__ __align__(16) half g_e2h[NPOS * HDIM];
__device__ __align__(16) half g_e2m[NPOS * HDIM];
// encoder fp16 two-split packed weights
__device__ __align__(16) half g_w1eh[HDIM * EDIM * 3];
__device__ __align__(16) half g_w1em[HDIM * EDIM * 3];
__device__ __align__(16) half g_w2eh[HDIM * HDIM * 3];
__device__ __align__(16) half g_w2em[HDIM * HDIM * 3];
__device__ __align__(16) half g_w3eh[DDIM * HDIM];
__device__ __align__(16) half g_w3em[DDIM * HDIM];
// decoder bf16 hi/lo split activations
__device__ __align__(16) bf16 g_zqhi[NPOS * DDIM];
__device__ __align__(16) bf16 g_zqlo[NPOS * DDIM];
__device__ __align__(16) bf16 g_d1hi[NPOS * HDIM];
__device__ __align__(16) bf16 g_d1lo[NPOS * HDIM];
__device__ __align__(16) bf16 g_d2hi[NPOS * HDIM];
__device__ __align__(16) bf16 g_d2lo[NPOS * HDIM];
__device__ __align__(16) bf16 g_ahi[NPOS * EDIM];
__device__ __align__(16) bf16 g_alo[NPOS * EDIM];
// decoder bf16 hi/lo split packed weights
__device__ __align__(16) bf16 g_w1hi[HDIM * DDIM];
__device__ __align__(16) bf16 g_w1lo[HDIM * DDIM];
__device__ __align__(16) bf16 g_w2hi[HDIM * HDIM * 3];
__device__ __align__(16) bf16 g_w2lo[HDIM * HDIM * 3];
__device__ __align__(16) bf16 g_w3hi[EDIM * HDIM];
__device__ __align__(16) bf16 g_w3lo[EDIM * HDIM];
__device__ __align__(16) bf16 g_bhi[VOCAB * EDIM];
__device__ __align__(16) bf16 g_blo[VOCAB * EDIM];

__device__ __forceinline__ uint32_t smem_to_u32(const void* smem_ptr) {
    uint32_t addr;
    asm("{ .reg .u64 tmp; cvta.to.shared.u64 tmp, %1; cvt.u32.u64 %0, tmp; }"
        : "=r"(addr) : "l"(smem_ptr));
    return addr;
}

__device__ __forceinline__ void cp_async16(uint32_t saddr, const void* gptr, int src_bytes) {
    asm volatile("cp.async.cg.shared.global [%0], [%1], 16, %2;"
                 :: "r"(saddr), "l"(gptr), "r"(src_bytes));
}

// fp16 two-split: x = h + (m/2048); m kept in normal fp16 range
__device__ __forceinline__ void split2h(float x, half& h, half& m) {
    h = __float2half_rn(x);
    m = __float2half_rn((x - __half2float(h)) * LO_SCALE);
}

// ---------------- embedding lookup with fused fp16 two-split ------------------
__global__ void embed_split2h(const int* __restrict__ x,
                              const float* __restrict__ tok,
                              half* __restrict__ H, half* __restrict__ M)
{
    int idx = blockIdx.x * blockDim.x + threadIdx.x;   // NPOS*32 float4s
    int n = idx >> 5;
    int j = idx & 31;
    int t = x[n];
    float4 v = reinterpret_cast<const float4*>(tok)[t * 32 + j];
    half h0,m0,h1,m1,h2,m2,h3,m3;
    split2h(v.x,h0,m0); split2h(v.y,h1,m1);
    split2h(v.z,h2,m2); split2h(v.w,h3,m3);
    __half2 p;
    p.x=h0; p.y=h1; reinterpret_cast<__half2*>(H)[n*64+j*2+0]=p;
    p.x=h2; p.y=h3; reinterpret_cast<__half2*>(H)[n*64+j*2+1]=p;
    p.x=m0; p.y=m1; reinterpret_cast<__half2*>(M)[n*64+j*2+0]=p;
    p.x=m2; p.y=m3; reinterpret_cast<__half2*>(M)[n*64+j*2+1]=p;
}

// ---------------- weight pack + splits ----------------------------------------
template<int CIN, int KW, int COUT>
__global__ void pack_split(const float* __restrict__ W,
                           bf16* __restrict__ Hi, bf16* __restrict__ Lo)
{
    int idx = blockIdx.x * blockDim.x + threadIdx.x;
    if (idx >= COUT * KW * CIN) return;
    int o   = idx / (KW * CIN);
    int rem = idx - o * (KW * CIN);
    int tap = rem / CIN;
    int ci  = rem - tap * CIN;
    float w = W[(size_t)o * CIN * KW + ci * KW + tap];
    bf16 h = __float2bfloat16(w);
    Hi[idx] = h;
    Lo[idx] = __float2bfloat16(w - __bfloat162float(h));
}

template<int CIN, int KW, int COUT>
__global__ void pack_split2h(const float* __restrict__ W,
                             half* __restrict__ H, half* __restrict__ M)
{
    int idx = blockIdx.x * blockDim.x + threadIdx.x;
    if (idx >= COUT * KW * CIN) return;
    int o   = idx / (KW * CIN);
    int rem = idx - o * (KW * CIN);
    int tap = rem / CIN;
    int ci  = rem - tap * CIN;
    float w = W[(size_t)o * CIN * KW + ci * KW + tap];
    half h, m;
    split2h(w, h, m);
    H[idx] = h; M[idx] = m;
}

// ---------------- codebook norms (no FMA: match sum(c*c)) --------------------
__global__ void cnorm_kernel(const float* __restrict__ CB, float* __restrict__ CN)
{
    int c = blockIdx.x * blockDim.x + threadIdx.x;
    if (c < KCODE) {
        float s = 0.f;
        for (int d = 0; d < DDIM; d++) {
            float v = CB[c * DDIM + d];
            s = __fadd_rn(s, __fmul_rn(v, v));
        }
        CN[c] = s;
    }
}

// ---------------- VQ: argmin over codes + commit-loss partials ---------------
__global__ void __launch_bounds__(256)
vq_kernel(const float* __restrict__ Z, const float* __restrict__ CB,
          const float* __restrict__ CN, int* __restrict__ Codes,
          float* __restrict__ CommitPart)
{
    __shared__ float Zt[64][66];
    __shared__ float Cs[64][66];
    __shared__ float znS[64];
    __shared__ float cvals[64];

    const int pm0 = blockIdx.x * 64;
    const int tid = threadIdx.x;
    const int tx = tid & 15, ty = tid >> 4;

#pragma unroll
    for (int i = 0; i < 16; i++) {
        int idx = tid + i * 256;
        int m = idx >> 6, d = idx & 63;
        Zt[d][m] = Z[(size_t)(pm0 + m) * 64 + d];
    }
    __syncthreads();

    if (tid < 64) {
        const int m = tid;
        float s = 0.f;
        for (int d = 0; d < 64; d++) {
            float v = Zt[d][m];
            s = __fadd_rn(s, __fmul_rn(v, v));
        }
        znS[m] = s;
    }
    __syncthreads();

    float zm[4];
#pragma unroll
    for (int i = 0; i < 4; i++) zm[i] = znS[ty * 4 + i];

    float minv[4]; int mini[4];
#pragma unroll
    for (int i = 0; i < 4; i++) { minv[i] = 3.4e38f; mini[i] = 0; }

    for (int c0 = 0; c0 < KCODE; c0 += 64) {
        __syncthreads();
#pragma unroll
        for (int i = 0; i < 16; i++) {
            int idx = tid + i * 256;
            int c = idx >> 6, d = idx & 63;
            Cs[d][c] = CB[(size_t)(c0 + c) * 64 + d];
        }
        __syncthreads();

        float dot[4][4];
#pragma unroll
        for (int i = 0; i < 4; i++)
#pragma unroll
            for (int j = 0; j < 4; j++) dot[i][j] = 0.f;
#pragma unroll
        for (int kk = 0; kk < 64; kk++) {
            float a[4], b[4];
#pragma unroll
            for (int i = 0; i < 4; i++) a[i] = Zt[kk][ty * 4 + i];
#pragma unroll
            for (int j = 0; j < 4; j++) b[j] = Cs[kk][tx * 4 + j];
#pragma unroll
            for (int i = 0; i < 4; i++)
#pragma unroll
                for (int j = 0; j < 4; j++)
                    dot[i][j] = fmaf(a[i], b[j], dot[i][j]);
        }
#pragma unroll
        for (int j = 0; j < 4; j++) {
            const int c = c0 + tx * 4 + j;
            const float cn = CN[c];
#pragma unroll
            for (int i = 0; i < 4; i++) {
                float t    = __fadd_rn(zm[i], -__fmul_rn(2.f, dot[i][j]));
                float dist = __fadd_rn(t, cn);
                if (dist < minv[i]) { minv[i] = dist; mini[i] = c; }
            }
        }
    }
    __syncthreads();

    float* redv = &Cs[0][0];
    int*   redi = reinterpret_cast<int*>(&Cs[0][0]) + 1024;
#pragma unroll
    for (int i = 0; i < 4; i++) {
        const int m = ty * 4 + i;
        redv[m * 16 + tx] = minv[i];
        redi[m * 16 + tx] = mini[i];
    }
    __syncthreads();
    if (tid < 64) {
        const int m = tid;
        float bv = redv[m * 16];
        int   bi = redi[m * 16];
        for (int t = 1; t < 16; t++) {
            float v = redv[m * 16 + t];
            int  ix = redi[m * 16 + t];
            if (v < bv || (v == bv && ix < bi)) { bv = v; bi = ix; }
        }
        Codes[pm0 + m] = bi;
        cvals[m] = bv;
    }
    __syncthreads();
    if (tid == 0) {
        float s = 0.f;
        for (int m = 0; m < 64; m++) s += cvals[m];
        CommitPart[blockIdx.x] = s;
    }
}

// ---------------- gather z_q with fused bf16 hi/lo split ----------------------
__global__ void gather_zq_split(const int* __restrict__ codes,
                                const float* __restrict__ CB,
                                bf16* __restrict__ Hi, bf16* __restrict__ Lo)
{
    int idx = blockIdx.x * blockDim.x + threadIdx.x;   // NPOS*16 float4s
    int n = idx >> 4;
    int j = idx & 15;
    float4 v = reinterpret_cast<const float4*>(CB)[codes[n] * 16 + j];
    bf16 h0 = __float2bfloat16(v.x), h1 = __float2bfloat16(v.y);
    bf16 h2 = __float2bfloat16(v.z), h3 = __float2bfloat16(v.w);
    __nv_bfloat162 hh0; hh0.x = h0; hh0.y = h1;
    __nv_bfloat162 hh1; hh1.x = h2; hh1.y = h3;
    __nv_bfloat162 ll0; ll0.x = __float2bfloat16(v.x - __bfloat162float(h0));
    ll0.y = __float2bfloat16(v.y - __bfloat162float(h1));
    __nv_bfloat162 ll1; ll1.x = __float2bfloat16(v.z - __bfloat162float(h2));
    ll1.y = __float2bfloat16(v.w - __bfloat162float(h3));
    reinterpret_cast<__nv_bfloat162*>(Hi)[n * 32 + j * 2 + 0] = hh0;
    reinterpret_cast<__nv_bfloat162*>(Hi)[n * 32 + j * 2 + 1] = hh1;
    reinterpret_cast<__nv_bfloat162*>(Lo)[n * 32 + j * 2 + 0] = ll0;
    reinterpret_cast<__nv_bfloat162*>(Lo)[n * 32 + j * 2 + 1] = ll1;
}

// ---------------- mma helpers -------------------------------------------------
__device__ __forceinline__ void ldsm_x4(uint32_t* r, uint32_t addr) {
    asm volatile("ldmatrix.sync.aligned.m8n8.x4.shared.b16 {%0,%1,%2,%3}, [%4];"
                 : "=r"(r[0]), "=r"(r[1]), "=r"(r[2]), "=r"(r[3]) : "r"(addr));
}
__device__ __forceinline__ void mma16816(float* d, const uint32_t* a,
                                         uint32_t b0, uint32_t b1) {
    asm volatile(
        "mma.sync.aligned.m16n8k16.row.col.f32.bf16.bf16.f32 "
        "{%0,%1,%2,%3}, {%4,%5,%6,%7}, {%8,%9}, {%0,%1,%2,%3};"
        : "+f"(d[0]), "+f"(d[1]), "+f"(d[2]), "+f"(d[3])
        : "r"(a[0]), "r"(a[1]), "r"(a[2]), "r"(a[3]), "r"(b0), "r"(b1));
}
__device__ __forceinline__ void mma16816h(float* d, const uint32_t* a,
                                          uint32_t b0, uint32_t b1) {
    asm volatile(
        "mma.sync.aligned.m16n8k16.row.col.f32.f16.f16.f32 "
        "{%0,%1,%2,%3}, {%4,%5,%6,%7}, {%8,%9}, {%0,%1,%2,%3};"
        : "+f"(d[0]), "+f"(d[1]), "+f"(d[2]), "+f"(d[3])
        : "r"(a[0]), "r"(a[1]), "r"(a[2]), "r"(a[3]), "r"(b0), "r"(b1));
}

// ---------------- generic bf16x3 (hi/lo) tensor conv, 16-warp version --------
#define TC_SMEM 196608

template<int CIN, int KW, int COUT, bool RELU, bool WF32, bool WSPLIT, bool LNF>
__global__ void __launch_bounds__(512)
tconv(const bf16* __restrict__ Ahi, const bf16* __restrict__ Alo,
      const bf16* __restrict__ Whi, const bf16* __restrict__ Wlo,
      const float* __restrict__ Bias,
      const float* __restrict__ LG, const float* __restrict__ LB,
      float* __restrict__ Yf, bf16* __restrict__ Yhi, bf16* __restrict__ Ylo)
{
    constexpr int KTOT = CIN * KW;
    constexpr int NCH  = KTOT / 64;
    constexpr int PAD  = (KW == 3) ? 1 : 0;

    extern __shared__ char smem[];
    const int tid = threadIdx.x;
    const int pm0 = blockIdx.x * 128;
    const int nv0 = blockIdx.y * 128;

    const int wid = tid >> 5, lane = tid & 31;
    const int wm = (wid >> 2) * 32;
    const int wn = (wid & 3) * 32;
    const int lr = lane & 7, lq = lane >> 3;

    float acc[2][4][4];
#pragma unroll
    for (int mi = 0; mi < 2; mi++)
#pragma unroll
        for (int ni = 0; ni < 4; ni++)
#pragma unroll
            for (int e = 0; e < 4; e++) acc[mi][ni][e] = 0.f;

    const uint4* A4h = reinterpret_cast<const uint4*>(Ahi);
    const uint4* A4l = reinterpret_cast<const uint4*>(Alo);
    const uint4* B4h = reinterpret_cast<const uint4*>(Whi);
    const uint4* B4l = reinterpret_cast<const uint4*>(Wlo);

    const uint32_t sb = smem_to_u32(smem);

    auto load_chunk = [&](int ch, int buf) {
        const uint32_t bo = (uint32_t)buf * 65536u;
        const int tap = (ch * 64) / CIN;
        const int ci0 = (ch * 64) % CIN;
#pragma unroll
        for (int i = 0; i < 2; i++) {
            int idx = tid + i * 512;
            int row = idx >> 3, c = idx & 7;
            int p = pm0 + row;
            bool ok = true;
            if (KW == 3) {
                int ls = (p & (LSEQ - 1)) + tap - PAD;
                ok = ((unsigned)ls < (unsigned)LSEQ);
            }
            size_t gi = ok ? ((size_t)(p + tap - PAD) * (CIN / 8) + (ci0 / 8) + c) : 0;
            int nb = ok ? 16 : 0;
            int pc = (c ^ row) & 7;
            uint32_t so = (uint32_t)(row * 128 + pc * 16);
            cp_async16(sb + bo + so,          A4h + gi, nb);
            cp_async16(sb + bo + 16384u + so, A4l + gi, nb);
        }
#pragma unroll
        for (int i = 0; i < 2; i++) {
            int idx = tid + i * 512;
            int row = idx >> 3, c = idx & 7;
            size_t gi = (size_t)(nv0 + row) * (KTOT / 8) + ch * 8 + c;
            int pc = (c ^ row) & 7;
            uint32_t so = (uint32_t)(row * 128 + pc * 16);
            cp_async16(sb + bo + 32768u + so, B4h + gi, 16);
            cp_async16(sb + bo + 49152u + so, B4l + gi, 16);
        }
        asm volatile("cp.async.commit_group;");
    };

    load_chunk(0, 0);
    if (1 < NCH) load_chunk(1, 1);

    for (int ch = 0; ch < NCH; ch++) {
        if (ch + 1 < NCH)
            asm volatile("cp.async.wait_group 1;");
        else
            asm volatile("cp.async.wait_group 0;");
        __syncthreads();
        if (ch + 2 < NCH) load_chunk(ch + 2, (ch + 2) % 3);

        const uint32_t bo = (uint32_t)(ch % 3) * 65536u;
        const uint32_t aHB = sb + bo;
        const uint32_t aLB = sb + bo + 16384u;
        const uint32_t bHB = sb + bo + 32768u;
        const uint32_t bLB = sb + bo + 49152u;
#pragma unroll
        for (int k16 = 0; k16 < 4; k16++) {
            const int kc0 = k16 * 2;
            uint32_t ah[2][4], al[2][4];
#pragma unroll
            for (int mi = 0; mi < 2; mi++) {
                int row = wm + mi * 16 + lr + (lq & 1) * 8;
                int kc  = kc0 + (lq >> 1);
                int pc  = (kc ^ row) & 7;
                ldsm_x4(ah[mi], aHB + row * 128 + pc * 16);
                ldsm_x4(al[mi], aLB + row * 128 + pc * 16);
            }
#pragma unroll
            for (int nc = 0; nc < 2; nc++) {
                uint32_t bh[4], bl[4];
                int row = wn + nc * 16 + lr + (lq >> 1) * 8;
                int kc  = kc0 + (lq & 1);
                int pc  = (kc ^ row) & 7;
                ldsm_x4(bh, bHB + row * 128 + pc * 16);
                ldsm_x4(bl, bLB + row * 128 + pc * 16);
                mma16816(acc[0][nc * 2 + 0], ah[0], bh[0], bh[1]);
                mma16816(acc[0][nc * 2 + 1], ah[0], bh[2], bh[3]);
                mma16816(acc[1][nc * 2 + 0], ah[1], bh[0], bh[1]);
                mma16816(acc[1][nc * 2 + 1], ah[1], bh[2], bh[3]);
                mma16816(acc[0][nc * 2 + 0], ah[0], bl[0], bl[1]);
                mma16816(acc[0][nc * 2 + 1], ah[0], bl[2], bl[3]);
                mma16816(acc[1][nc * 2 + 0], ah[1], bl[0], bl[1]);
                mma16816(acc[1][nc * 2 + 1], ah[1], bl[2], bl[3]);
                mma16816(acc[0][nc * 2 + 0], al[0], bh[0], bh[1]);
                mma16816(acc[0][nc * 2 + 1], al[0], bh[2], bh[3]);
                mma16816(acc[1][nc * 2 + 0], al[1], bh[0], bh[1]);
                mma16816(acc[1][nc * 2 + 1], al[1], bh[2], bh[3]);
            }
        }
    }

    const int gid = lane >> 2, tig = lane & 3;
#pragma unroll
    for (int mi = 0; mi < 2; mi++)
#pragma unroll
        for (int ni = 0; ni < 4; ni++) {
            const int n = nv0 + wn + ni * 8 + tig * 2;
            const float2 bv = *reinterpret_cast<const float2*>(Bias + n);
            acc[mi][ni][0] += bv.x;  acc[mi][ni][1] += bv.y;
            acc[mi][ni][2] += bv.x;  acc[mi][ni][3] += bv.y;
            if (RELU) {
#pragma unroll
                for (int e = 0; e < 4; e++) acc[mi][ni][e] = fmaxf(acc[mi][ni][e], 0.f);
            }
        }

    if (LNF) {
        float* red = reinterpret_cast<float*>(smem);
        __syncthreads();
        float ps[2][2];
#pragma unroll
        for (int mi = 0; mi < 2; mi++) { ps[mi][0] = 0.f; ps[mi][1] = 0.f; }
#pragma unroll
        for (int mi = 0; mi < 2; mi++)
#pragma unroll
            for (int ni = 0; ni < 4; ni++) {
                ps[mi][0] += acc[mi][ni][0] + acc[mi][ni][1];
                ps[mi][1] += acc[mi][ni][2] + acc[mi][ni][3];
            }
#pragma unroll
        for (int mi = 0; mi < 2; mi++)
#pragma unroll
            for (int h = 0; h < 2; h++) {
                ps[mi][h] += __shfl_xor_sync(0xffffffffu, ps[mi][h], 1);
                ps[mi][h] += __shfl_xor_sync(0xffffffffu, ps[mi][h], 2);
            }
        if (tig == 0) {
#pragma unroll
            for (int mi = 0; mi < 2; mi++)
#pragma unroll
                for (int h = 0; h < 2; h++) {
                    int row = wm + mi * 16 + gid + h * 8;
                    red[row * 4 + (wn >> 5)] = ps[mi][h];
                }
        }
        __syncthreads();
        float mu[2][2];
#pragma unroll
        for (int mi = 0; mi < 2; mi++)
#pragma unroll
            for (int h = 0; h < 2; h++) {
                int row = wm + mi * 16 + gid + h * 8;
                mu[mi][h] = (red[row * 4] + red[row * 4 + 1] +
                             red[row * 4 + 2] + red[row * 4 + 3]) * (1.f / 128.f);
            }
        float q[2][2];
#pragma unroll
        for (int mi = 0; mi < 2; mi++) { q[mi][0] = 0.f; q[mi][1] = 0.f; }
#pragma unroll
        for (int mi = 0; mi < 2; mi++)
#pragma unroll
            for (int ni = 0; ni < 4; ni++) {
                float d0 = acc[mi][ni][0] - mu[mi][0];
                float d1 = acc[mi][ni][1] - mu[mi][0];
                float d2 = acc[mi][ni][2] - mu[mi][1];
                float d3 = acc[mi][ni][3] - mu[mi][1];
                q[mi][0] += d0 * d0 + d1 * d1;
                q[mi][1] += d2 * d2 + d3 * d3;
            }
#pragma unroll
        for (int mi = 0; mi < 2; mi++)
#pragma unroll
            for (int h = 0; h < 2; h++) {
                q[mi][h] += __shfl_xor_sync(0xffffffffu, q[mi][h], 1);
                q[mi][h] += __shfl_xor_sync(0xffffffffu, q[mi][h], 2);
            }
        if (tig == 0) {
#pragma unroll
            for (int mi = 0; mi < 2; mi++)
#pragma unroll
                for (int h = 0; h < 2; h++) {
                    int row = wm + mi * 16 + gid + h * 8;
                    red[512 + row * 4 + (wn >> 5)] = q[mi][h];
                }
        }
        __syncthreads();
        float rs[2][2];
#pragma unroll
        for (int mi = 0; mi < 2; mi++)
#pragma unroll
            for (int h = 0; h < 2; h++) {
                int row = wm + mi * 16 + gid + h * 8;
                float var = (red[512 + row * 4] + red[512 + row * 4 + 1] +
                             red[512 + row * 4 + 2] + red[512 + row * 4 + 3]) * (1.f / 128.f);
                rs[mi][h] = rsqrtf(var + LN_EPS);
            }
#pragma unroll
        for (int mi = 0; mi < 2; mi++) {
            const int m0 = pm0 + wm + mi * 16 + gid;
#pragma unroll
            for (int ni = 0; ni < 4; ni++) {
                const int c = wn + ni * 8 + tig * 2;
                const float2 gv = *reinterpret_cast<const float2*>(LG + c);
                const float2 bb = *reinterpret_cast<const float2*>(LB + c);
                float y0 = (acc[mi][ni][0] - mu[mi][0]) * rs[mi][0] * gv.x + bb.x;
                float y1 = (acc[mi][ni][1] - mu[mi][0]) * rs[mi][0] * gv.y + bb.y;
                float y2 = (acc[mi][ni][2] - mu[mi][1]) * rs[mi][1] * gv.x + bb.x;
                float y3 = (acc[mi][ni][3] - mu[mi][1]) * rs[mi][1] * gv.y + bb.y;
                bf16 h0 = __float2bfloat16(y0), h1 = __float2bfloat16(y1);
                bf16 h2 = __float2bfloat16(y2), h3 = __float2bfloat16(y3);
                __nv_bfloat162 p0; p0.x = h0; p0.y = h1;
                __nv_bfloat162 p1; p1.x = h2; p1.y = h3;
                *reinterpret_cast<__nv_bfloat162*>(Yhi + (size_t)m0 * COUT + c)       = p0;
                *reinterpret_cast<__nv_bfloat162*>(Yhi + (size_t)(m0 + 8) * COUT + c) = p1;
                p0.x = __float2bfloat16(y0 - __bfloat162float(h0));
                p0.y = __float2bfloat16(y1 - __bfloat162float(h1));
                p1.x = __float2bfloat16(y2 - __bfloat162float(h2));
                p1.y = __float2bfloat16(y3 - __bfloat162float(h3));
                *reinterpret_cast<__nv_bfloat162*>(Ylo + (size_t)m0 * COUT + c)       = p0;
                *reinterpret_cast<__nv_bfloat162*>(Ylo + (size_t)(m0 + 8) * COUT + c) = p1;
            }
        }
        return;
    }

#pragma unroll
    for (int mi = 0; mi < 2; mi++) {
        const int m0 = pm0 + wm + mi * 16 + gid;
#pragma unroll
        for (int ni = 0; ni < 4; ni++) {
            const int n = nv0 + wn + ni * 8 + tig * 2;
            float v00 = acc[mi][ni][0];
            float v01 = acc[mi][ni][1];
            float v10 = acc[mi][ni][2];
            float v11 = acc[mi][ni][3];
            if (WF32) {
                float2 a0; a0.x = v00; a0.y = v01;
                float2 a1; a1.x = v10; a1.y = v11;
                *reinterpret_cast<float2*>(Yf + (size_t)m0 * COUT + n)       = a0;
                *reinterpret_cast<float2*>(Yf + (size_t)(m0 + 8) * COUT + n) = a1;
            }
            if (WSPLIT) {
                bf16 h00 = __float2bfloat16(v00), h01 = __float2bfloat16(v01);
                bf16 h10 = __float2bfloat16(v10), h11 = __float2bfloat16(v11);
                __nv_bfloat162 hh0; hh0.x = h00; hh0.y = h01;
                __nv_bfloat162 hh1; hh1.x = h10; hh1.y = h11;
                __nv_bfloat162 ll0;
                ll0.x = __float2bfloat16(v00 - __bfloat162float(h00));
                ll0.y = __float2bfloat16(v01 - __bfloat162float(h01));
                __nv_bfloat162 ll1;
                ll1.x = __float2bfloat16(v10 - __bfloat162float(h10));
                ll1.y = __float2bfloat16(v11 - __bfloat162float(h11));
                *reinterpret_cast<__nv_bfloat162*>(Yhi + (size_t)m0 * COUT + n)       = hh0;
                *reinterpret_cast<__nv_bfloat162*>(Yhi + (size_t)(m0 + 8) * COUT + n) = hh1;
                *reinterpret_cast<__nv_bfloat162*>(Ylo + (size_t)m0 * COUT + n)       = ll0;
                *reinterpret_cast<__nv_bfloat162*>(Ylo + (size_t)(m0 + 8) * COUT + n) = ll1;
            }
        }
    }
}

// ---------------- fp16 two-split tensor conv (encoder), 16-warp version ------
template<int CIN, int KW, int COUT, bool WF32>
__global__ void __launch_bounds__(512)
tconvh(const half* __restrict__ Ah, const half* __restrict__ Am,
       const half* __restrict__ Wh, const half* __restrict__ Wm,
       const float* __restrict__ Bias, float* __restrict__ Yf,
       half* __restrict__ Yh, half* __restrict__ Ym)
{
    constexpr int KTOT = CIN * KW;
    constexpr int NCH  = KTOT / 64;
    constexpr int PAD  = (KW == 3) ? 1 : 0;

    extern __shared__ char smem[];
    const int tid = threadIdx.x;
    const int pm0 = blockIdx.x * 128;
    const int nv0 = blockIdx.y * 128;

    const int wid = tid >> 5, lane = tid & 31;
    const int wm = (wid >> 2) * 32;
    const int wn = (wid & 3) * 32;
    const int lr = lane & 7, lq = lane >> 3;

    float acc1[2][4][4];
    float acc2[2][4][4];
#pragma unroll
    for (int mi = 0; mi < 2; mi++)
#pragma unroll
        for (int ni = 0; ni < 4; ni++)
#pragma unroll
            for (int e = 0; e < 4; e++) { acc1[mi][ni][e] = 0.f; acc2[mi][ni][e] = 0.f; }

    const uint4* A4h = reinterpret_cast<const uint4*>(Ah);
    const uint4* A4m = reinterpret_cast<const uint4*>(Am);
    const uint4* B4h = reinterpret_cast<const uint4*>(Wh);
    const uint4* B4m = reinterpret_cast<const uint4*>(Wm);

    const uint32_t sb = smem_to_u32(smem);

    auto load_chunk = [&](int ch, int buf) {
        const uint32_t bo = (uint32_t)buf * 65536u;
        const int tap = (ch * 64) / CIN;
        const int ci0 = (ch * 64) % CIN;
#pragma unroll
        for (int i = 0; i < 2; i++) {
            int idx = tid + i * 512;
            int row = idx >> 3, c = idx & 7;
            int p = pm0 + row;
            bool ok = true;
            if (KW == 3) {
                int ls = (p & (LSEQ - 1)) + tap - PAD;
                ok = ((unsigned)ls < (unsigned)LSEQ);
            }
            size_t gi = ok ? ((size_t)(p + tap - PAD) * (CIN / 8) + (ci0 / 8) + c) : 0;
            int nb = ok ? 16 : 0;
            int pc = (c ^ row) & 7;
            uint32_t so = (uint32_t)(row * 128 + pc * 16);
            cp_async16(sb + bo + so,          A4h + gi, nb);
            cp_async16(sb + bo + 16384u + so, A4m + gi, nb);
        }
#pragma unroll
        for (int i = 0; i < 2; i++) {
            int idx = tid + i * 512;
            int row = idx >> 3, c = idx & 7;
            size_t gi = (size_t)(nv0 + row) * (KTOT / 8) + ch * 8 + c;
            int pc = (c ^ row) & 7;
            uint32_t so = (uint32_t)(row * 128 + pc * 16);
            cp_async16(sb + bo + 32768u + so, B4h + gi, 16);
            cp_async16(sb + bo + 49152u + so, B4m + gi, 16);
        }
        asm volatile("cp.async.commit_group;");
    };

    load_chunk(0, 0);
    if (1 < NCH) load_chunk(1, 1);

    for (int ch = 0; ch < NCH; ch++) {
        if (ch + 1 < NCH)
            asm volatile("cp.async.wait_group 1;");
        else
            asm volatile("cp.async.wait_group 0;");
        __syncthreads();
        if (ch + 2 < NCH) load_chunk(ch + 2, (ch + 2) % 3);

        const uint32_t bo = (uint32_t)(ch % 3) * 65536u;
        const uint32_t aHB = sb + bo;
        const uint32_t aMB = sb + bo + 16384u;
        const uint32_t bHB = sb + bo + 32768u;
        const uint32_t bMB = sb + bo + 49152u;
#pragma unroll
        for (int k16 = 0; k16 < 4; k16++) {
            const int kc0 = k16 * 2;
            uint32_t ah[2][4], am[2][4];
#pragma unroll
            for (int mi = 0; mi < 2; mi++) {
                int row = wm + mi * 16 + lr + (lq & 1) * 8;
                int kc  = kc0 + (lq >> 1);
                int pc  = (kc ^ row) & 7;
                ldsm_x4(ah[mi], aHB + row * 128 + pc * 16);
                ldsm_x4(am[mi], aMB + row * 128 + pc * 16);
            }
#pragma unroll
            for (int nc = 0; nc < 2; nc++) {
                uint32_t bh[4], bm[4];
                int row = wn + nc * 16 + lr + (lq >> 1) * 8;
                int kc  = kc0 + (lq & 1);
                int pc  = (kc ^ row) & 7;
                ldsm_x4(bh, bHB + row * 128 + pc * 16);
                ldsm_x4(bm, bMB + row * 128 + pc * 16);
                mma16816h(acc1[0][nc * 2 + 0], ah[0], bh[0], bh[1]);
                mma16816h(acc1[0][nc * 2 + 1], ah[0], bh[2], bh[3]);
                mma16816h(acc1[1][nc * 2 + 0], ah[1], bh[0], bh[1]);
                mma16816h(acc1[1][nc * 2 + 1], ah[1], bh[2], bh[3]);
                mma16816h(acc2[0][nc * 2 + 0], ah[0], bm[0], bm[1]);
                mma16816h(acc2[0][nc * 2 + 1], ah[0], bm[2], bm[3]);
                mma16816h(acc2[1][nc * 2 + 0], ah[1], bm[0], bm[1]);
                mma16816h(acc2[1][nc * 2 + 1], ah[1], bm[2], bm[3]);
                mma16816h(acc2[0][nc * 2 + 0], am[0], bh[0], bh[1]);
                mma16816h(acc2[0][nc * 2 + 1], am[0], bh[2], bh[3]);
                mma16816h(acc2[1][nc * 2 + 0], am[1], bh[0], bh[1]);
                mma16816h(acc2[1][nc * 2 + 1], am[1], bh[2], bh[3]);
            }
        }
    }

    const int gid = lane >> 2, tig = lane & 3;
#pragma unroll
    for (int mi = 0; mi < 2; mi++) {
        const int m0 = pm0 + wm + mi * 16 + gid;
#pragma unroll
        for (int ni = 0; ni < 4; ni++) {
            const int n = nv0 + wn + ni * 8 + tig * 2;
            const float2 bv = *reinterpret_cast<const float2*>(Bias + n);
            float v00 = fmaxf(fmaf(acc2[mi][ni][0], LO_INV, acc1[mi][ni][0]) + bv.x, 0.f);
            float v01 = fmaxf(fmaf(acc2[mi][ni][1], LO_INV, acc1[mi][ni][1]) + bv.y, 0.f);
            float v10 = fmaxf(fmaf(acc2[mi][ni][2], LO_INV, acc1[mi][ni][2]) + bv.x, 0.f);
            float v11 = fmaxf(fmaf(acc2[mi][ni][3], LO_INV, acc1[mi][ni][3]) + bv.y, 0.f);
            if (WF32) {
                float2 a0; a0.x = v00; a0.y = v01;
                float2 a1; a1.x = v10; a1.y = v11;
                *reinterpret_cast<float2*>(Yf + (size_t)m0 * COUT + n)       = a0;
                *reinterpret_cast<float2*>(Yf + (size_t)(m0 + 8) * COUT + n) = a1;
            } else {
                half h00,m00,h01,m01,h10,m10,h11,m11;
                split2h(v00,h00,m00); split2h(v01,h01,m01);
                split2h(v10,h10,m10); split2h(v11,h11,m11);
                __half2 p0, p1;
                p0.x=h00; p0.y=h01; p1.x=h10; p1.y=h11;
                *reinterpret_cast<__half2*>(Yh + (size_t)m0 * COUT + n)       = p0;
                *reinterpret_cast<__half2*>(Yh + (size_t)(m0 + 8) * COUT + n) = p1;
                p0.x=m00; p0.y=m01; p1.x=m10; p1.y=m11;
                *reinterpret_cast<__half2*>(Ym + (size_t)m0 * COUT + n)       = p0;
                *reinterpret_cast<__half2*>(Ym + (size_t)(m0 + 8) * COUT + n) = p1;
            }
        }
    }
}

// ---------------- encoder head: fp16x3 GEMM [128x64, K=256] + fused LN(64) ---
// full K resident; LN reduces within lane quads (cols of one row live in 4 tigs)
__global__ void __launch_bounds__(256)
head_mma_ln(const half* __restrict__ Ah, const half* __restrict__ Am,
            const half* __restrict__ Wh, const half* __restrict__ Wm,
            const float* __restrict__ Bias,
            const float* __restrict__ G, const float* __restrict__ Bt,
            float* __restrict__ Z)
{
    extern __shared__ char smem[];
    const int tid = threadIdx.x;
    const int pm0 = blockIdx.x * 128;
    const uint32_t sb = smem_to_u32(smem);
    // layout: AH 0 (64K), AM 65536 (64K), BH 131072 (32K), BM 163840 (32K)

    {
        const uint4* A4h = reinterpret_cast<const uint4*>(Ah);
        const uint4* A4m = reinterpret_cast<const uint4*>(Am);
#pragma unroll
        for (int i = 0; i < 16; i++) {
            int idx = tid + i * 256;          // 0..4095
            int row = idx >> 5, c = idx & 31;
            int pc = (c & 24) | ((c ^ row) & 7);
            uint32_t so = (uint32_t)(row * 512 + pc * 16);
            size_t gi = (size_t)(pm0 + row) * 32 + c;
            cp_async16(sb + so,          A4h + gi, 16);
            cp_async16(sb + 65536u + so, A4m + gi, 16);
        }
        const uint4* B4h = reinterpret_cast<const uint4*>(Wh);
        const uint4* B4m = reinterpret_cast<const uint4*>(Wm);
#pragma unroll
        for (int i = 0; i < 8; i++) {
            int idx = tid + i * 256;          // 0..2047
            int row = idx >> 5, c = idx & 31;
            int pc = (c & 24) | ((c ^ row) & 7);
            uint32_t so = (uint32_t)(row * 512 + pc * 16);
            size_t gi = (size_t)row * 32 + c;
            cp_async16(sb + 131072u + so, B4h + gi, 16);
            cp_async16(sb + 163840u + so, B4m + gi, 16);
        }
        asm volatile("cp.async.commit_group;");
    }

    const int wid = tid >> 5, lane = tid & 31;
    const int wm = wid * 16;                // 8 warps x 16 rows
    const int lr = lane & 7, lq = lane >> 3;

    float acc1[8][4], acc2[8][4];
#pragma unroll
    for (int ni = 0; ni < 8; ni++)
#pragma unroll
        for (int e = 0; e < 4; e++) { acc1[ni][e] = 0.f; acc2[ni][e] = 0.f; }

    asm volatile("cp.async.wait_group 0;");
    __syncthreads();

#pragma unroll
    for (int k16 = 0; k16 < 16; k16++) {
        const int kc0 = k16 * 2;
        uint32_t ah[4], am[4];
        {
            int row = wm + lr + (lq & 1) * 8;
            int kc  = kc0 + (lq >> 1);
            int pc  = (kc & 24) | ((kc ^ row) & 7);
            ldsm_x4(ah, sb + row * 512 + pc * 16);
            ldsm_x4(am, sb + 65536u + row * 512 + pc * 16);
        }
#pragma unroll
        for (int nc = 0; nc < 4; nc++) {
            uint32_t bh[4], bm[4];
            int row = nc * 16 + lr + (lq >> 1) * 8;
            int kc  = kc0 + (lq & 1);
            int pc  = (kc & 24) | ((kc ^ row) & 7);
            ldsm_x4(bh, sb + 131072u + row * 512 + pc * 16);
            ldsm_x4(bm, sb + 163840u + row * 512 + pc * 16);
            mma16816h(acc1[nc * 2 + 0], ah, bh[0], bh[1]);
            mma16816h(acc1[nc * 2 + 1], ah, bh[2], bh[3]);
            mma16816h(acc2[nc * 2 + 0], ah, bm[0], bm[1]);
            mma16816h(acc2[nc * 2 + 1], ah, bm[2], bm[3]);
            mma16816h(acc2[nc * 2 + 0], am, bh[0], bh[1]);
            mma16816h(acc2[nc * 2 + 1], am, bh[2], bh[3]);
        }
    }

    const int gid = lane >> 2, tig = lane & 3;
    float v[8][4];
#pragma unroll
    for (int ni = 0; ni < 8; ni++) {
        const int n = ni * 8 + tig * 2;
        const float2 bv = *reinterpret_cast<const float2*>(Bias + n);
        v[ni][0] = fmaf(acc2[ni][0], LO_INV, acc1[ni][0]) + bv.x;
        v[ni][1] = fmaf(acc2[ni][1], LO_INV, acc1[ni][1]) + bv.y;
        v[ni][2] = fmaf(acc2[ni][2], LO_INV, acc1[ni][2]) + bv.x;
        v[ni][3] = fmaf(acc2[ni][3], LO_INV, acc1[ni][3]) + bv.y;
    }
    // LayerNorm over 64 cols: each row's cols live across the 4 tig threads
    float s0 = 0.f, s1 = 0.f;
#pragma unroll
    for (int ni = 0; ni < 8; ni++) { s0 += v[ni][0] + v[ni][1]; s1 += v[ni][2] + v[ni][3]; }
    s0 += __shfl_xor_sync(0xffffffffu, s0, 1);  s0 += __shfl_xor_sync(0xffffffffu, s0, 2);
    s1 += __shfl_xor_sync(0xffffffffu, s1, 1);  s1 += __shfl_xor_sync(0xffffffffu, s1, 2);
    float mu0 = s0 * (1.f / 64.f), mu1 = s1 * (1.f / 64.f);
    float q0 = 0.f, q1 = 0.f;
#pragma unroll
    for (int ni = 0; ni < 8; ni++) {
        float d0 = v[ni][0] - mu0, d1 = v[ni][1] - mu0;
        float d2 = v[ni][2] - mu1, d3 = v[ni][3] - mu1;
        q0 += d0 * d0 + d1 * d1;
        q1 += d2 * d2 + d3 * d3;
    }
    q0 += __shfl_xor_sync(0xffffffffu, q0, 1);  q0 += __shfl_xor_sync(0xffffffffu, q0, 2);
    q1 += __shfl_xor_sync(0xffffffffu, q1, 1);  q1 += __shfl_xor_sync(0xffffffffu, q1, 2);
    float rs0 = rsqrtf(q0 * (1.f / 64.f) + LN_EPS);
    float rs1 = rsqrtf(q1 * (1.f / 64.f) + LN_EPS);

    const int r0 = pm0 + wm + gid, r1 = r0 + 8;
#pragma unroll
    for (int ni = 0; ni < 8; ni++) {
        const int c = ni * 8 + tig * 2;
        const float2 gv = *reinterpret_cast<const float2*>(G + c);
        const float2 bb = *reinterpret_cast<const float2*>(Bt + c);
        float2 o0, o1;
        o0.x = (v[ni][0] - mu0) * rs0 * gv.x + bb.x;
        o0.y = (v[ni][1] - mu0) * rs0 * gv.y + bb.y;
        o1.x = (v[ni][2] - mu1) * rs1 * gv.x + bb.x;
        o1.y = (v[ni][3] - mu1) * rs1 * gv.y + bb.y;
        *reinterpret_cast<float2*>(Z + (size_t)r0 * 64 + c) = o0;
        *reinterpret_cast<float2*>(Z + (size_t)r1 * 64 + c) = o1;
    }
}

// ---------------- wide full-K-resident bf16x3 logits GEMM, 16-warp -----------
#define LGW_SMEM 196608

__global__ void __launch_bounds__(512, 1)
logits_wide(const bf16* __restrict__ Ahi, const bf16* __restrict__ Alo,
            const bf16* __restrict__ Bhi, const bf16* __restrict__ Blo,
            const float* __restrict__ Bias, float* __restrict__ Out)
{
    extern __shared__ char smem[];
    const int tid = threadIdx.x;
    const int pm0 = blockIdx.x * 128;
    const int nv0 = blockIdx.y * 256;

    const uint32_t sb = smem_to_u32(smem);

    {
        const uint4* A4h = reinterpret_cast<const uint4*>(Ahi);
        const uint4* A4l = reinterpret_cast<const uint4*>(Alo);
#pragma unroll
        for (int i = 0; i < 4; i++) {
            int idx = tid + i * 512;
            int row = idx >> 4, c = idx & 15;
            int pc = (c & 8) | ((c ^ row) & 7);
            cp_async16(sb + (uint32_t)(row * 256 + pc * 16),
                       A4h + (size_t)(pm0 + row) * 16 + c, 16);
            cp_async16(sb + 32768u + (uint32_t)(row * 256 + pc * 16),
                       A4l + (size_t)(pm0 + row) * 16 + c, 16);
        }
        const uint4* B4h = reinterpret_cast<const uint4*>(Bhi);
        const uint4* B4l = reinterpret_cast<const uint4*>(Blo);
#pragma unroll
        for (int i = 0; i < 8; i++) {
            int idx = tid + i * 512;
            int row = idx >> 4, c = idx & 15;
            int pc = (c & 8) | ((c ^ row) & 7);
            cp_async16(sb + 65536u + (uint32_t)(row * 256 + pc * 16),
                       B4h + (size_t)(nv0 + row) * 16 + c, 16);
            cp_async16(sb + 131072u + (uint32_t)(row * 256 + pc * 16),
                       B4l + (size_t)(nv0 + row) * 16 + c, 16);
        }
        asm volatile("cp.async.commit_group;");
    }

    const int wid = tid >> 5, lane = tid & 31;
    const int wm = (wid >> 2) * 32;       // 0,32,64,96
    const int wn = (wid & 3) * 64;        // 0,64,128,192
    const int lr = lane & 7, lq = lane >> 3;

    float acc[2][8][4];
#pragma unroll
    for (int mi = 0; mi < 2; mi++)
#pragma unroll
        for (int ni = 0; ni < 8; ni++)
#pragma unroll
            for (int e = 0; e < 4; e++) acc[mi][ni][e] = 0.f;

    asm volatile("cp.async.wait_group 0;");
    __syncthreads();

#pragma unroll
    for (int k16 = 0; k16 < 8; k16++) {
        const int kc0 = k16 * 2;
        uint32_t ah[2][4], al[2][4];
#pragma unroll
        for (int mi = 0; mi < 2; mi++) {
            int row = wm + mi * 16 + lr + (lq & 1) * 8;
            int kc  = kc0 + (lq >> 1);
            int pc  = (kc & 8) | ((kc ^ row) & 7);
            ldsm_x4(ah[mi], sb + row * 256 + pc * 16);
            ldsm_x4(al[mi], sb + 32768u + row * 256 + pc * 16);
        }
#pragma unroll
        for (int nc = 0; nc < 4; nc++) {
            uint32_t bh[4], bl[4];
            int row = wn + nc * 16 + lr + (lq >> 1) * 8;
            int kc  = kc0 + (lq & 1);
            int pc  = (kc & 8) | ((kc ^ row) & 7);
            ldsm_x4(bh, sb + 65536u + row * 256 + pc * 16);
            ldsm_x4(bl, sb + 131072u + row * 256 + pc * 16);
            mma16816(acc[0][nc * 2 + 0], ah[0], bh[0], bh[1]);
            mma16816(acc[0][nc * 2 + 1], ah[0], bh[2], bh[3]);
            mma16816(acc[1][nc * 2 + 0], ah[1], bh[0], bh[1]);
            mma16816(acc[1][nc * 2 + 1], ah[1], bh[2], bh[3]);
            mma16816(acc[0][nc * 2 + 0], ah[0], bl[0], bl[1]);
            mma16816(acc[0][nc * 2 + 1], ah[0], bl[2], bl[3]);
            mma16816(acc[1][nc * 2 + 0], ah[1], bl[0], bl[1]);
            mma16816(acc[1][nc * 2 + 1], ah[1], bl[2], bl[3]);
            mma16816(acc[0][nc * 2 + 0], al[0], bh[0], bh[1]);
            mma16816(acc[0][nc * 2 + 1], al[0], bh[2], bh[3]);
            mma16816(acc[1][nc * 2 + 0], al[1], bh[0], bh[1]);
            mma16816(acc[1][nc * 2 + 1], al[1], bh[2], bh[3]);
        }
    }

    const int gid = lane >> 2, tig = lane & 3;
#pragma unroll
    for (int mi = 0; mi < 2; mi++) {
        const int m0 = pm0 + wm + mi * 16 + gid;
#pragma unroll
        for (int ni = 0; ni < 8; ni++) {
            const int n = nv0 + wn + ni * 8 + tig * 2;
            const float2 bv = *reinterpret_cast<const float2*>(Bias + n);
            float2 v0, v1;
            v0.x = acc[mi][ni][0] + bv.x;  v0.y = acc[mi][ni][1] + bv.y;
            v1.x = acc[mi][ni][2] + bv.x;  v1.y = acc[mi][ni][3] + bv.y;
            *reinterpret_cast<float2*>(Out + (size_t)m0 * VOCAB + n)       = v0;
            *reinterpret_cast<float2*>(Out + (size_t)(m0 + 8) * VOCAB + n) = v1;
        }
    }
}

// ---------------- tail: loss scalar + codes ----------------------------------
__global__ void commit_final(const float* __restrict__ Part, float* __restrict__ slot)
{
    if (threadIdx.x == 0 && blockIdx.x == 0) {
        float s = 0.f;
        for (int i = 0; i < NPOS / 64; i++) s += Part[i];
        *slot = 0.1f * s / ((float)NPOS * (float)DDIM);
    }
}

__global__ void write_codes(const int* __restrict__ codes, float* __restrict__ out)
{
    int n = blockIdx.x * blockDim.x + threadIdx.x;
    if (n < NPOS) out[n] = (float)codes[n];
}

// ---------------- launch ------------------------------------------------------
extern "C" void kernel_launch(void* const* d_in, const int* in_sizes, int n_in,
                              void* d_out, int out_size)
{
    (void)in_sizes; (void)n_in;
    const int*   x    = (const int*)  d_in[0];
    const float* tok  = (const float*)d_in[1];
    const float* ew1  = (const float*)d_in[2];
    const float* eb1  = (const float*)d_in[3];
    const float* ew2  = (const float*)d_in[4];
    const float* eb2  = (const float*)d_in[5];
    const float* ew3  = (const float*)d_in[6];
    const float* eb3  = (const float*)d_in[7];
    const float* elg  = (const float*)d_in[8];
    const float* elb  = (const float*)d_in[9];
    const float* cb   = (const float*)d_in[10];
    const float* dw1  = (const float*)d_in[11];
    const float* db1  = (const float*)d_in[12];
    const float* dw2  = (const float*)d_in[13];
    const float* db2  = (const float*)d_in[14];
    const float* dw3  = (const float*)d_in[15];
    const float* db3  = (const float*)d_in[16];
    const float* dlg  = (const float*)d_in[17];
    const float* dlb  = (const float*)d_in[18];
    const float* ow   = (const float*)d_in[19];
    const float* ob   = (const float*)d_in[20];
    float* out = (float*)d_out;

    float *z, *cn, *cp;
    int* codes;
    half *ebh,*ebm,*e1h,*e1m,*e2h,*e2m,*w1eh,*w1em,*w2eh,*w2em,*w3eh,*w3em;
    bf16 *zqhi,*zqlo,*d1hi,*d1lo,*d2hi,*d2lo,*ahi,*alo;
    bf16 *w1hi,*w1lo,*w2hi,*w2lo,*w3hi,*w3lo,*bhi,*blo;
    cudaGetSymbolAddress((void**)&z,     g_z);
    cudaGetSymbolAddress((void**)&codes, g_codes);
    cudaGetSymbolAddress((void**)&cn,    g_cnorm);
    cudaGetSymbolAddress((void**)&cp,    g_commit);
    cudaGetSymbolAddress((void**)&ebh,   g_ebh);
    cudaGetSymbolAddress((void**)&ebm,   g_ebm);
    cudaGetSymbolAddress((void**)&e1h,   g_e1h);
    cudaGetSymbolAddress((void**)&e1m,   g_e1m);
    cudaGetSymbolAddress((void**)&e2h,   g_e2h);
    cudaGetSymbolAddress((void**)&e2m,   g_e2m);
    cudaGetSymbolAddress((void**)&w1eh,  g_w1eh);
    cudaGetSymbolAddress((void**)&w1em,  g_w1em);
    cudaGetSymbolAddress((void**)&w2eh,  g_w2eh);
    cudaGetSymbolAddress((void**)&w2em,  g_w2em);
    cudaGetSymbolAddress((void**)&w3eh,  g_w3eh);
    cudaGetSymbolAddress((void**)&w3em,  g_w3em);
    cudaGetSymbolAddress((void**)&zqhi,  g_zqhi);
    cudaGetSymbolAddress((void**)&zqlo,  g_zqlo);
    cudaGetSymbolAddress((void**)&d1hi,  g_d1hi);
    cudaGetSymbolAddress((void**)&d1lo,  g_d1lo);
    cudaGetSymbolAddress((void**)&d2hi,  g_d2hi);
    cudaGetSymbolAddress((void**)&d2lo,  g_d2lo);
    cudaGetSymbolAddress((void**)&ahi,   g_ahi);
    cudaGetSymbolAddress((void**)&alo,   g_alo);
    cudaGetSymbolAddress((void**)&w1hi,  g_w1hi);
    cudaGetSymbolAddress((void**)&w1lo,  g_w1lo);
    cudaGetSymbolAddress((void**)&w2hi,  g_w2hi);
    cudaGetSymbolAddress((void**)&w2lo,  g_w2lo);
    cudaGetSymbolAddress((void**)&w3hi,  g_w3hi);
    cudaGetSymbolAddress((void**)&w3lo,  g_w3lo);
    cudaGetSymbolAddress((void**)&bhi,   g_bhi);
    cudaGetSymbolAddress((void**)&blo,   g_blo);

    cudaFuncSetAttribute((const void*)tconvh<128, 3, 256, false>,
                         cudaFuncAttributeMaxDynamicSharedMemorySize, TC_SMEM);
    cudaFuncSetAttribute((const void*)tconvh<256, 3, 256, false>,
                         cudaFuncAttributeMaxDynamicSharedMemorySize, TC_SMEM);
    cudaFuncSetAttribute((const void*)head_mma_ln,
                         cudaFuncAttributeMaxDynamicSharedMemorySize, TC_SMEM);
    cudaFuncSetAttribute((const void*)tconv< 64, 1, 256, true,  false, true,  false>,
                         cudaFuncAttributeMaxDynamicSharedMemorySize, TC_SMEM);
    cudaFuncSetAttribute((const void*)tconv<256, 3, 256, true,  false, true,  false>,
                         cudaFuncAttributeMaxDynamicSharedMemorySize, TC_SMEM);
    cudaFuncSetAttribute((const void*)tconv<256, 1, 128, true,  false, false, true >,
                         cudaFuncAttributeMaxDynamicSharedMemorySize, TC_SMEM);
    cudaFuncSetAttribute((const void*)logits_wide,
                         cudaFuncAttributeMaxDynamicSharedMemorySize, LGW_SMEM);

    // ---- encoder (fp16 two-split tensor cores, 16-warp pipelined) ----
    pack_split2h<128, 3, 256><<<(256*384)  / 256, 256>>>(ew1, w1eh, w1em);
    pack_split2h<256, 3, 256><<<(256*768)  / 256, 256>>>(ew2, w2eh, w2em);
    pack_split2h<256, 1,  64><<<(64*256)   / 256, 256>>>(ew3, w3eh, w3em);
    embed_split2h<<<NPOS * 32 / 256, 256>>>(x, tok, ebh, ebm);
    tconvh<128, 3, 256, false><<<dim3(NPOS/128, 2), 512, TC_SMEM>>>(
        ebh, ebm, w1eh, w1em, eb1, nullptr, e1h, e1m);
    tconvh<256, 3, 256, false><<<dim3(NPOS/128, 2), 512, TC_SMEM>>>(
        e1h, e1m, w2eh, w2em, eb2, nullptr, e2h, e2m);
    head_mma_ln<<<NPOS/128, 256, TC_SMEM>>>(e2h, e2m, w3eh, w3em, eb3, elg, elb, z);

    // ---- vector quantization ----
    cnorm_kernel<<<1, 512>>>(cb, cn);
    vq_kernel<<<NPOS / 64, 256>>>(z, cb, cn, codes, cp);
    gather_zq_split<<<NPOS * 16 / 256, 256>>>(codes, cb, zqhi, zqlo);

    // ---- decoder weight packs + decoder (bf16x3, 16-warp pipelined) ----
    pack_split< 64, 1, 256>  <<<(256*64)   / 256, 256>>>(dw1, w1hi, w1lo);
    pack_split<256, 3, 256>  <<<(256*768)  / 256, 256>>>(dw2, w2hi, w2lo);
    pack_split<256, 1, 128>  <<<(128*256)  / 256, 256>>>(dw3, w3hi, w3lo);
    pack_split<128, 1, VOCAB><<<(VOCAB*128)/ 256, 256>>>(ow,  bhi,  blo);

    tconv< 64, 1, 256, true,  false, true,  false><<<dim3(NPOS/128, 2), 512, TC_SMEM>>>(
        zqhi, zqlo, w1hi, w1lo, db1, nullptr, nullptr, nullptr, d1hi, d1lo);
    tconv<256, 3, 256, true,  false, true,  false><<<dim3(NPOS/128, 2), 512, TC_SMEM>>>(
        d1hi, d1lo, w2hi, w2lo, db2, nullptr, nullptr, nullptr, d2hi, d2lo);
    tconv<256, 1, 128, true,  false, false, true ><<<dim3(NPOS/128, 1), 512, TC_SMEM>>>(
        d2hi, d2lo, w3hi, w3lo, db3, dlg, dlb, nullptr, ahi, alo);

    // ---- vocab projection (wide full-K bf16x3, 16-warp) -> d_out ----
    logits_wide<<<dim3(NPOS/128, VOCAB/256), 512, LGW_SMEM>>>(
        ahi, alo, bhi, blo, ob, out);

    // ---- tail: loss scalar + codes ----
    const long long NV = (long long)NPOS * VOCAB;   // 134217728
    if ((long long)out_size >= NV + 1)
        commit_final<<<1, 32>>>(cp, out + NV);
    if ((long long)out_size >= NV + 1 + NPOS)
        write_codes<<<NPOS / 256, 256>>>(codes, out + NV + 1);
}

// round 15
// speedup vs baseline: 1.0782x; 1.0113x over previous
#include <cuda_runtime.h>
#include <cuda_bf16.h>
#include <cuda_fp16.h>
#include <cstdint>

// Problem constants
#define NPOS   32768          // B*L = 8*4096
#define LSEQ   4096
#define EDIM   128
#define HDIM   256
#define DDIM   64
#define KCODE  512
#define VOCAB  4096
#define LN_EPS 1e-5f

typedef __nv_bfloat16 bf16;

#define LO_SCALE   2048.0f
#define LO_INV     (1.0f / 2048.0f)

// ---------------- scratch (static device globals; no allocation) -------------
__device__ float g_z  [NPOS * DDIM];    // z_e after LN
__device__ int   g_codes[NPOS];
__device__ float g_cnorm[KCODE];
__device__ float g_commit[NPOS / 64];
// encoder fp16 two-split activations (lo scaled by 2048)
__device__ __align__(16) half g_ebh[NPOS * EDIM];
__device__ __align__(16) half g_ebm[NPOS * EDIM];
__device__ __align__(16) half g_e1h[NPOS * HDIM];
__device__ __align__(16) half g_e1m[NPOS * HDIM];
__device__ __align__(16) half g_e2h[NPOS * HDIM];
__device__ __align__(16) half g_e2m[NPOS * HDIM];
// encoder fp16 two-split packed weights
__device__ __align__(16) half g_w1eh[HDIM * EDIM * 3];
__device__ __align__(16) half g_w1em[HDIM * EDIM * 3];
__device__ __align__(16) half g_w2eh[HDIM * HDIM * 3];
__device__ __align__(16) half g_w2em[HDIM * HDIM * 3];
__device__ __align__(16) half g_w3eh[DDIM * HDIM];
__device__ __align__(16) half g_w3em[DDIM * HDIM];
// decoder bf16 hi/lo split activations
__device__ __align__(16) bf16 g_zqhi[NPOS * DDIM];
__device__ __align__(16) bf16 g_zqlo[NPOS * DDIM];
__device__ __align__(16) bf16 g_d1hi[NPOS * HDIM];
__device__ __align__(16) bf16 g_d1lo[NPOS * HDIM];
__device__ __align__(16) bf16 g_d2hi[NPOS * HDIM];
__device__ __align__(16) bf16 g_d2lo[NPOS * HDIM];
__device__ __align__(16) bf16 g_ahi[NPOS * EDIM];
__device__ __align__(16) bf16 g_alo[NPOS * EDIM];
// decoder bf16 hi/lo split packed weights
__device__ __align__(16) bf16 g_w1hi[HDIM * DDIM];
__device__ __align__(16) bf16 g_w1lo[HDIM * DDIM];
__device__ __align__(16) bf16 g_w2hi[HDIM * HDIM * 3];
__device__ __align__(16) bf16 g_w2lo[HDIM * HDIM * 3];
__device__ __align__(16) bf16 g_w3hi[EDIM * HDIM];
__device__ __align__(16) bf16 g_w3lo[EDIM * HDIM];
__device__ __align__(16) bf16 g_bhi[VOCAB * EDIM];
__device__ __align__(16) bf16 g_blo[VOCAB * EDIM];

__device__ __forceinline__ uint32_t smem_to_u32(const void* smem_ptr) {
    uint32_t addr;
    asm("{ .reg .u64 tmp; cvta.to.shared.u64 tmp, %1; cvt.u32.u64 %0, tmp; }"
        : "=r"(addr) : "l"(smem_ptr));
    return addr;
}

__device__ __forceinline__ void cp_async16(uint32_t saddr, const void* gptr, int src_bytes) {
    asm volatile("cp.async.cg.shared.global [%0], [%1], 16, %2;"
                 :: "r"(saddr), "l"(gptr), "r"(src_bytes));
}

// fp16 two-split: x = h + (m/2048); m kept in normal fp16 range
__device__ __forceinline__ void split2h(float x, half& h, half& m) {
    h = __float2half_rn(x);
    m = __float2half_rn((x - __half2float(h)) * LO_SCALE);
}

// ---------------- embedding lookup with fused fp16 two-split ------------------
__global__ void embed_split2h(const int* __restrict__ x,
                              const float* __restrict__ tok,
                              half* __restrict__ H, half* __restrict__ M)
{
    int idx = blockIdx.x * blockDim.x + threadIdx.x;   // NPOS*32 float4s
    int n = idx >> 5;
    int j = idx & 31;
    int t = x[n];
    float4 v = reinterpret_cast<const float4*>(tok)[t * 32 + j];
    half h0,m0,h1,m1,h2,m2,h3,m3;
    split2h(v.x,h0,m0); split2h(v.y,h1,m1);
    split2h(v.z,h2,m2); split2h(v.w,h3,m3);
    __half2 p;
    p.x=h0; p.y=h1; reinterpret_cast<__half2*>(H)[n*64+j*2+0]=p;
    p.x=h2; p.y=h3; reinterpret_cast<__half2*>(H)[n*64+j*2+1]=p;
    p.x=m0; p.y=m1; reinterpret_cast<__half2*>(M)[n*64+j*2+0]=p;
    p.x=m2; p.y=m3; reinterpret_cast<__half2*>(M)[n*64+j*2+1]=p;
}

// ---------------- weight pack + splits ----------------------------------------
template<int CIN, int KW, int COUT>
__global__ void pack_split(const float* __restrict__ W,
                           bf16* __restrict__ Hi, bf16* __restrict__ Lo)
{
    int idx = blockIdx.x * blockDim.x + threadIdx.x;
    if (idx >= COUT * KW * CIN) return;
    int o   = idx / (KW * CIN);
    int rem = idx - o * (KW * CIN);
    int tap = rem / CIN;
    int ci  = rem - tap * CIN;
    float w = W[(size_t)o * CIN * KW + ci * KW + tap];
    bf16 h = __float2bfloat16(w);
    Hi[idx] = h;
    Lo[idx] = __float2bfloat16(w - __bfloat162float(h));
}

template<int CIN, int KW, int COUT>
__global__ void pack_split2h(const float* __restrict__ W,
                             half* __restrict__ H, half* __restrict__ M)
{
    int idx = blockIdx.x * blockDim.x + threadIdx.x;
    if (idx >= COUT * KW * CIN) return;
    int o   = idx / (KW * CIN);
    int rem = idx - o * (KW * CIN);
    int tap = rem / CIN;
    int ci  = rem - tap * CIN;
    float w = W[(size_t)o * CIN * KW + ci * KW + tap];
    half h, m;
    split2h(w, h, m);
    H[idx] = h; M[idx] = m;
}

// ---------------- codebook norms (no FMA: match sum(c*c)) --------------------
__global__ void cnorm_kernel(const float* __restrict__ CB, float* __restrict__ CN)
{
    int c = blockIdx.x * blockDim.x + threadIdx.x;
    if (c < KCODE) {
        float s = 0.f;
        for (int d = 0; d < DDIM; d++) {
            float v = CB[c * DDIM + d];
            s = __fadd_rn(s, __fmul_rn(v, v));
        }
        CN[c] = s;
    }
}

// ---------------- VQ: argmin over codes + commit-loss partials ---------------
__global__ void __launch_bounds__(256)
vq_kernel(const float* __restrict__ Z, const float* __restrict__ CB,
          const float* __restrict__ CN, int* __restrict__ Codes,
          float* __restrict__ CommitPart)
{
    __shared__ float Zt[64][66];
    __shared__ float Cs[64][66];
    __shared__ float znS[64];
    __shared__ float cvals[64];

    const int pm0 = blockIdx.x * 64;
    const int tid = threadIdx.x;
    const int tx = tid & 15, ty = tid >> 4;

#pragma unroll
    for (int i = 0; i < 16; i++) {
        int idx = tid + i * 256;
        int m = idx >> 6, d = idx & 63;
        Zt[d][m] = Z[(size_t)(pm0 + m) * 64 + d];
    }
    __syncthreads();

    if (tid < 64) {
        const int m = tid;
        float s = 0.f;
        for (int d = 0; d < 64; d++) {
            float v = Zt[d][m];
            s = __fadd_rn(s, __fmul_rn(v, v));
        }
        znS[m] = s;
    }
    __syncthreads();

    float zm[4];
#pragma unroll
    for (int i = 0; i < 4; i++) zm[i] = znS[ty * 4 + i];

    float minv[4]; int mini[4];
#pragma unroll
    for (int i = 0; i < 4; i++) { minv[i] = 3.4e38f; mini[i] = 0; }

    for (int c0 = 0; c0 < KCODE; c0 += 64) {
        __syncthreads();
#pragma unroll
        for (int i = 0; i < 16; i++) {
            int idx = tid + i * 256;
            int c = idx >> 6, d = idx & 63;
            Cs[d][c] = CB[(size_t)(c0 + c) * 64 + d];
        }
        __syncthreads();

        float dot[4][4];
#pragma unroll
        for (int i = 0; i < 4; i++)
#pragma unroll
            for (int j = 0; j < 4; j++) dot[i][j] = 0.f;
#pragma unroll
        for (int kk = 0; kk < 64; kk++) {
            float a[4], b[4];
#pragma unroll
            for (int i = 0; i < 4; i++) a[i] = Zt[kk][ty * 4 + i];
#pragma unroll
            for (int j = 0; j < 4; j++) b[j] = Cs[kk][tx * 4 + j];
#pragma unroll
            for (int i = 0; i < 4; i++)
#pragma unroll
                for (int j = 0; j < 4; j++)
                    dot[i][j] = fmaf(a[i], b[j], dot[i][j]);
        }
#pragma unroll
        for (int j = 0; j < 4; j++) {
            const int c = c0 + tx * 4 + j;
            const float cn = CN[c];
#pragma unroll
            for (int i = 0; i < 4; i++) {
                float t    = __fadd_rn(zm[i], -__fmul_rn(2.f, dot[i][j]));
                float dist = __fadd_rn(t, cn);
                if (dist < minv[i]) { minv[i] = dist; mini[i] = c; }
            }
        }
    }
    __syncthreads();

    float* redv = &Cs[0][0];
    int*   redi = reinterpret_cast<int*>(&Cs[0][0]) + 1024;
#pragma unroll
    for (int i = 0; i < 4; i++) {
        const int m = ty * 4 + i;
        redv[m * 16 + tx] = minv[i];
        redi[m * 16 + tx] = mini[i];
    }
    __syncthreads();
    if (tid < 64) {
        const int m = tid;
        float bv = redv[m * 16];
        int   bi = redi[m * 16];
        for (int t = 1; t < 16; t++) {
            float v = redv[m * 16 + t];
            int  ix = redi[m * 16 + t];
            if (v < bv || (v == bv && ix < bi)) { bv = v; bi = ix; }
        }
        Codes[pm0 + m] = bi;
        cvals[m] = bv;
    }
    __syncthreads();
    if (tid == 0) {
        float s = 0.f;
        for (int m = 0; m < 64; m++) s += cvals[m];
        CommitPart[blockIdx.x] = s;
    }
}

// ---------------- gather z_q with fused bf16 hi/lo split ----------------------
__global__ void gather_zq_split(const int* __restrict__ codes,
                                const float* __restrict__ CB,
                                bf16* __restrict__ Hi, bf16* __restrict__ Lo)
{
    int idx = blockIdx.x * blockDim.x + threadIdx.x;   // NPOS*16 float4s
    int n = idx >> 4;
    int j = idx & 15;
    float4 v = reinterpret_cast<const float4*>(CB)[codes[n] * 16 + j];
    bf16 h0 = __float2bfloat16(v.x), h1 = __float2bfloat16(v.y);
    bf16 h2 = __float2bfloat16(v.z), h3 = __float2bfloat16(v.w);
    __nv_bfloat162 hh0; hh0.x = h0; hh0.y = h1;
    __nv_bfloat162 hh1; hh1.x = h2; hh1.y = h3;
    __nv_bfloat162 ll0; ll0.x = __float2bfloat16(v.x - __bfloat162float(h0));
    ll0.y = __float2bfloat16(v.y - __bfloat162float(h1));
    __nv_bfloat162 ll1; ll1.x = __float2bfloat16(v.z - __bfloat162float(h2));
    ll1.y = __float2bfloat16(v.w - __bfloat162float(h3));
    reinterpret_cast<__nv_bfloat162*>(Hi)[n * 32 + j * 2 + 0] = hh0;
    reinterpret_cast<__nv_bfloat162*>(Hi)[n * 32 + j * 2 + 1] = hh1;
    reinterpret_cast<__nv_bfloat162*>(Lo)[n * 32 + j * 2 + 0] = ll0;
    reinterpret_cast<__nv_bfloat162*>(Lo)[n * 32 + j * 2 + 1] = ll1;
}

// ---------------- mma helpers -------------------------------------------------
__device__ __forceinline__ void ldsm_x4(uint32_t* r, uint32_t addr) {
    asm volatile("ldmatrix.sync.aligned.m8n8.x4.shared.b16 {%0,%1,%2,%3}, [%4];"
                 : "=r"(r[0]), "=r"(r[1]), "=r"(r[2]), "=r"(r[3]) : "r"(addr));
}
__device__ __forceinline__ void mma16816(float* d, const uint32_t* a,
                                         uint32_t b0, uint32_t b1) {
    asm volatile(
        "mma.sync.aligned.m16n8k16.row.col.f32.bf16.bf16.f32 "
        "{%0,%1,%2,%3}, {%4,%5,%6,%7}, {%8,%9}, {%0,%1,%2,%3};"
        : "+f"(d[0]), "+f"(d[1]), "+f"(d[2]), "+f"(d[3])
        : "r"(a[0]), "r"(a[1]), "r"(a[2]), "r"(a[3]), "r"(b0), "r"(b1));
}
__device__ __forceinline__ void mma16816h(float* d, const uint32_t* a,
                                          uint32_t b0, uint32_t b1) {
    asm volatile(
        "mma.sync.aligned.m16n8k16.row.col.f32.f16.f16.f32 "
        "{%0,%1,%2,%3}, {%4,%5,%6,%7}, {%8,%9}, {%0,%1,%2,%3};"
        : "+f"(d[0]), "+f"(d[1]), "+f"(d[2]), "+f"(d[3])
        : "r"(a[0]), "r"(a[1]), "r"(a[2]), "r"(a[3]), "r"(b0), "r"(b1));
}

// ---------------- generic bf16x3 (hi/lo) tensor conv, 16-warp version --------
#define TC_SMEM 196608

template<int CIN, int KW, int COUT, bool RELU, bool WF32, bool WSPLIT, bool LNF>
__global__ void __launch_bounds__(512)
tconv(const bf16* __restrict__ Ahi, const bf16* __restrict__ Alo,
      const bf16* __restrict__ Whi, const bf16* __restrict__ Wlo,
      const float* __restrict__ Bias,
      const float* __restrict__ LG, const float* __restrict__ LB,
      float* __restrict__ Yf, bf16* __restrict__ Yhi, bf16* __restrict__ Ylo)
{
    constexpr int KTOT = CIN * KW;
    constexpr int NCH  = KTOT / 64;
    constexpr int PAD  = (KW == 3) ? 1 : 0;

    extern __shared__ char smem[];
    const int tid = threadIdx.x;
    const int pm0 = blockIdx.x * 128;
    const int nv0 = blockIdx.y * 128;

    const int wid = tid >> 5, lane = tid & 31;
    const int wm = (wid >> 2) * 32;
    const int wn = (wid & 3) * 32;
    const int lr = lane & 7, lq = lane >> 3;

    float acc[2][4][4];
#pragma unroll
    for (int mi = 0; mi < 2; mi++)
#pragma unroll
        for (int ni = 0; ni < 4; ni++)
#pragma unroll
            for (int e = 0; e < 4; e++) acc[mi][ni][e] = 0.f;

    const uint4* A4h = reinterpret_cast<const uint4*>(Ahi);
    const uint4* A4l = reinterpret_cast<const uint4*>(Alo);
    const uint4* B4h = reinterpret_cast<const uint4*>(Whi);
    const uint4* B4l = reinterpret_cast<const uint4*>(Wlo);

    const uint32_t sb = smem_to_u32(smem);

    auto load_chunk = [&](int ch, int buf) {
        const uint32_t bo = (uint32_t)buf * 65536u;
        const int tap = (ch * 64) / CIN;
        const int ci0 = (ch * 64) % CIN;
#pragma unroll
        for (int i = 0; i < 2; i++) {
            int idx = tid + i * 512;
            int row = idx >> 3, c = idx & 7;
            int p = pm0 + row;
            bool ok = true;
            if (KW == 3) {
                int ls = (p & (LSEQ - 1)) + tap - PAD;
                ok = ((unsigned)ls < (unsigned)LSEQ);
            }
            size_t gi = ok ? ((size_t)(p + tap - PAD) * (CIN / 8) + (ci0 / 8) + c) : 0;
            int nb = ok ? 16 : 0;
            int pc = (c ^ row) & 7;
            uint32_t so = (uint32_t)(row * 128 + pc * 16);
            cp_async16(sb + bo + so,          A4h + gi, nb);
            cp_async16(sb + bo + 16384u + so, A4l + gi, nb);
        }
#pragma unroll
        for (int i = 0; i < 2; i++) {
            int idx = tid + i * 512;
            int row = idx >> 3, c = idx & 7;
            size_t gi = (size_t)(nv0 + row) * (KTOT / 8) + ch * 8 + c;
            int pc = (c ^ row) & 7;
            uint32_t so = (uint32_t)(row * 128 + pc * 16);
            cp_async16(sb + bo + 32768u + so, B4h + gi, 16);
            cp_async16(sb + bo + 49152u + so, B4l + gi, 16);
        }
        asm volatile("cp.async.commit_group;");
    };

    load_chunk(0, 0);
    if (1 < NCH) load_chunk(1, 1);

    for (int ch = 0; ch < NCH; ch++) {
        if (ch + 1 < NCH)
            asm volatile("cp.async.wait_group 1;");
        else
            asm volatile("cp.async.wait_group 0;");
        __syncthreads();
        if (ch + 2 < NCH) load_chunk(ch + 2, (ch + 2) % 3);

        const uint32_t bo = (uint32_t)(ch % 3) * 65536u;
        const uint32_t aHB = sb + bo;
        const uint32_t aLB = sb + bo + 16384u;
        const uint32_t bHB = sb + bo + 32768u;
        const uint32_t bLB = sb + bo + 49152u;
#pragma unroll
        for (int k16 = 0; k16 < 4; k16++) {
            const int kc0 = k16 * 2;
            uint32_t ah[2][4], al[2][4];
#pragma unroll
            for (int mi = 0; mi < 2; mi++) {
                int row = wm + mi * 16 + lr + (lq & 1) * 8;
                int kc  = kc0 + (lq >> 1);
                int pc  = (kc ^ row) & 7;
                ldsm_x4(ah[mi], aHB + row * 128 + pc * 16);
                ldsm_x4(al[mi], aLB + row * 128 + pc * 16);
            }
#pragma unroll
            for (int nc = 0; nc < 2; nc++) {
                uint32_t bh[4], bl[4];
                int row = wn + nc * 16 + lr + (lq >> 1) * 8;
                int kc  = kc0 + (lq & 1);
                int pc  = (kc ^ row) & 7;
                ldsm_x4(bh, bHB + row * 128 + pc * 16);
                ldsm_x4(bl, bLB + row * 128 + pc * 16);
                mma16816(acc[0][nc * 2 + 0], ah[0], bh[0], bh[1]);
                mma16816(acc[0][nc * 2 + 1], ah[0], bh[2], bh[3]);
                mma16816(acc[1][nc * 2 + 0], ah[1], bh[0], bh[1]);
                mma16816(acc[1][nc * 2 + 1], ah[1], bh[2], bh[3]);
                mma16816(acc[0][nc * 2 + 0], ah[0], bl[0], bl[1]);
                mma16816(acc[0][nc * 2 + 1], ah[0], bl[2], bl[3]);
                mma16816(acc[1][nc * 2 + 0], ah[1], bl[0], bl[1]);
                mma16816(acc[1][nc * 2 + 1], ah[1], bl[2], bl[3]);
                mma16816(acc[0][nc * 2 + 0], al[0], bh[0], bh[1]);
                mma16816(acc[0][nc * 2 + 1], al[0], bh[2], bh[3]);
                mma16816(acc[1][nc * 2 + 0], al[1], bh[0], bh[1]);
                mma16816(acc[1][nc * 2 + 1], al[1], bh[2], bh[3]);
            }
        }
    }

    const int gid = lane >> 2, tig = lane & 3;
#pragma unroll
    for (int mi = 0; mi < 2; mi++)
#pragma unroll
        for (int ni = 0; ni < 4; ni++) {
            const int n = nv0 + wn + ni * 8 + tig * 2;
            const float2 bv = *reinterpret_cast<const float2*>(Bias + n);
            acc[mi][ni][0] += bv.x;  acc[mi][ni][1] += bv.y;
            acc[mi][ni][2] += bv.x;  acc[mi][ni][3] += bv.y;
            if (RELU) {
#pragma unroll
                for (int e = 0; e < 4; e++) acc[mi][ni][e] = fmaxf(acc[mi][ni][e], 0.f);
            }
        }

    if (LNF) {
        float* red = reinterpret_cast<float*>(smem);
        __syncthreads();
        float ps[2][2];
#pragma unroll
        for (int mi = 0; mi < 2; mi++) { ps[mi][0] = 0.f; ps[mi][1] = 0.f; }
#pragma unroll
        for (int mi = 0; mi < 2; mi++)
#pragma unroll
            for (int ni = 0; ni < 4; ni++) {
                ps[mi][0] += acc[mi][ni][0] + acc[mi][ni][1];
                ps[mi][1] += acc[mi][ni][2] + acc[mi][ni][3];
            }
#pragma unroll
        for (int mi = 0; mi < 2; mi++)
#pragma unroll
            for (int h = 0; h < 2; h++) {
                ps[mi][h] += __shfl_xor_sync(0xffffffffu, ps[mi][h], 1);
                ps[mi][h] += __shfl_xor_sync(0xffffffffu, ps[mi][h], 2);
            }
        if (tig == 0) {
#pragma unroll
            for (int mi = 0; mi < 2; mi++)
#pragma unroll
                for (int h = 0; h < 2; h++) {
                    int row = wm + mi * 16 + gid + h * 8;
                    red[row * 4 + (wn >> 5)] = ps[mi][h];
                }
        }
        __syncthreads();
        float mu[2][2];
#pragma unroll
        for (int mi = 0; mi < 2; mi++)
#pragma unroll
            for (int h = 0; h < 2; h++) {
                int row = wm + mi * 16 + gid + h * 8;
                mu[mi][h] = (red[row * 4] + red[row * 4 + 1] +
                             red[row * 4 + 2] + red[row * 4 + 3]) * (1.f / 128.f);
            }
        float q[2][2];
#pragma unroll
        for (int mi = 0; mi < 2; mi++) { q[mi][0] = 0.f; q[mi][1] = 0.f; }
#pragma unroll
        for (int mi = 0; mi < 2; mi++)
#pragma unroll
            for (int ni = 0; ni < 4; ni++) {
                float d0 = acc[mi][ni][0] - mu[mi][0];
                float d1 = acc[mi][ni][1] - mu[mi][0];
                float d2 = acc[mi][ni][2] - mu[mi][1];
                float d3 = acc[mi][ni][3] - mu[mi][1];
                q[mi][0] += d0 * d0 + d1 * d1;
                q[mi][1] += d2 * d2 + d3 * d3;
            }
#pragma unroll
        for (int mi = 0; mi < 2; mi++)
#pragma unroll
            for (int h = 0; h < 2; h++) {
                q[mi][h] += __shfl_xor_sync(0xffffffffu, q[mi][h], 1);
                q[mi][h] += __shfl_xor_sync(0xffffffffu, q[mi][h], 2);
            }
        if (tig == 0) {
#pragma unroll
            for (int mi = 0; mi < 2; mi++)
#pragma unroll
                for (int h = 0; h < 2; h++) {
                    int row = wm + mi * 16 + gid + h * 8;
                    red[512 + row * 4 + (wn >> 5)] = q[mi][h];
                }
        }
        __syncthreads();
        float rs[2][2];
#pragma unroll
        for (int mi = 0; mi < 2; mi++)
#pragma unroll
            for (int h = 0; h < 2; h++) {
                int row = wm + mi * 16 + gid + h * 8;
                float var = (red[512 + row * 4] + red[512 + row * 4 + 1] +
                             red[512 + row * 4 + 2] + red[512 + row * 4 + 3]) * (1.f / 128.f);
                rs[mi][h] = rsqrtf(var + LN_EPS);
            }
#pragma unroll
        for (int mi = 0; mi < 2; mi++) {
            const int m0 = pm0 + wm + mi * 16 + gid;
#pragma unroll
            for (int ni = 0; ni < 4; ni++) {
                const int c = wn + ni * 8 + tig * 2;
                const float2 gv = *reinterpret_cast<const float2*>(LG + c);
                const float2 bb = *reinterpret_cast<const float2*>(LB + c);
                float y0 = (acc[mi][ni][0] - mu[mi][0]) * rs[mi][0] * gv.x + bb.x;
                float y1 = (acc[mi][ni][1] - mu[mi][0]) * rs[mi][0] * gv.y + bb.y;
                float y2 = (acc[mi][ni][2] - mu[mi][1]) * rs[mi][1] * gv.x + bb.x;
                float y3 = (acc[mi][ni][3] - mu[mi][1]) * rs[mi][1] * gv.y + bb.y;
                bf16 h0 = __float2bfloat16(y0), h1 = __float2bfloat16(y1);
                bf16 h2 = __float2bfloat16(y2), h3 = __float2bfloat16(y3);
                __nv_bfloat162 p0; p0.x = h0; p0.y = h1;
                __nv_bfloat162 p1; p1.x = h2; p1.y = h3;
                *reinterpret_cast<__nv_bfloat162*>(Yhi + (size_t)m0 * COUT + c)       = p0;
                *reinterpret_cast<__nv_bfloat162*>(Yhi + (size_t)(m0 + 8) * COUT + c) = p1;
                p0.x = __float2bfloat16(y0 - __bfloat162float(h0));
                p0.y = __float2bfloat16(y1 - __bfloat162float(h1));
                p1.x = __float2bfloat16(y2 - __bfloat162float(h2));
                p1.y = __float2bfloat16(y3 - __bfloat162float(h3));
                *reinterpret_cast<__nv_bfloat162*>(Ylo + (size_t)m0 * COUT + c)       = p0;
                *reinterpret_cast<__nv_bfloat162*>(Ylo + (size_t)(m0 + 8) * COUT + c) = p1;
            }
        }
        return;
    }

#pragma unroll
    for (int mi = 0; mi < 2; mi++) {
        const int m0 = pm0 + wm + mi * 16 + gid;
#pragma unroll
        for (int ni = 0; ni < 4; ni++) {
            const int n = nv0 + wn + ni * 8 + tig * 2;
            float v00 = acc[mi][ni][0];
            float v01 = acc[mi][ni][1];
            float v10 = acc[mi][ni][2];
            float v11 = acc[mi][ni][3];
            if (WF32) {
                float2 a0; a0.x = v00; a0.y = v01;
                float2 a1; a1.x = v10; a1.y = v11;
                *reinterpret_cast<float2*>(Yf + (size_t)m0 * COUT + n)       = a0;
                *reinterpret_cast<float2*>(Yf + (size_t)(m0 + 8) * COUT + n) = a1;
            }
            if (WSPLIT) {
                bf16 h00 = __float2bfloat16(v00), h01 = __float2bfloat16(v01);
                bf16 h10 = __float2bfloat16(v10), h11 = __float2bfloat16(v11);
                __nv_bfloat162 hh0; hh0.x = h00; hh0.y = h01;
                __nv_bfloat162 hh1; hh1.x = h10; hh1.y = h11;
                __nv_bfloat162 ll0;
                ll0.x = __float2bfloat16(v00 - __bfloat162float(h00));
                ll0.y = __float2bfloat16(v01 - __bfloat162float(h01));
                __nv_bfloat162 ll1;
                ll1.x = __float2bfloat16(v10 - __bfloat162float(h10));
                ll1.y = __float2bfloat16(v11 - __bfloat162float(h11));
                *reinterpret_cast<__nv_bfloat162*>(Yhi + (size_t)m0 * COUT + n)       = hh0;
                *reinterpret_cast<__nv_bfloat162*>(Yhi + (size_t)(m0 + 8) * COUT + n) = hh1;
                *reinterpret_cast<__nv_bfloat162*>(Ylo + (size_t)m0 * COUT + n)       = ll0;
                *reinterpret_cast<__nv_bfloat162*>(Ylo + (size_t)(m0 + 8) * COUT + n) = ll1;
            }
        }
    }
}

// ---------------- fp16 two-split tensor conv (encoder), 16-warp version ------
template<int CIN, int KW, int COUT, bool WF32>
__global__ void __launch_bounds__(512)
tconvh(const half* __restrict__ Ah, const half* __restrict__ Am,
       const half* __restrict__ Wh, const half* __restrict__ Wm,
       const float* __restrict__ Bias, float* __restrict__ Yf,
       half* __restrict__ Yh, half* __restrict__ Ym)
{
    constexpr int KTOT = CIN * KW;
    constexpr int NCH  = KTOT / 64;
    constexpr int PAD  = (KW == 3) ? 1 : 0;

    extern __shared__ char smem[];
    const int tid = threadIdx.x;
    const int pm0 = blockIdx.x * 128;
    const int nv0 = blockIdx.y * 128;

    const int wid = tid >> 5, lane = tid & 31;
    const int wm = (wid >> 2) * 32;
    const int wn = (wid & 3) * 32;
    const int lr = lane & 7, lq = lane >> 3;

    float acc1[2][4][4];
    float acc2[2][4][4];
#pragma unroll
    for (int mi = 0; mi < 2; mi++)
#pragma unroll
        for (int ni = 0; ni < 4; ni++)
#pragma unroll
            for (int e = 0; e < 4; e++) { acc1[mi][ni][e] = 0.f; acc2[mi][ni][e] = 0.f; }

    const uint4* A4h = reinterpret_cast<const uint4*>(Ah);
    const uint4* A4m = reinterpret_cast<const uint4*>(Am);
    const uint4* B4h = reinterpret_cast<const uint4*>(Wh);
    const uint4* B4m = reinterpret_cast<const uint4*>(Wm);

    const uint32_t sb = smem_to_u32(smem);

    auto load_chunk = [&](int ch, int buf) {
        const uint32_t bo = (uint32_t)buf * 65536u;
        const int tap = (ch * 64) / CIN;
        const int ci0 = (ch * 64) % CIN;
#pragma unroll
        for (int i = 0; i < 2; i++) {
            int idx = tid + i * 512;
            int row = idx >> 3, c = idx & 7;
            int p = pm0 + row;
            bool ok = true;
            if (KW == 3) {
                int ls = (p & (LSEQ - 1)) + tap - PAD;
                ok = ((unsigned)ls < (unsigned)LSEQ);
            }
            size_t gi = ok ? ((size_t)(p + tap - PAD) * (CIN / 8) + (ci0 / 8) + c) : 0;
            int nb = ok ? 16 : 0;
            int pc = (c ^ row) & 7;
            uint32_t so = (uint32_t)(row * 128 + pc * 16);
            cp_async16(sb + bo + so,          A4h + gi, nb);
            cp_async16(sb + bo + 16384u + so, A4m + gi, nb);
        }
#pragma unroll
        for (int i = 0; i < 2; i++) {
            int idx = tid + i * 512;
            int row = idx >> 3, c = idx & 7;
            size_t gi = (size_t)(nv0 + row) * (KTOT / 8) + ch * 8 + c;
            int pc = (c ^ row) & 7;
            uint32_t so = (uint32_t)(row * 128 + pc * 16);
            cp_async16(sb + bo + 32768u + so, B4h + gi, 16);
            cp_async16(sb + bo + 49152u + so, B4m + gi, 16);
        }
        asm volatile("cp.async.commit_group;");
    };

    load_chunk(0, 0);
    if (1 < NCH) load_chunk(1, 1);

    for (int ch = 0; ch < NCH; ch++) {
        if (ch + 1 < NCH)
            asm volatile("cp.async.wait_group 1;");
        else
            asm volatile("cp.async.wait_group 0;");
        __syncthreads();
        if (ch + 2 < NCH) load_chunk(ch + 2, (ch + 2) % 3);

        const uint32_t bo = (uint32_t)(ch % 3) * 65536u;
        const uint32_t aHB = sb + bo;
        const uint32_t aMB = sb + bo + 16384u;
        const uint32_t bHB = sb + bo + 32768u;
        const uint32_t bMB = sb + bo + 49152u;
#pragma unroll
        for (int k16 = 0; k16 < 4; k16++) {
            const int kc0 = k16 * 2;
            uint32_t ah[2][4], am[2][4];
#pragma unroll
            for (int mi = 0; mi < 2; mi++) {
                int row = wm + mi * 16 + lr + (lq & 1) * 8;
                int kc  = kc0 + (lq >> 1);
                int pc  = (kc ^ row) & 7;
                ldsm_x4(ah[mi], aHB + row * 128 + pc * 16);
                ldsm_x4(am[mi], aMB + row * 128 + pc * 16);
            }
#pragma unroll
            for (int nc = 0; nc < 2; nc++) {
                uint32_t bh[4], bm[4];
                int row = wn + nc * 16 + lr + (lq >> 1) * 8;
                int kc  = kc0 + (lq & 1);
                int pc  = (kc ^ row) & 7;
                ldsm_x4(bh, bHB + row * 128 + pc * 16);
                ldsm_x4(bm, bMB + row * 128 + pc * 16);
                mma16816h(acc1[0][nc * 2 + 0], ah[0], bh[0], bh[1]);
                mma16816h(acc1[0][nc * 2 + 1], ah[0], bh[2], bh[3]);
                mma16816h(acc1[1][nc * 2 + 0], ah[1], bh[0], bh[1]);
                mma16816h(acc1[1][nc * 2 + 1], ah[1], bh[2], bh[3]);
                mma16816h(acc2[0][nc * 2 + 0], ah[0], bm[0], bm[1]);
                mma16816h(acc2[0][nc * 2 + 1], ah[0], bm[2], bm[3]);
                mma16816h(acc2[1][nc * 2 + 0], ah[1], bm[0], bm[1]);
                mma16816h(acc2[1][nc * 2 + 1], ah[1], bm[2], bm[3]);
                mma16816h(acc2[0][nc * 2 + 0], am[0], bh[0], bh[1]);
                mma16816h(acc2[0][nc * 2 + 1], am[0], bh[2], bh[3]);
                mma16816h(acc2[1][nc * 2 + 0], am[1], bh[0], bh[1]);
                mma16816h(acc2[1][nc * 2 + 1], am[1], bh[2], bh[3]);
            }
        }
    }

    const int gid = lane >> 2, tig = lane & 3;
#pragma unroll
    for (int mi = 0; mi < 2; mi++) {
        const int m0 = pm0 + wm + mi * 16 + gid;
#pragma unroll
        for (int ni = 0; ni < 4; ni++) {
            const int n = nv0 + wn + ni * 8 + tig * 2;
            const float2 bv = *reinterpret_cast<const float2*>(Bias + n);
            float v00 = fmaxf(fmaf(acc2[mi][ni][0], LO_INV, acc1[mi][ni][0]) + bv.x, 0.f);
            float v01 = fmaxf(fmaf(acc2[mi][ni][1], LO_INV, acc1[mi][ni][1]) + bv.y, 0.f);
            float v10 = fmaxf(fmaf(acc2[mi][ni][2], LO_INV, acc1[mi][ni][2]) + bv.x, 0.f);
            float v11 = fmaxf(fmaf(acc2[mi][ni][3], LO_INV, acc1[mi][ni][3]) + bv.y, 0.f);
            if (WF32) {
                float2 a0; a0.x = v00; a0.y = v01;
                float2 a1; a1.x = v10; a1.y = v11;
                *reinterpret_cast<float2*>(Yf + (size_t)m0 * COUT + n)       = a0;
                *reinterpret_cast<float2*>(Yf + (size_t)(m0 + 8) * COUT + n) = a1;
            } else {
                half h00,m00,h01,m01,h10,m10,h11,m11;
                split2h(v00,h00,m00); split2h(v01,h01,m01);
                split2h(v10,h10,m10); split2h(v11,h11,m11);
                __half2 p0, p1;
                p0.x=h00; p0.y=h01; p1.x=h10; p1.y=h11;
                *reinterpret_cast<__half2*>(Yh + (size_t)m0 * COUT + n)       = p0;
                *reinterpret_cast<__half2*>(Yh + (size_t)(m0 + 8) * COUT + n) = p1;
                p0.x=m00; p0.y=m01; p1.x=m10; p1.y=m11;
                *reinterpret_cast<__half2*>(Ym + (size_t)m0 * COUT + n)       = p0;
                *reinterpret_cast<__half2*>(Ym + (size_t)(m0 + 8) * COUT + n) = p1;
            }
        }
    }
}

// ---------------- encoder head: fp16x3 GEMM [128x64, K=256] + fused LN(64) ---
__global__ void __launch_bounds__(256)
head_mma_ln(const half* __restrict__ Ah, const half* __restrict__ Am,
            const half* __restrict__ Wh, const half* __restrict__ Wm,
            const float* __restrict__ Bias,
            const float* __restrict__ G, const float* __restrict__ Bt,
            float* __restrict__ Z)
{
    extern __shared__ char smem[];
    const int tid = threadIdx.x;
    const int pm0 = blockIdx.x * 128;
    const uint32_t sb = smem_to_u32(smem);

    {
        const uint4* A4h = reinterpret_cast<const uint4*>(Ah);
        const uint4* A4m = reinterpret_cast<const uint4*>(Am);
#pragma unroll
        for (int i = 0; i < 16; i++) {
            int idx = tid + i * 256;
            int row = idx >> 5, c = idx & 31;
            int pc = (c & 24) | ((c ^ row) & 7);
            uint32_t so = (uint32_t)(row * 512 + pc * 16);
            size_t gi = (size_t)(pm0 + row) * 32 + c;
            cp_async16(sb + so,          A4h + gi, 16);
            cp_async16(sb + 65536u + so, A4m + gi, 16);
        }
        const uint4* B4h = reinterpret_cast<const uint4*>(Wh);
        const uint4* B4m = reinterpret_cast<const uint4*>(Wm);
#pragma unroll
        for (int i = 0; i < 8; i++) {
            int idx = tid + i * 256;
            int row = idx >> 5, c = idx & 31;
            int pc = (c & 24) | ((c ^ row) & 7);
            uint32_t so = (uint32_t)(row * 512 + pc * 16);
            size_t gi = (size_t)row * 32 + c;
            cp_async16(sb + 131072u + so, B4h + gi, 16);
            cp_async16(sb + 163840u + so, B4m + gi, 16);
        }
        asm volatile("cp.async.commit_group;");
    }

    const int wid = tid >> 5, lane = tid & 31;
    const int wm = wid * 16;
    const int lr = lane & 7, lq = lane >> 3;

    float acc1[8][4], acc2[8][4];
#pragma unroll
    for (int ni = 0; ni < 8; ni++)
#pragma unroll
        for (int e = 0; e < 4; e++) { acc1[ni][e] = 0.f; acc2[ni][e] = 0.f; }

    asm volatile("cp.async.wait_group 0;");
    __syncthreads();

#pragma unroll
    for (int k16 = 0; k16 < 16; k16++) {
        const int kc0 = k16 * 2;
        uint32_t ah[4], am[4];
        {
            int row = wm + lr + (lq & 1) * 8;
            int kc  = kc0 + (lq >> 1);
            int pc  = (kc & 24) | ((kc ^ row) & 7);
            ldsm_x4(ah, sb + row * 512 + pc * 16);
            ldsm_x4(am, sb + 65536u + row * 512 + pc * 16);
        }
#pragma unroll
        for (int nc = 0; nc < 4; nc++) {
            uint32_t bh[4], bm[4];
            int row = nc * 16 + lr + (lq >> 1) * 8;
            int kc  = kc0 + (lq & 1);
            int pc  = (kc & 24) | ((kc ^ row) & 7);
            ldsm_x4(bh, sb + 131072u + row * 512 + pc * 16);
            ldsm_x4(bm, sb + 163840u + row * 512 + pc * 16);
            mma16816h(acc1[nc * 2 + 0], ah, bh[0], bh[1]);
            mma16816h(acc1[nc * 2 + 1], ah, bh[2], bh[3]);
            mma16816h(acc2[nc * 2 + 0], ah, bm[0], bm[1]);
            mma16816h(acc2[nc * 2 + 1], ah, bm[2], bm[3]);
            mma16816h(acc2[nc * 2 + 0], am, bh[0], bh[1]);
            mma16816h(acc2[nc * 2 + 1], am, bh[2], bh[3]);
        }
    }

    const int gid = lane >> 2, tig = lane & 3;
    float v[8][4];
#pragma unroll
    for (int ni = 0; ni < 8; ni++) {
        const int n = ni * 8 + tig * 2;
        const float2 bv = *reinterpret_cast<const float2*>(Bias + n);
        v[ni][0] = fmaf(acc2[ni][0], LO_INV, acc1[ni][0]) + bv.x;
        v[ni][1] = fmaf(acc2[ni][1], LO_INV, acc1[ni][1]) + bv.y;
        v[ni][2] = fmaf(acc2[ni][2], LO_INV, acc1[ni][2]) + bv.x;
        v[ni][3] = fmaf(acc2[ni][3], LO_INV, acc1[ni][3]) + bv.y;
    }
    float s0 = 0.f, s1 = 0.f;
#pragma unroll
    for (int ni = 0; ni < 8; ni++) { s0 += v[ni][0] + v[ni][1]; s1 += v[ni][2] + v[ni][3]; }
    s0 += __shfl_xor_sync(0xffffffffu, s0, 1);  s0 += __shfl_xor_sync(0xffffffffu, s0, 2);
    s1 += __shfl_xor_sync(0xffffffffu, s1, 1);  s1 += __shfl_xor_sync(0xffffffffu, s1, 2);
    float mu0 = s0 * (1.f / 64.f), mu1 = s1 * (1.f / 64.f);
    float q0 = 0.f, q1 = 0.f;
#pragma unroll
    for (int ni = 0; ni < 8; ni++) {
        float d0 = v[ni][0] - mu0, d1 = v[ni][1] - mu0;
        float d2 = v[ni][2] - mu1, d3 = v[ni][3] - mu1;
        q0 += d0 * d0 + d1 * d1;
        q1 += d2 * d2 + d3 * d3;
    }
    q0 += __shfl_xor_sync(0xffffffffu, q0, 1);  q0 += __shfl_xor_sync(0xffffffffu, q0, 2);
    q1 += __shfl_xor_sync(0xffffffffu, q1, 1);  q1 += __shfl_xor_sync(0xffffffffu, q1, 2);
    float rs0 = rsqrtf(q0 * (1.f / 64.f) + LN_EPS);
    float rs1 = rsqrtf(q1 * (1.f / 64.f) + LN_EPS);

    const int r0 = pm0 + wm + gid, r1 = r0 + 8;
#pragma unroll
    for (int ni = 0; ni < 8; ni++) {
        const int c = ni * 8 + tig * 2;
        const float2 gv = *reinterpret_cast<const float2*>(G + c);
        const float2 bb = *reinterpret_cast<const float2*>(Bt + c);
        float2 o0, o1;
        o0.x = (v[ni][0] - mu0) * rs0 * gv.x + bb.x;
        o0.y = (v[ni][1] - mu0) * rs0 * gv.y + bb.y;
        o1.x = (v[ni][2] - mu1) * rs1 * gv.x + bb.x;
        o1.y = (v[ni][3] - mu1) * rs1 * gv.y + bb.y;
        *reinterpret_cast<float2*>(Z + (size_t)r0 * 64 + c) = o0;
        *reinterpret_cast<float2*>(Z + (size_t)r1 * 64 + c) = o1;
    }
}

// ---------------- wide full-K-resident bf16x3 logits GEMM, 16-warp -----------
#define LGW_SMEM 196608

__global__ void __launch_bounds__(512, 1)
logits_wide(const bf16* __restrict__ Ahi, const bf16* __restrict__ Alo,
            const bf16* __restrict__ Bhi, const bf16* __restrict__ Blo,
            const float* __restrict__ Bias, float* __restrict__ Out)
{
    extern __shared__ char smem[];
    const int tid = threadIdx.x;
    const int pm0 = blockIdx.x * 128;
    const int nv0 = blockIdx.y * 256;

    const uint32_t sb = smem_to_u32(smem);

    {
        const uint4* A4h = reinterpret_cast<const uint4*>(Ahi);
        const uint4* A4l = reinterpret_cast<const uint4*>(Alo);
#pragma unroll
        for (int i = 0; i < 4; i++) {
            int idx = tid + i * 512;
            int row = idx >> 4, c = idx & 15;
            int pc = (c & 8) | ((c ^ row) & 7);
            cp_async16(sb + (uint32_t)(row * 256 + pc * 16),
                       A4h + (size_t)(pm0 + row) * 16 + c, 16);
            cp_async16(sb + 32768u + (uint32_t)(row * 256 + pc * 16),
                       A4l + (size_t)(pm0 + row) * 16 + c, 16);
        }
        const uint4* B4h = reinterpret_cast<const uint4*>(Bhi);
        const uint4* B4l = reinterpret_cast<const uint4*>(Blo);
#pragma unroll
        for (int i = 0; i < 8; i++) {
            int idx = tid + i * 512;
            int row = idx >> 4, c = idx & 15;
            int pc = (c & 8) | ((c ^ row) & 7);
            cp_async16(sb + 65536u + (uint32_t)(row * 256 + pc * 16),
                       B4h + (size_t)(nv0 + row) * 16 + c, 16);
            cp_async16(sb + 131072u + (uint32_t)(row * 256 + pc * 16),
                       B4l + (size_t)(nv0 + row) * 16 + c, 16);
        }
        asm volatile("cp.async.commit_group;");
    }

    const int wid = tid >> 5, lane = tid & 31;
    const int wm = (wid >> 2) * 32;       // 0,32,64,96
    const int wn = (wid & 3) * 64;        // 0,64,128,192
    const int lr = lane & 7, lq = lane >> 3;

    float acc[2][8][4];
#pragma unroll
    for (int mi = 0; mi < 2; mi++)
#pragma unroll
        for (int ni = 0; ni < 8; ni++)
#pragma unroll
            for (int e = 0; e < 4; e++) acc[mi][ni][e] = 0.f;

    asm volatile("cp.async.wait_group 0;");
    __syncthreads();

#pragma unroll
    for (int k16 = 0; k16 < 8; k16++) {
        const int kc0 = k16 * 2;
        uint32_t ah[2][4], al[2][4];
#pragma unroll
        for (int mi = 0; mi < 2; mi++) {
            int row = wm + mi * 16 + lr + (lq & 1) * 8;
            int kc  = kc0 + (lq >> 1);
            int pc  = (kc & 8) | ((kc ^ row) & 7);
            ldsm_x4(ah[mi], sb + row * 256 + pc * 16);
            ldsm_x4(al[mi], sb + 32768u + row * 256 + pc * 16);
        }
#pragma unroll
        for (int nc = 0; nc < 4; nc++) {
            uint32_t bh[4], bl[4];
            int row = wn + nc * 16 + lr + (lq >> 1) * 8;
            int kc  = kc0 + (lq & 1);
            int pc  = (kc & 8) | ((kc ^ row) & 7);
            ldsm_x4(bh, sb + 65536u + row * 256 + pc * 16);
            ldsm_x4(bl, sb + 131072u + row * 256 + pc * 16);
            mma16816(acc[0][nc * 2 + 0], ah[0], bh[0], bh[1]);
            mma16816(acc[0][nc * 2 + 1], ah[0], bh[2], bh[3]);
            mma16816(acc[1][nc * 2 + 0], ah[1], bh[0], bh[1]);
            mma16816(acc[1][nc * 2 + 1], ah[1], bh[2], bh[3]);
            mma16816(acc[0][nc * 2 + 0], ah[0], bl[0], bl[1]);
            mma16816(acc[0][nc * 2 + 1], ah[0], bl[2], bl[3]);
            mma16816(acc[1][nc * 2 + 0], ah[1], bl[0], bl[1]);
            mma16816(acc[1][nc * 2 + 1], ah[1], bl[2], bl[3]);
            mma16816(acc[0][nc * 2 + 0], al[0], bh[0], bh[1]);
            mma16816(acc[0][nc * 2 + 1], al[0], bh[2], bh[3]);
            mma16816(acc[1][nc * 2 + 0], al[1], bh[0], bh[1]);
            mma16816(acc[1][nc * 2 + 1], al[1], bh[2], bh[3]);
        }
    }

    const int gid = lane >> 2, tig = lane & 3;
#pragma unroll
    for (int mi = 0; mi < 2; mi++) {
        const int m0 = pm0 + wm + mi * 16 + gid;
#pragma unroll
        for (int ni = 0; ni < 8; ni++) {
            const int n = nv0 + wn + ni * 8 + tig * 2;
            const float2 bv = *reinterpret_cast<const float2*>(Bias + n);
            float2 v0, v1;
            v0.x = acc[mi][ni][0] + bv.x;  v0.y = acc[mi][ni][1] + bv.y;
            v1.x = acc[mi][ni][2] + bv.x;  v1.y = acc[mi][ni][3] + bv.y;
            *reinterpret_cast<float2*>(Out + (size_t)m0 * VOCAB + n)       = v0;
            *reinterpret_cast<float2*>(Out + (size_t)(m0 + 8) * VOCAB + n) = v1;
        }
    }
}

// ---------------- tail: loss scalar + codes ----------------------------------
__global__ void commit_final(const float* __restrict__ Part, float* __restrict__ slot)
{
    if (threadIdx.x == 0 && blockIdx.x == 0) {
        float s = 0.f;
        for (int i = 0; i < NPOS / 64; i++) s += Part[i];
        *slot = 0.1f * s / ((float)NPOS * (float)DDIM);
    }
}

__global__ void write_codes(const int* __restrict__ codes, float* __restrict__ out)
{
    int n = blockIdx.x * blockDim.x + threadIdx.x;
    if (n < NPOS) out[n] = (float)codes[n];
}

// ---------------- launch ------------------------------------------------------
extern "C" void kernel_launch(void* const* d_in, const int* in_sizes, int n_in,
                              void* d_out, int out_size)
{
    (void)in_sizes; (void)n_in;
    const int*   x    = (const int*)  d_in[0];
    const float* tok  = (const float*)d_in[1];
    const float* ew1  = (const float*)d_in[2];
    const float* eb1  = (const float*)d_in[3];
    const float* ew2  = (const float*)d_in[4];
    const float* eb2  = (const float*)d_in[5];
    const float* ew3  = (const float*)d_in[6];
    const float* eb3  = (const float*)d_in[7];
    const float* elg  = (const float*)d_in[8];
    const float* elb  = (const float*)d_in[9];
    const float* cb   = (const float*)d_in[10];
    const float* dw1  = (const float*)d_in[11];
    const float* db1  = (const float*)d_in[12];
    const float* dw2  = (const float*)d_in[13];
    const float* db2  = (const float*)d_in[14];
    const float* dw3  = (const float*)d_in[15];
    const float* db3  = (const float*)d_in[16];
    const float* dlg  = (const float*)d_in[17];
    const float* dlb  = (const float*)d_in[18];
    const float* ow   = (const float*)d_in[19];
    const float* ob   = (const float*)d_in[20];
    float* out = (float*)d_out;

    float *z, *cn, *cp;
    int* codes;
    half *ebh,*ebm,*e1h,*e1m,*e2h,*e2m,*w1eh,*w1em,*w2eh,*w2em,*w3eh,*w3em;
    bf16 *zqhi,*zqlo,*d1hi,*d1lo,*d2hi,*d2lo,*ahi,*alo;
    bf16 *w1hi,*w1lo,*w2hi,*w2lo,*w3hi,*w3lo,*bhi,*blo;
    cudaGetSymbolAddress((void**)&z,     g_z);
    cudaGetSymbolAddress((void**)&codes, g_codes);
    cudaGetSymbolAddress((void**)&cn,    g_cnorm);
    cudaGetSymbolAddress((void**)&cp,    g_commit);
    cudaGetSymbolAddress((void**)&ebh,   g_ebh);
    cudaGetSymbolAddress((void**)&ebm,   g_ebm);
    cudaGetSymbolAddress((void**)&e1h,   g_e1h);
    cudaGetSymbolAddress((void**)&e1m,   g_e1m);
    cudaGetSymbolAddress((void**)&e2h,   g_e2h);
    cudaGetSymbolAddress((void**)&e2m,   g_e2m);
    cudaGetSymbolAddress((void**)&w1eh,  g_w1eh);
    cudaGetSymbolAddress((void**)&w1em,  g_w1em);
    cudaGetSymbolAddress((void**)&w2eh,  g_w2eh);
    cudaGetSymbolAddress((void**)&w2em,  g_w2em);
    cudaGetSymbolAddress((void**)&w3eh,  g_w3eh);
    cudaGetSymbolAddress((void**)&w3em,  g_w3em);
    cudaGetSymbolAddress((void**)&zqhi,  g_zqhi);
    cudaGetSymbolAddress((void**)&zqlo,  g_zqlo);
    cudaGetSymbolAddress((void**)&d1hi,  g_d1hi);
    cudaGetSymbolAddress((void**)&d1lo,  g_d1lo);
    cudaGetSymbolAddress((void**)&d2hi,  g_d2hi);
    cudaGetSymbolAddress((void**)&d2lo,  g_d2lo);
    cudaGetSymbolAddress((void**)&ahi,   g_ahi);
    cudaGetSymbolAddress((void**)&alo,   g_alo);
    cudaGetSymbolAddress((void**)&w1hi,  g_w1hi);
    cudaGetSymbolAddress((void**)&w1lo,  g_w1lo);
    cudaGetSymbolAddress((void**)&w2hi,  g_w2hi);
    cudaGetSymbolAddress((void**)&w2lo,  g_w2lo);
    cudaGetSymbolAddress((void**)&w3hi,  g_w3hi);
    cudaGetSymbolAddress((void**)&w3lo,  g_w3lo);
    cudaGetSymbolAddress((void**)&bhi,   g_bhi);
    cudaGetSymbolAddress((void**)&blo,   g_blo);

    cudaFuncSetAttribute((const void*)tconvh<128, 3, 256, false>,
                         cudaFuncAttributeMaxDynamicSharedMemorySize, TC_SMEM);
    cudaFuncSetAttribute((const void*)tconvh<256, 3, 256, false>,
                         cudaFuncAttributeMaxDynamicSharedMemorySize, TC_SMEM);
    cudaFuncSetAttribute((const void*)head_mma_ln,
                         cudaFuncAttributeMaxDynamicSharedMemorySize, TC_SMEM);
    cudaFuncSetAttribute((const void*)tconv< 64, 1, 256, true,  false, true,  false>,
                         cudaFuncAttributeMaxDynamicSharedMemorySize, TC_SMEM);
    cudaFuncSetAttribute((const void*)tconv<256, 3, 256, true,  false, true,  false>,
                         cudaFuncAttributeMaxDynamicSharedMemorySize, TC_SMEM);
    cudaFuncSetAttribute((const void*)tconv<256, 1, 128, true,  false, false, true >,
                         cudaFuncAttributeMaxDynamicSharedMemorySize, TC_SMEM);
    cudaFuncSetAttribute((const void*)logits_wide,
                         cudaFuncAttributeMaxDynamicSharedMemorySize, LGW_SMEM);

    // ---- side stream for independent prep work (fork-join, capture-safe) ----
    cudaStream_t s2;
    cudaStreamCreateWithFlags(&s2, cudaStreamNonBlocking);
    cudaEvent_t eFork, eJoin, eFork2, eJoin2;
    cudaEventCreateWithFlags(&eFork,  cudaEventDisableTiming);
    cudaEventCreateWithFlags(&eJoin,  cudaEventDisableTiming);
    cudaEventCreateWithFlags(&eFork2, cudaEventDisableTiming);
    cudaEventCreateWithFlags(&eJoin2, cudaEventDisableTiming);

    cudaEventRecord(eFork, 0);
    cudaStreamWaitEvent(s2, eFork, 0);
    // side stream: all weight packs + codebook norms (independent of encoder)
    pack_split2h<128, 3, 256><<<(256*384)  / 256, 256, 0, s2>>>(ew1, w1eh, w1em);
    pack_split2h<256, 3, 256><<<(256*768)  / 256, 256, 0, s2>>>(ew2, w2eh, w2em);
    pack_split2h<256, 1,  64><<<(64*256)   / 256, 256, 0, s2>>>(ew3, w3eh, w3em);
    pack_split< 64, 1, 256>  <<<(256*64)   / 256, 256, 0, s2>>>(dw1, w1hi, w1lo);
    pack_split<256, 3, 256>  <<<(256*768)  / 256, 256, 0, s2>>>(dw2, w2hi, w2lo);
    pack_split<256, 1, 128>  <<<(128*256)  / 256, 256, 0, s2>>>(dw3, w3hi, w3lo);
    pack_split<128, 1, VOCAB><<<(VOCAB*128)/ 256, 256, 0, s2>>>(ow,  bhi,  blo);
    cnorm_kernel<<<1, 512, 0, s2>>>(cb, cn);
    cudaEventRecord(eJoin, s2);

    // ---- main stream: embedding + encoder (needs enc packs -> but enc conv1
    // needs w1eh which is on s2; embed is independent) ----
    embed_split2h<<<NPOS * 32 / 256, 256>>>(x, tok, ebh, ebm);
    // join before first consumer of packed weights
    cudaStreamWaitEvent(0, eJoin, 0);
    tconvh<128, 3, 256, false><<<dim3(NPOS/128, 2), 512, TC_SMEM>>>(
        ebh, ebm, w1eh, w1em, eb1, nullptr, e1h, e1m);
    tconvh<256, 3, 256, false><<<dim3(NPOS/128, 2), 512, TC_SMEM>>>(
        e1h, e1m, w2eh, w2em, eb2, nullptr, e2h, e2m);
    head_mma_ln<<<NPOS/128, 256, TC_SMEM>>>(e2h, e2m, w3eh, w3em, eb3, elg, elb, z);

    // ---- vector quantization ----
    vq_kernel<<<NPOS / 64, 256>>>(z, cb, cn, codes, cp);
    gather_zq_split<<<NPOS * 16 / 256, 256>>>(codes, cb, zqhi, zqlo);

    // ---- tail on side stream (depends only on VQ outputs), overlapped with
    // decoder + logits ----
    const long long NV = (long long)NPOS * VOCAB;   // 134217728
    cudaEventRecord(eFork2, 0);
    cudaStreamWaitEvent(s2, eFork2, 0);
    if ((long long)out_size >= NV + 1)
        commit_final<<<1, 32, 0, s2>>>(cp, out + NV);
    if ((long long)out_size >= NV + 1 + NPOS)
        write_codes<<<NPOS / 256, 256, 0, s2>>>(codes, out + NV + 1);
    cudaEventRecord(eJoin2, s2);

    // ---- decoder (bf16x3, 16-warp pipelined) ----
    tconv< 64, 1, 256, true,  false, true,  false><<<dim3(NPOS/128, 2), 512, TC_SMEM>>>(
        zqhi, zqlo, w1hi, w1lo, db1, nullptr, nullptr, nullptr, d1hi, d1lo);
    tconv<256, 3, 256, true,  false, true,  false><<<dim3(NPOS/128, 2), 512, TC_SMEM>>>(
        d1hi, d1lo, w2hi, w2lo, db2, nullptr, nullptr, nullptr, d2hi, d2lo);
    tconv<256, 1, 128, true,  false, false, true ><<<dim3(NPOS/128, 1), 512, TC_SMEM>>>(
        d2hi, d2lo, w3hi, w3lo, db3, dlg, dlb, nullptr, ahi, alo);

    // ---- vocab projection (wide full-K bf16x3, 16-warp) -> d_out ----
    logits_wide<<<dim3(NPOS/128, VOCAB/256), 512, LGW_SMEM>>>(
        ahi, alo, bhi, blo, ob, out);

    // join side-stream tail back into the main stream before capture ends
    cudaStreamWaitEvent(0, eJoin2, 0);

    cudaEventDestroy(eFork);
    cudaEventDestroy(eJoin);
    cudaEventDestroy(eFork2);
    cudaEventDestroy(eJoin2);
    cudaStreamDestroy(s2);
}

// round 16
// speedup vs baseline: 1.1173x; 1.0363x over previous
#include <cuda_runtime.h>
#include <cuda_bf16.h>
#include <cuda_fp16.h>
#include <cstdint>

// Problem constants
#define NPOS   32768          // B*L = 8*4096
#define LSEQ   4096
#define EDIM   128
#define HDIM   256
#define DDIM   64
#define KCODE  512
#define VOCAB  4096
#define LN_EPS 1e-5f

typedef __nv_bfloat16 bf16;

#define LO_SCALE   2048.0f
#define LO_INV     (1.0f / 2048.0f)

// ---------------- scratch (static device globals; no allocation) -------------
__device__ float g_z  [NPOS * DDIM];    // z_e after LN
__device__ int   g_codes[NPOS];
__device__ float g_cnorm[KCODE];
__device__ float g_commit[NPOS / 64];
// encoder fp16 two-split activations (lo scaled by 2048)
__device__ __align__(16) half g_ebh[NPOS * EDIM];
__device__ __align__(16) half g_ebm[NPOS * EDIM];
__device__ __align__(16) half g_e1h[NPOS * HDIM];
__device__ __align__(16) half g_e1m[NPOS * HDIM];
__device__ __align__(16) half g_e2h[NPOS * HDIM];
__device__ __align__(16) half g_e2m[NPOS * HDIM];
// encoder fp16 two-split packed weights
__device__ __align__(16) half g_w1eh[HDIM * EDIM * 3];
__device__ __align__(16) half g_w1em[HDIM * EDIM * 3];
__device__ __align__(16) half g_w2eh[HDIM * HDIM * 3];
__device__ __align__(16) half g_w2em[HDIM * HDIM * 3];
__device__ __align__(16) half g_w3eh[DDIM * HDIM];
__device__ __align__(16) half g_w3em[DDIM * HDIM];
// decoder bf16 hi/lo split activations
__device__ __align__(16) bf16 g_zqhi[NPOS * DDIM];
__device__ __align__(16) bf16 g_zqlo[NPOS * DDIM];
__device__ __align__(16) bf16 g_d1hi[NPOS * HDIM];
__device__ __align__(16) bf16 g_d1lo[NPOS * HDIM];
__device__ __align__(16) bf16 g_d2hi[NPOS * HDIM];
__device__ __align__(16) bf16 g_d2lo[NPOS * HDIM];
__device__ __align__(16) bf16 g_ahi[NPOS * EDIM];
__device__ __align__(16) bf16 g_alo[NPOS * EDIM];
// decoder bf16 hi/lo split packed weights
__device__ __align__(16) bf16 g_w1hi[HDIM * DDIM];
__device__ __align__(16) bf16 g_w1lo[HDIM * DDIM];
__device__ __align__(16) bf16 g_w2hi[HDIM * HDIM * 3];
__device__ __align__(16) bf16 g_w2lo[HDIM * HDIM * 3];
__device__ __align__(16) bf16 g_w3hi[EDIM * HDIM];
__device__ __align__(16) bf16 g_w3lo[EDIM * HDIM];
__device__ __align__(16) bf16 g_bhi[VOCAB * EDIM];
__device__ __align__(16) bf16 g_blo[VOCAB * EDIM];

__device__ __forceinline__ uint32_t smem_to_u32(const void* smem_ptr) {
    uint32_t addr;
    asm("{ .reg .u64 tmp; cvta.to.shared.u64 tmp, %1; cvt.u32.u64 %0, tmp; }"
        : "=r"(addr) : "l"(smem_ptr));
    return addr;
}

__device__ __forceinline__ void cp_async16(uint32_t saddr, const void* gptr, int src_bytes) {
    asm volatile("cp.async.cg.shared.global [%0], [%1], 16, %2;"
                 :: "r"(saddr), "l"(gptr), "r"(src_bytes));
}

// fp16 two-split: x = h + (m/2048); m kept in normal fp16 range
__device__ __forceinline__ void split2h(float x, half& h, half& m) {
    h = __float2half_rn(x);
    m = __float2half_rn((x - __half2float(h)) * LO_SCALE);
}

// ---------------- embedding lookup with fused fp16 two-split ------------------
__global__ void embed_split2h(const int* __restrict__ x,
                              const float* __restrict__ tok,
                              half* __restrict__ H, half* __restrict__ M)
{
    int idx = blockIdx.x * blockDim.x + threadIdx.x;   // NPOS*32 float4s
    int n = idx >> 5;
    int j = idx & 31;
    int t = x[n];
    float4 v = reinterpret_cast<const float4*>(tok)[t * 32 + j];
    half h0,m0,h1,m1,h2,m2,h3,m3;
    split2h(v.x,h0,m0); split2h(v.y,h1,m1);
    split2h(v.z,h2,m2); split2h(v.w,h3,m3);
    __half2 p;
    p.x=h0; p.y=h1; reinterpret_cast<__half2*>(H)[n*64+j*2+0]=p;
    p.x=h2; p.y=h3; reinterpret_cast<__half2*>(H)[n*64+j*2+1]=p;
    p.x=m0; p.y=m1; reinterpret_cast<__half2*>(M)[n*64+j*2+0]=p;
    p.x=m2; p.y=m3; reinterpret_cast<__half2*>(M)[n*64+j*2+1]=p;
}

// ---------------- weight pack + splits ----------------------------------------
template<int CIN, int KW, int COUT>
__global__ void pack_split(const float* __restrict__ W,
                           bf16* __restrict__ Hi, bf16* __restrict__ Lo)
{
    int idx = blockIdx.x * blockDim.x + threadIdx.x;
    if (idx >= COUT * KW * CIN) return;
    int o   = idx / (KW * CIN);
    int rem = idx - o * (KW * CIN);
    int tap = rem / CIN;
    int ci  = rem - tap * CIN;
    float w = W[(size_t)o * CIN * KW + ci * KW + tap];
    bf16 h = __float2bfloat16(w);
    Hi[idx] = h;
    Lo[idx] = __float2bfloat16(w - __bfloat162float(h));
}

template<int CIN, int KW, int COUT>
__global__ void pack_split2h(const float* __restrict__ W,
                             half* __restrict__ H, half* __restrict__ M)
{
    int idx = blockIdx.x * blockDim.x + threadIdx.x;
    if (idx >= COUT * KW * CIN) return;
    int o   = idx / (KW * CIN);
    int rem = idx - o * (KW * CIN);
    int tap = rem / CIN;
    int ci  = rem - tap * CIN;
    float w = W[(size_t)o * CIN * KW + ci * KW + tap];
    half h, m;
    split2h(w, h, m);
    H[idx] = h; M[idx] = m;
}

// ---------------- codebook norms (no FMA: match sum(c*c)) --------------------
__global__ void cnorm_kernel(const float* __restrict__ CB, float* __restrict__ CN)
{
    int c = blockIdx.x * blockDim.x + threadIdx.x;
    if (c < KCODE) {
        float s = 0.f;
        for (int d = 0; d < DDIM; d++) {
            float v = CB[c * DDIM + d];
            s = __fadd_rn(s, __fmul_rn(v, v));
        }
        CN[c] = s;
    }
}

// ---------------- VQ: argmin over codes + commit-loss partials ---------------
__global__ void __launch_bounds__(256)
vq_kernel(const float* __restrict__ Z, const float* __restrict__ CB,
          const float* __restrict__ CN, int* __restrict__ Codes,
          float* __restrict__ CommitPart)
{
    __shared__ float Zt[64][66];
    __shared__ float Cs[64][66];
    __shared__ float znS[64];
    __shared__ float cvals[64];

    const int pm0 = blockIdx.x * 64;
    const int tid = threadIdx.x;
    const int tx = tid & 15, ty = tid >> 4;

#pragma unroll
    for (int i = 0; i < 16; i++) {
        int idx = tid + i * 256;
        int m = idx >> 6, d = idx & 63;
        Zt[d][m] = Z[(size_t)(pm0 + m) * 64 + d];
    }
    __syncthreads();

    if (tid < 64) {
        const int m = tid;
        float s = 0.f;
        for (int d = 0; d < 64; d++) {
            float v = Zt[d][m];
            s = __fadd_rn(s, __fmul_rn(v, v));
        }
        znS[m] = s;
    }
    __syncthreads();

    float zm[4];
#pragma unroll
    for (int i = 0; i < 4; i++) zm[i] = znS[ty * 4 + i];

    float minv[4]; int mini[4];
#pragma unroll
    for (int i = 0; i < 4; i++) { minv[i] = 3.4e38f; mini[i] = 0; }

    for (int c0 = 0; c0 < KCODE; c0 += 64) {
        __syncthreads();
#pragma unroll
        for (int i = 0; i < 16; i++) {
            int idx = tid + i * 256;
            int c = idx >> 6, d = idx & 63;
            Cs[d][c] = CB[(size_t)(c0 + c) * 64 + d];
        }
        __syncthreads();

        float dot[4][4];
#pragma unroll
        for (int i = 0; i < 4; i++)
#pragma unroll
            for (int j = 0; j < 4; j++) dot[i][j] = 0.f;
#pragma unroll
        for (int kk = 0; kk < 64; kk++) {
            float a[4], b[4];
#pragma unroll
            for (int i = 0; i < 4; i++) a[i] = Zt[kk][ty * 4 + i];
#pragma unroll
            for (int j = 0; j < 4; j++) b[j] = Cs[kk][tx * 4 + j];
#pragma unroll
            for (int i = 0; i < 4; i++)
#pragma unroll
                for (int j = 0; j < 4; j++)
                    dot[i][j] = fmaf(a[i], b[j], dot[i][j]);
        }
#pragma unroll
        for (int j = 0; j < 4; j++) {
            const int c = c0 + tx * 4 + j;
            const float cn = CN[c];
#pragma unroll
            for (int i = 0; i < 4; i++) {
                float t    = __fadd_rn(zm[i], -__fmul_rn(2.f, dot[i][j]));
                float dist = __fadd_rn(t, cn);
                if (dist < minv[i]) { minv[i] = dist; mini[i] = c; }
            }
        }
    }
    __syncthreads();

    float* redv = &Cs[0][0];
    int*   redi = reinterpret_cast<int*>(&Cs[0][0]) + 1024;
#pragma unroll
    for (int i = 0; i < 4; i++) {
        const int m = ty * 4 + i;
        redv[m * 16 + tx] = minv[i];
        redi[m * 16 + tx] = mini[i];
    }
    __syncthreads();
    if (tid < 64) {
        const int m = tid;
        float bv = redv[m * 16];
        int   bi = redi[m * 16];
        for (int t = 1; t < 16; t++) {
            float v = redv[m * 16 + t];
            int  ix = redi[m * 16 + t];
            if (v < bv || (v == bv && ix < bi)) { bv = v; bi = ix; }
        }
        Codes[pm0 + m] = bi;
        cvals[m] = bv;
    }
    __syncthreads();
    if (tid == 0) {
        float s = 0.f;
        for (int m = 0; m < 64; m++) s += cvals[m];
        CommitPart[blockIdx.x] = s;
    }
}

// ---------------- gather z_q with fused bf16 hi/lo split ----------------------
__global__ void gather_zq_split(const int* __restrict__ codes,
                                const float* __restrict__ CB,
                                bf16* __restrict__ Hi, bf16* __restrict__ Lo)
{
    int idx = blockIdx.x * blockDim.x + threadIdx.x;   // NPOS*16 float4s
    int n = idx >> 4;
    int j = idx & 15;
    float4 v = reinterpret_cast<const float4*>(CB)[codes[n] * 16 + j];
    bf16 h0 = __float2bfloat16(v.x), h1 = __float2bfloat16(v.y);
    bf16 h2 = __float2bfloat16(v.z), h3 = __float2bfloat16(v.w);
    __nv_bfloat162 hh0; hh0.x = h0; hh0.y = h1;
    __nv_bfloat162 hh1; hh1.x = h2; hh1.y = h3;
    __nv_bfloat162 ll0; ll0.x = __float2bfloat16(v.x - __bfloat162float(h0));
    ll0.y = __float2bfloat16(v.y - __bfloat162float(h1));
    __nv_bfloat162 ll1; ll1.x = __float2bfloat16(v.z - __bfloat162float(h2));
    ll1.y = __float2bfloat16(v.w - __bfloat162float(h3));
    reinterpret_cast<__nv_bfloat162*>(Hi)[n * 32 + j * 2 + 0] = hh0;
    reinterpret_cast<__nv_bfloat162*>(Hi)[n * 32 + j * 2 + 1] = hh1;
    reinterpret_cast<__nv_bfloat162*>(Lo)[n * 32 + j * 2 + 0] = ll0;
    reinterpret_cast<__nv_bfloat162*>(Lo)[n * 32 + j * 2 + 1] = ll1;
}

// ---------------- mma helpers -------------------------------------------------
__device__ __forceinline__ void ldsm_x4(uint32_t* r, uint32_t addr) {
    asm volatile("ldmatrix.sync.aligned.m8n8.x4.shared.b16 {%0,%1,%2,%3}, [%4];"
                 : "=r"(r[0]), "=r"(r[1]), "=r"(r[2]), "=r"(r[3]) : "r"(addr));
}
__device__ __forceinline__ void mma16816(float* d, const uint32_t* a,
                                         uint32_t b0, uint32_t b1) {
    asm volatile(
        "mma.sync.aligned.m16n8k16.row.col.f32.bf16.bf16.f32 "
        "{%0,%1,%2,%3}, {%4,%5,%6,%7}, {%8,%9}, {%0,%1,%2,%3};"
        : "+f"(d[0]), "+f"(d[1]), "+f"(d[2]), "+f"(d[3])
        : "r"(a[0]), "r"(a[1]), "r"(a[2]), "r"(a[3]), "r"(b0), "r"(b1));
}
__device__ __forceinline__ void mma16816h(float* d, const uint32_t* a,
                                          uint32_t b0, uint32_t b1) {
    asm volatile(
        "mma.sync.aligned.m16n8k16.row.col.f32.f16.f16.f32 "
        "{%0,%1,%2,%3}, {%4,%5,%6,%7}, {%8,%9}, {%0,%1,%2,%3};"
        : "+f"(d[0]), "+f"(d[1]), "+f"(d[2]), "+f"(d[3])
        : "r"(a[0]), "r"(a[1]), "r"(a[2]), "r"(a[3]), "r"(b0), "r"(b1));
}

// ---------------- generic bf16x3 (hi/lo) tensor conv, 16-warp version --------
#define TC_SMEM 196608

template<int CIN, int KW, int COUT, bool RELU, bool WF32, bool WSPLIT, bool LNF>
__global__ void __launch_bounds__(512)
tconv(const bf16* __restrict__ Ahi, const bf16* __restrict__ Alo,
      const bf16* __restrict__ Whi, const bf16* __restrict__ Wlo,
      const float* __restrict__ Bias,
      const float* __restrict__ LG, const float* __restrict__ LB,
      float* __restrict__ Yf, bf16* __restrict__ Yhi, bf16* __restrict__ Ylo)
{
    constexpr int KTOT = CIN * KW;
    constexpr int NCH  = KTOT / 64;
    constexpr int PAD  = (KW == 3) ? 1 : 0;

    extern __shared__ char smem[];
    const int tid = threadIdx.x;
    const int pm0 = blockIdx.x * 128;
    const int nv0 = blockIdx.y * 128;

    const int wid = tid >> 5, lane = tid & 31;
    const int wm = (wid >> 2) * 32;
    const int wn = (wid & 3) * 32;
    const int lr = lane & 7, lq = lane >> 3;

    float acc[2][4][4];
#pragma unroll
    for (int mi = 0; mi < 2; mi++)
#pragma unroll
        for (int ni = 0; ni < 4; ni++)
#pragma unroll
            for (int e = 0; e < 4; e++) acc[mi][ni][e] = 0.f;

    const uint4* A4h = reinterpret_cast<const uint4*>(Ahi);
    const uint4* A4l = reinterpret_cast<const uint4*>(Alo);
    const uint4* B4h = reinterpret_cast<const uint4*>(Whi);
    const uint4* B4l = reinterpret_cast<const uint4*>(Wlo);

    const uint32_t sb = smem_to_u32(smem);

    auto load_chunk = [&](int ch, int buf) {
        const uint32_t bo = (uint32_t)buf * 65536u;
        const int tap = (ch * 64) / CIN;
        const int ci0 = (ch * 64) % CIN;
#pragma unroll
        for (int i = 0; i < 2; i++) {
            int idx = tid + i * 512;
            int row = idx >> 3, c = idx & 7;
            int p = pm0 + row;
            bool ok = true;
            if (KW == 3) {
                int ls = (p & (LSEQ - 1)) + tap - PAD;
                ok = ((unsigned)ls < (unsigned)LSEQ);
            }
            size_t gi = ok ? ((size_t)(p + tap - PAD) * (CIN / 8) + (ci0 / 8) + c) : 0;
            int nb = ok ? 16 : 0;
            int pc = (c ^ row) & 7;
            uint32_t so = (uint32_t)(row * 128 + pc * 16);
            cp_async16(sb + bo + so,          A4h + gi, nb);
            cp_async16(sb + bo + 16384u + so, A4l + gi, nb);
        }
#pragma unroll
        for (int i = 0; i < 2; i++) {
            int idx = tid + i * 512;
            int row = idx >> 3, c = idx & 7;
            size_t gi = (size_t)(nv0 + row) * (KTOT / 8) + ch * 8 + c;
            int pc = (c ^ row) & 7;
            uint32_t so = (uint32_t)(row * 128 + pc * 16);
            cp_async16(sb + bo + 32768u + so, B4h + gi, 16);
            cp_async16(sb + bo + 49152u + so, B4l + gi, 16);
        }
        asm volatile("cp.async.commit_group;");
    };

    load_chunk(0, 0);
    if (1 < NCH) load_chunk(1, 1);

    for (int ch = 0; ch < NCH; ch++) {
        if (ch + 1 < NCH)
            asm volatile("cp.async.wait_group 1;");
        else
            asm volatile("cp.async.wait_group 0;");
        __syncthreads();
        if (ch + 2 < NCH) load_chunk(ch + 2, (ch + 2) % 3);

        const uint32_t bo = (uint32_t)(ch % 3) * 65536u;
        const uint32_t aHB = sb + bo;
        const uint32_t aLB = sb + bo + 16384u;
        const uint32_t bHB = sb + bo + 32768u;
        const uint32_t bLB = sb + bo + 49152u;
#pragma unroll
        for (int k16 = 0; k16 < 4; k16++) {
            const int kc0 = k16 * 2;
            uint32_t ah[2][4], al[2][4];
#pragma unroll
            for (int mi = 0; mi < 2; mi++) {
                int row = wm + mi * 16 + lr + (lq & 1) * 8;
                int kc  = kc0 + (lq >> 1);
                int pc  = (kc ^ row) & 7;
                ldsm_x4(ah[mi], aHB + row * 128 + pc * 16);
                ldsm_x4(al[mi], aLB + row * 128 + pc * 16);
            }
#pragma unroll
            for (int nc = 0; nc < 2; nc++) {
                uint32_t bh[4], bl[4];
                int row = wn + nc * 16 + lr + (lq >> 1) * 8;
                int kc  = kc0 + (lq & 1);
                int pc  = (kc ^ row) & 7;
                ldsm_x4(bh, bHB + row * 128 + pc * 16);
                ldsm_x4(bl, bLB + row * 128 + pc * 16);
                mma16816(acc[0][nc * 2 + 0], ah[0], bh[0], bh[1]);
                mma16816(acc[0][nc * 2 + 1], ah[0], bh[2], bh[3]);
                mma16816(acc[1][nc * 2 + 0], ah[1], bh[0], bh[1]);
                mma16816(acc[1][nc * 2 + 1], ah[1], bh[2], bh[3]);
                mma16816(acc[0][nc * 2 + 0], ah[0], bl[0], bl[1]);
                mma16816(acc[0][nc * 2 + 1], ah[0], bl[2], bl[3]);
                mma16816(acc[1][nc * 2 + 0], ah[1], bl[0], bl[1]);
                mma16816(acc[1][nc * 2 + 1], ah[1], bl[2], bl[3]);
                mma16816(acc[0][nc * 2 + 0], al[0], bh[0], bh[1]);
                mma16816(acc[0][nc * 2 + 1], al[0], bh[2], bh[3]);
                mma16816(acc[1][nc * 2 + 0], al[1], bh[0], bh[1]);
                mma16816(acc[1][nc * 2 + 1], al[1], bh[2], bh[3]);
            }
        }
    }

    const int gid = lane >> 2, tig = lane & 3;
#pragma unroll
    for (int mi = 0; mi < 2; mi++)
#pragma unroll
        for (int ni = 0; ni < 4; ni++) {
            const int n = nv0 + wn + ni * 8 + tig * 2;
            const float2 bv = *reinterpret_cast<const float2*>(Bias + n);
            acc[mi][ni][0] += bv.x;  acc[mi][ni][1] += bv.y;
            acc[mi][ni][2] += bv.x;  acc[mi][ni][3] += bv.y;
            if (RELU) {
#pragma unroll
                for (int e = 0; e < 4; e++) acc[mi][ni][e] = fmaxf(acc[mi][ni][e], 0.f);
            }
        }

    if (LNF) {
        float* red = reinterpret_cast<float*>(smem);
        __syncthreads();
        float ps[2][2];
#pragma unroll
        for (int mi = 0; mi < 2; mi++) { ps[mi][0] = 0.f; ps[mi][1] = 0.f; }
#pragma unroll
        for (int mi = 0; mi < 2; mi++)
#pragma unroll
            for (int ni = 0; ni < 4; ni++) {
                ps[mi][0] += acc[mi][ni][0] + acc[mi][ni][1];
                ps[mi][1] += acc[mi][ni][2] + acc[mi][ni][3];
            }
#pragma unroll
        for (int mi = 0; mi < 2; mi++)
#pragma unroll
            for (int h = 0; h < 2; h++) {
                ps[mi][h] += __shfl_xor_sync(0xffffffffu, ps[mi][h], 1);
                ps[mi][h] += __shfl_xor_sync(0xffffffffu, ps[mi][h], 2);
            }
        if (tig == 0) {
#pragma unroll
            for (int mi = 0; mi < 2; mi++)
#pragma unroll
                for (int h = 0; h < 2; h++) {
                    int row = wm + mi * 16 + gid + h * 8;
                    red[row * 4 + (wn >> 5)] = ps[mi][h];
                }
        }
        __syncthreads();
        float mu[2][2];
#pragma unroll
        for (int mi = 0; mi < 2; mi++)
#pragma unroll
            for (int h = 0; h < 2; h++) {
                int row = wm + mi * 16 + gid + h * 8;
                mu[mi][h] = (red[row * 4] + red[row * 4 + 1] +
                             red[row * 4 + 2] + red[row * 4 + 3]) * (1.f / 128.f);
            }
        float q[2][2];
#pragma unroll
        for (int mi = 0; mi < 2; mi++) { q[mi][0] = 0.f; q[mi][1] = 0.f; }
#pragma unroll
        for (int mi = 0; mi < 2; mi++)
#pragma unroll
            for (int ni = 0; ni < 4; ni++) {
                float d0 = acc[mi][ni][0] - mu[mi][0];
                float d1 = acc[mi][ni][1] - mu[mi][0];
                float d2 = acc[mi][ni][2] - mu[mi][1];
                float d3 = acc[mi][ni][3] - mu[mi][1];
                q[mi][0] += d0 * d0 + d1 * d1;
                q[mi][1] += d2 * d2 + d3 * d3;
            }
#pragma unroll
        for (int mi = 0; mi < 2; mi++)
#pragma unroll
            for (int h = 0; h < 2; h++) {
                q[mi][h] += __shfl_xor_sync(0xffffffffu, q[mi][h], 1);
                q[mi][h] += __shfl_xor_sync(0xffffffffu, q[mi][h], 2);
            }
        if (tig == 0) {
#pragma unroll
            for (int mi = 0; mi < 2; mi++)
#pragma unroll
                for (int h = 0; h < 2; h++) {
                    int row = wm + mi * 16 + gid + h * 8;
                    red[512 + row * 4 + (wn >> 5)] = q[mi][h];
                }
        }
        __syncthreads();
        float rs[2][2];
#pragma unroll
        for (int mi = 0; mi < 2; mi++)
#pragma unroll
            for (int h = 0; h < 2; h++) {
                int row = wm + mi * 16 + gid + h * 8;
                float var = (red[512 + row * 4] + red[512 + row * 4 + 1] +
                             red[512 + row * 4 + 2] + red[512 + row * 4 + 3]) * (1.f / 128.f);
                rs[mi][h] = rsqrtf(var + LN_EPS);
            }
#pragma unroll
        for (int mi = 0; mi < 2; mi++) {
            const int m0 = pm0 + wm + mi * 16 + gid;
#pragma unroll
            for (int ni = 0; ni < 4; ni++) {
                const int c = wn + ni * 8 + tig * 2;
                const float2 gv = *reinterpret_cast<const float2*>(LG + c);
                const float2 bb = *reinterpret_cast<const float2*>(LB + c);
                float y0 = (acc[mi][ni][0] - mu[mi][0]) * rs[mi][0] * gv.x + bb.x;
                float y1 = (acc[mi][ni][1] - mu[mi][0]) * rs[mi][0] * gv.y + bb.y;
                float y2 = (acc[mi][ni][2] - mu[mi][1]) * rs[mi][1] * gv.x + bb.x;
                float y3 = (acc[mi][ni][3] - mu[mi][1]) * rs[mi][1] * gv.y + bb.y;
                bf16 h0 = __float2bfloat16(y0), h1 = __float2bfloat16(y1);
                bf16 h2 = __float2bfloat16(y2), h3 = __float2bfloat16(y3);
                __nv_bfloat162 p0; p0.x = h0; p0.y = h1;
                __nv_bfloat162 p1; p1.x = h2; p1.y = h3;
                *reinterpret_cast<__nv_bfloat162*>(Yhi + (size_t)m0 * COUT + c)       = p0;
                *reinterpret_cast<__nv_bfloat162*>(Yhi + (size_t)(m0 + 8) * COUT + c) = p1;
                p0.x = __float2bfloat16(y0 - __bfloat162float(h0));
                p0.y = __float2bfloat16(y1 - __bfloat162float(h1));
                p1.x = __float2bfloat16(y2 - __bfloat162float(h2));
                p1.y = __float2bfloat16(y3 - __bfloat162float(h3));
                *reinterpret_cast<__nv_bfloat162*>(Ylo + (size_t)m0 * COUT + c)       = p0;
                *reinterpret_cast<__nv_bfloat162*>(Ylo + (size_t)(m0 + 8) * COUT + c) = p1;
            }
        }
        return;
    }

#pragma unroll
    for (int mi = 0; mi < 2; mi++) {
        const int m0 = pm0 + wm + mi * 16 + gid;
#pragma unroll
        for (int ni = 0; ni < 4; ni++) {
            const int n = nv0 + wn + ni * 8 + tig * 2;
            float v00 = acc[mi][ni][0];
            float v01 = acc[mi][ni][1];
            float v10 = acc[mi][ni][2];
            float v11 = acc[mi][ni][3];
            if (WF32) {
                float2 a0; a0.x = v00; a0.y = v01;
                float2 a1; a1.x = v10; a1.y = v11;
                *reinterpret_cast<float2*>(Yf + (size_t)m0 * COUT + n)       = a0;
                *reinterpret_cast<float2*>(Yf + (size_t)(m0 + 8) * COUT + n) = a1;
            }
            if (WSPLIT) {
                bf16 h00 = __float2bfloat16(v00), h01 = __float2bfloat16(v01);
                bf16 h10 = __float2bfloat16(v10), h11 = __float2bfloat16(v11);
                __nv_bfloat162 hh0; hh0.x = h00; hh0.y = h01;
                __nv_bfloat162 hh1; hh1.x = h10; hh1.y = h11;
                __nv_bfloat162 ll0;
                ll0.x = __float2bfloat16(v00 - __bfloat162float(h00));
                ll0.y = __float2bfloat16(v01 - __bfloat162float(h01));
                __nv_bfloat162 ll1;
                ll1.x = __float2bfloat16(v10 - __bfloat162float(h10));
                ll1.y = __float2bfloat16(v11 - __bfloat162float(h11));
                *reinterpret_cast<__nv_bfloat162*>(Yhi + (size_t)m0 * COUT + n)       = hh0;
                *reinterpret_cast<__nv_bfloat162*>(Yhi + (size_t)(m0 + 8) * COUT + n) = hh1;
                *reinterpret_cast<__nv_bfloat162*>(Ylo + (size_t)m0 * COUT + n)       = ll0;
                *reinterpret_cast<__nv_bfloat162*>(Ylo + (size_t)(m0 + 8) * COUT + n) = ll1;
            }
        }
    }
}

// ---------------- fp16 two-split tensor conv (encoder), 16-warp version ------
template<int CIN, int KW, int COUT, bool WF32>
__global__ void __launch_bounds__(512)
tconvh(const half* __restrict__ Ah, const half* __restrict__ Am,
       const half* __restrict__ Wh, const half* __restrict__ Wm,
       const float* __restrict__ Bias, float* __restrict__ Yf,
       half* __restrict__ Yh, half* __restrict__ Ym)
{
    constexpr int KTOT = CIN * KW;
    constexpr int NCH  = KTOT / 64;
    constexpr int PAD  = (KW == 3) ? 1 : 0;

    extern __shared__ char smem[];
    const int tid = threadIdx.x;
    const int pm0 = blockIdx.x * 128;
    const int nv0 = blockIdx.y * 128;

    const int wid = tid >> 5, lane = tid & 31;
    const int wm = (wid >> 2) * 32;
    const int wn = (wid & 3) * 32;
    const int lr = lane & 7, lq = lane >> 3;

    float acc1[2][4][4];
    float acc2[2][4][4];
#pragma unroll
    for (int mi = 0; mi < 2; mi++)
#pragma unroll
        for (int ni = 0; ni < 4; ni++)
#pragma unroll
            for (int e = 0; e < 4; e++) { acc1[mi][ni][e] = 0.f; acc2[mi][ni][e] = 0.f; }

    const uint4* A4h = reinterpret_cast<const uint4*>(Ah);
    const uint4* A4m = reinterpret_cast<const uint4*>(Am);
    const uint4* B4h = reinterpret_cast<const uint4*>(Wh);
    const uint4* B4m = reinterpret_cast<const uint4*>(Wm);

    const uint32_t sb = smem_to_u32(smem);

    auto load_chunk = [&](int ch, int buf) {
        const uint32_t bo = (uint32_t)buf * 65536u;
        const int tap = (ch * 64) / CIN;
        const int ci0 = (ch * 64) % CIN;
#pragma unroll
        for (int i = 0; i < 2; i++) {
            int idx = tid + i * 512;
            int row = idx >> 3, c = idx & 7;
            int p = pm0 + row;
            bool ok = true;
            if (KW == 3) {
                int ls = (p & (LSEQ - 1)) + tap - PAD;
                ok = ((unsigned)ls < (unsigned)LSEQ);
            }
            size_t gi = ok ? ((size_t)(p + tap - PAD) * (CIN / 8) + (ci0 / 8) + c) : 0;
            int nb = ok ? 16 : 0;
            int pc = (c ^ row) & 7;
            uint32_t so = (uint32_t)(row * 128 + pc * 16);
            cp_async16(sb + bo + so,          A4h + gi, nb);
            cp_async16(sb + bo + 16384u + so, A4m + gi, nb);
        }
#pragma unroll
        for (int i = 0; i < 2; i++) {
            int idx = tid + i * 512;
            int row = idx >> 3, c = idx & 7;
            size_t gi = (size_t)(nv0 + row) * (KTOT / 8) + ch * 8 + c;
            int pc = (c ^ row) & 7;
            uint32_t so = (uint32_t)(row * 128 + pc * 16);
            cp_async16(sb + bo + 32768u + so, B4h + gi, 16);
            cp_async16(sb + bo + 49152u + so, B4m + gi, 16);
        }
        asm volatile("cp.async.commit_group;");
    };

    load_chunk(0, 0);
    if (1 < NCH) load_chunk(1, 1);

    for (int ch = 0; ch < NCH; ch++) {
        if (ch + 1 < NCH)
            asm volatile("cp.async.wait_group 1;");
        else
            asm volatile("cp.async.wait_group 0;");
        __syncthreads();
        if (ch + 2 < NCH) load_chunk(ch + 2, (ch + 2) % 3);

        const uint32_t bo = (uint32_t)(ch % 3) * 65536u;
        const uint32_t aHB = sb + bo;
        const uint32_t aMB = sb + bo + 16384u;
        const uint32_t bHB = sb + bo + 32768u;
        const uint32_t bMB = sb + bo + 49152u;
#pragma unroll
        for (int k16 = 0; k16 < 4; k16++) {
            const int kc0 = k16 * 2;
            uint32_t ah[2][4], am[2][4];
#pragma unroll
            for (int mi = 0; mi < 2; mi++) {
                int row = wm + mi * 16 + lr + (lq & 1) * 8;
                int kc  = kc0 + (lq >> 1);
                int pc  = (kc ^ row) & 7;
                ldsm_x4(ah[mi], aHB + row * 128 + pc * 16);
                ldsm_x4(am[mi], aMB + row * 128 + pc * 16);
            }
#pragma unroll
            for (int nc = 0; nc < 2; nc++) {
                uint32_t bh[4], bm[4];
                int row = wn + nc * 16 + lr + (lq >> 1) * 8;
                int kc  = kc0 + (lq & 1);
                int pc  = (kc ^ row) & 7;
                ldsm_x4(bh, bHB + row * 128 + pc * 16);
                ldsm_x4(bm, bMB + row * 128 + pc * 16);
                mma16816h(acc1[0][nc * 2 + 0], ah[0], bh[0], bh[1]);
                mma16816h(acc1[0][nc * 2 + 1], ah[0], bh[2], bh[3]);
                mma16816h(acc1[1][nc * 2 + 0], ah[1], bh[0], bh[1]);
                mma16816h(acc1[1][nc * 2 + 1], ah[1], bh[2], bh[3]);
                mma16816h(acc2[0][nc * 2 + 0], ah[0], bm[0], bm[1]);
                mma16816h(acc2[0][nc * 2 + 1], ah[0], bm[2], bm[3]);
                mma16816h(acc2[1][nc * 2 + 0], ah[1], bm[0], bm[1]);
                mma16816h(acc2[1][nc * 2 + 1], ah[1], bm[2], bm[3]);
                mma16816h(acc2[0][nc * 2 + 0], am[0], bh[0], bh[1]);
                mma16816h(acc2[0][nc * 2 + 1], am[0], bh[2], bh[3]);
                mma16816h(acc2[1][nc * 2 + 0], am[1], bh[0], bh[1]);
                mma16816h(acc2[1][nc * 2 + 1], am[1], bh[2], bh[3]);
            }
        }
    }

    const int gid = lane >> 2, tig = lane & 3;
#pragma unroll
    for (int mi = 0; mi < 2; mi++) {
        const int m0 = pm0 + wm + mi * 16 + gid;
#pragma unroll
        for (int ni = 0; ni < 4; ni++) {
            const int n = nv0 + wn + ni * 8 + tig * 2;
            const float2 bv = *reinterpret_cast<const float2*>(Bias + n);
            float v00 = fmaxf(fmaf(acc2[mi][ni][0], LO_INV, acc1[mi][ni][0]) + bv.x, 0.f);
            float v01 = fmaxf(fmaf(acc2[mi][ni][1], LO_INV, acc1[mi][ni][1]) + bv.y, 0.f);
            float v10 = fmaxf(fmaf(acc2[mi][ni][2], LO_INV, acc1[mi][ni][2]) + bv.x, 0.f);
            float v11 = fmaxf(fmaf(acc2[mi][ni][3], LO_INV, acc1[mi][ni][3]) + bv.y, 0.f);
            if (WF32) {
                float2 a0; a0.x = v00; a0.y = v01;
                float2 a1; a1.x = v10; a1.y = v11;
                *reinterpret_cast<float2*>(Yf + (size_t)m0 * COUT + n)       = a0;
                *reinterpret_cast<float2*>(Yf + (size_t)(m0 + 8) * COUT + n) = a1;
            } else {
                half h00,m00,h01,m01,h10,m10,h11,m11;
                split2h(v00,h00,m00); split2h(v01,h01,m01);
                split2h(v10,h10,m10); split2h(v11,h11,m11);
                __half2 p0, p1;
                p0.x=h00; p0.y=h01; p1.x=h10; p1.y=h11;
                *reinterpret_cast<__half2*>(Yh + (size_t)m0 * COUT + n)       = p0;
                *reinterpret_cast<__half2*>(Yh + (size_t)(m0 + 8) * COUT + n) = p1;
                p0.x=m00; p0.y=m01; p1.x=m10; p1.y=m11;
                *reinterpret_cast<__half2*>(Ym + (size_t)m0 * COUT + n)       = p0;
                *reinterpret_cast<__half2*>(Ym + (size_t)(m0 + 8) * COUT + n) = p1;
            }
        }
    }
}

// ---------------- encoder head: fp16x3 GEMM [128x64, K=256] + fused LN(64) ---
__global__ void __launch_bounds__(256)
head_mma_ln(const half* __restrict__ Ah, const half* __restrict__ Am,
            const half* __restrict__ Wh, const half* __restrict__ Wm,
            const float* __restrict__ Bias,
            const float* __restrict__ G, const float* __restrict__ Bt,
            float* __restrict__ Z)
{
    extern __shared__ char smem[];
    const int tid = threadIdx.x;
    const int pm0 = blockIdx.x * 128;
    const uint32_t sb = smem_to_u32(smem);

    {
        const uint4* A4h = reinterpret_cast<const uint4*>(Ah);
        const uint4* A4m = reinterpret_cast<const uint4*>(Am);
#pragma unroll
        for (int i = 0; i < 16; i++) {
            int idx = tid + i * 256;
            int row = idx >> 5, c = idx & 31;
            int pc = (c & 24) | ((c ^ row) & 7);
            uint32_t so = (uint32_t)(row * 512 + pc * 16);
            size_t gi = (size_t)(pm0 + row) * 32 + c;
            cp_async16(sb + so,          A4h + gi, 16);
            cp_async16(sb + 65536u + so, A4m + gi, 16);
        }
        const uint4* B4h = reinterpret_cast<const uint4*>(Wh);
        const uint4* B4m = reinterpret_cast<const uint4*>(Wm);
#pragma unroll
        for (int i = 0; i < 8; i++) {
            int idx = tid + i * 256;
            int row = idx >> 5, c = idx & 31;
            int pc = (c & 24) | ((c ^ row) & 7);
            uint32_t so = (uint32_t)(row * 512 + pc * 16);
            size_t gi = (size_t)row * 32 + c;
            cp_async16(sb + 131072u + so, B4h + gi, 16);
            cp_async16(sb + 163840u + so, B4m + gi, 16);
        }
        asm volatile("cp.async.commit_group;");
    }

    const int wid = tid >> 5, lane = tid & 31;
    const int wm = wid * 16;
    const int lr = lane & 7, lq = lane >> 3;

    float acc1[8][4], acc2[8][4];
#pragma unroll
    for (int ni = 0; ni < 8; ni++)
#pragma unroll
        for (int e = 0; e < 4; e++) { acc1[ni][e] = 0.f; acc2[ni][e] = 0.f; }

    asm volatile("cp.async.wait_group 0;");
    __syncthreads();

#pragma unroll
    for (int k16 = 0; k16 < 16; k16++) {
        const int kc0 = k16 * 2;
        uint32_t ah[4], am[4];
        {
            int row = wm + lr + (lq & 1) * 8;
            int kc  = kc0 + (lq >> 1);
            int pc  = (kc & 24) | ((kc ^ row) & 7);
            ldsm_x4(ah, sb + row * 512 + pc * 16);
            ldsm_x4(am, sb + 65536u + row * 512 + pc * 16);
        }
#pragma unroll
        for (int nc = 0; nc < 4; nc++) {
            uint32_t bh[4], bm[4];
            int row = nc * 16 + lr + (lq >> 1) * 8;
            int kc  = kc0 + (lq & 1);
            int pc  = (kc & 24) | ((kc ^ row) & 7);
            ldsm_x4(bh, sb + 131072u + row * 512 + pc * 16);
            ldsm_x4(bm, sb + 163840u + row * 512 + pc * 16);
            mma16816h(acc1[nc * 2 + 0], ah, bh[0], bh[1]);
            mma16816h(acc1[nc * 2 + 1], ah, bh[2], bh[3]);
            mma16816h(acc2[nc * 2 + 0], ah, bm[0], bm[1]);
            mma16816h(acc2[nc * 2 + 1], ah, bm[2], bm[3]);
            mma16816h(acc2[nc * 2 + 0], am, bh[0], bh[1]);
            mma16816h(acc2[nc * 2 + 1], am, bh[2], bh[3]);
        }
    }

    const int gid = lane >> 2, tig = lane & 3;
    float v[8][4];
#pragma unroll
    for (int ni = 0; ni < 8; ni++) {
        const int n = ni * 8 + tig * 2;
        const float2 bv = *reinterpret_cast<const float2*>(Bias + n);
        v[ni][0] = fmaf(acc2[ni][0], LO_INV, acc1[ni][0]) + bv.x;
        v[ni][1] = fmaf(acc2[ni][1], LO_INV, acc1[ni][1]) + bv.y;
        v[ni][2] = fmaf(acc2[ni][2], LO_INV, acc1[ni][2]) + bv.x;
        v[ni][3] = fmaf(acc2[ni][3], LO_INV, acc1[ni][3]) + bv.y;
    }
    float s0 = 0.f, s1 = 0.f;
#pragma unroll
    for (int ni = 0; ni < 8; ni++) { s0 += v[ni][0] + v[ni][1]; s1 += v[ni][2] + v[ni][3]; }
    s0 += __shfl_xor_sync(0xffffffffu, s0, 1);  s0 += __shfl_xor_sync(0xffffffffu, s0, 2);
    s1 += __shfl_xor_sync(0xffffffffu, s1, 1);  s1 += __shfl_xor_sync(0xffffffffu, s1, 2);
    float mu0 = s0 * (1.f / 64.f), mu1 = s1 * (1.f / 64.f);
    float q0 = 0.f, q1 = 0.f;
#pragma unroll
    for (int ni = 0; ni < 8; ni++) {
        float d0 = v[ni][0] - mu0, d1 = v[ni][1] - mu0;
        float d2 = v[ni][2] - mu1, d3 = v[ni][3] - mu1;
        q0 += d0 * d0 + d1 * d1;
        q1 += d2 * d2 + d3 * d3;
    }
    q0 += __shfl_xor_sync(0xffffffffu, q0, 1);  q0 += __shfl_xor_sync(0xffffffffu, q0, 2);
    q1 += __shfl_xor_sync(0xffffffffu, q1, 1);  q1 += __shfl_xor_sync(0xffffffffu, q1, 2);
    float rs0 = rsqrtf(q0 * (1.f / 64.f) + LN_EPS);
    float rs1 = rsqrtf(q1 * (1.f / 64.f) + LN_EPS);

    const int r0 = pm0 + wm + gid, r1 = r0 + 8;
#pragma unroll
    for (int ni = 0; ni < 8; ni++) {
        const int c = ni * 8 + tig * 2;
        const float2 gv = *reinterpret_cast<const float2*>(G + c);
        const float2 bb = *reinterpret_cast<const float2*>(Bt + c);
        float2 o0, o1;
        o0.x = (v[ni][0] - mu0) * rs0 * gv.x + bb.x;
        o0.y = (v[ni][1] - mu0) * rs0 * gv.y + bb.y;
        o1.x = (v[ni][2] - mu1) * rs1 * gv.x + bb.x;
        o1.y = (v[ni][3] - mu1) * rs1 * gv.y + bb.y;
        *reinterpret_cast<float2*>(Z + (size_t)r0 * 64 + c) = o0;
        *reinterpret_cast<float2*>(Z + (size_t)r1 * 64 + c) = o1;
    }
}

// ---------------- wide full-K-resident bf16x3 logits GEMM, 16-warp -----------
#define LGW_SMEM 196608

__global__ void __launch_bounds__(512, 1)
logits_wide(const bf16* __restrict__ Ahi, const bf16* __restrict__ Alo,
            const bf16* __restrict__ Bhi, const bf16* __restrict__ Blo,
            const float* __restrict__ Bias, float* __restrict__ Out)
{
    extern __shared__ char smem[];
    const int tid = threadIdx.x;
    const int pm0 = blockIdx.x * 128;
    const int nv0 = blockIdx.y * 256;

    const uint32_t sb = smem_to_u32(smem);

    {
        const uint4* A4h = reinterpret_cast<const uint4*>(Ahi);
        const uint4* A4l = reinterpret_cast<const uint4*>(Alo);
#pragma unroll
        for (int i = 0; i < 4; i++) {
            int idx = tid + i * 512;
            int row = idx >> 4, c = idx & 15;
            int pc = (c & 8) | ((c ^ row) & 7);
            cp_async16(sb + (uint32_t)(row * 256 + pc * 16),
                       A4h + (size_t)(pm0 + row) * 16 + c, 16);
            cp_async16(sb + 32768u + (uint32_t)(row * 256 + pc * 16),
                       A4l + (size_t)(pm0 + row) * 16 + c, 16);
        }
        const uint4* B4h = reinterpret_cast<const uint4*>(Bhi);
        const uint4* B4l = reinterpret_cast<const uint4*>(Blo);
#pragma unroll
        for (int i = 0; i < 8; i++) {
            int idx = tid + i * 512;
            int row = idx >> 4, c = idx & 15;
            int pc = (c & 8) | ((c ^ row) & 7);
            cp_async16(sb + 65536u + (uint32_t)(row * 256 + pc * 16),
                       B4h + (size_t)(nv0 + row) * 16 + c, 16);
            cp_async16(sb + 131072u + (uint32_t)(row * 256 + pc * 16),
                       B4l + (size_t)(nv0 + row) * 16 + c, 16);
        }
        asm volatile("cp.async.commit_group;");
    }

    const int wid = tid >> 5, lane = tid & 31;
    const int wm = (wid >> 2) * 32;       // 0,32,64,96
    const int wn = (wid & 3) * 64;        // 0,64,128,192
    const int lr = lane & 7, lq = lane >> 3;

    float acc[2][8][4];
#pragma unroll
    for (int mi = 0; mi < 2; mi++)
#pragma unroll
        for (int ni = 0; ni < 8; ni++)
#pragma unroll
            for (int e = 0; e < 4; e++) acc[mi][ni][e] = 0.f;

    asm volatile("cp.async.wait_group 0;");
    __syncthreads();

#pragma unroll
    for (int k16 = 0; k16 < 8; k16++) {
        const int kc0 = k16 * 2;
        uint32_t ah[2][4], al[2][4];
#pragma unroll
        for (int mi = 0; mi < 2; mi++) {
            int row = wm + mi * 16 + lr + (lq & 1) * 8;
            int kc  = kc0 + (lq >> 1);
            int pc  = (kc & 8) | ((kc ^ row) & 7);
            ldsm_x4(ah[mi], sb + row * 256 + pc * 16);
            ldsm_x4(al[mi], sb + 32768u + row * 256 + pc * 16);
        }
#pragma unroll
        for (int nc = 0; nc < 4; nc++) {
            uint32_t bh[4], bl[4];
            int row = wn + nc * 16 + lr + (lq >> 1) * 8;
            int kc  = kc0 + (lq & 1);
            int pc  = (kc & 8) | ((kc ^ row) & 7);
            ldsm_x4(bh, sb + 65536u + row * 256 + pc * 16);
            ldsm_x4(bl, sb + 131072u + row * 256 + pc * 16);
            mma16816(acc[0][nc * 2 + 0], ah[0], bh[0], bh[1]);
            mma16816(acc[0][nc * 2 + 1], ah[0], bh[2], bh[3]);
            mma16816(acc[1][nc * 2 + 0], ah[1], bh[0], bh[1]);
            mma16816(acc[1][nc * 2 + 1], ah[1], bh[2], bh[3]);
            mma16816(acc[0][nc * 2 + 0], ah[0], bl[0], bl[1]);
            mma16816(acc[0][nc * 2 + 1], ah[0], bl[2], bl[3]);
            mma16816(acc[1][nc * 2 + 0], ah[1], bl[0], bl[1]);
            mma16816(acc[1][nc * 2 + 1], ah[1], bl[2], bl[3]);
            mma16816(acc[0][nc * 2 + 0], al[0], bh[0], bh[1]);
            mma16816(acc[0][nc * 2 + 1], al[0], bh[2], bh[3]);
            mma16816(acc[1][nc * 2 + 0], al[1], bh[0], bh[1]);
            mma16816(acc[1][nc * 2 + 1], al[1], bh[2], bh[3]);
        }
    }

    const int gid = lane >> 2, tig = lane & 3;
#pragma unroll
    for (int mi = 0; mi < 2; mi++) {
        const int m0 = pm0 + wm + mi * 16 + gid;
#pragma unroll
        for (int ni = 0; ni < 8; ni++) {
            const int n = nv0 + wn + ni * 8 + tig * 2;
            const float2 bv = *reinterpret_cast<const float2*>(Bias + n);
            float2 v0, v1;
            v0.x = acc[mi][ni][0] + bv.x;  v0.y = acc[mi][ni][1] + bv.y;
            v1.x = acc[mi][ni][2] + bv.x;  v1.y = acc[mi][ni][3] + bv.y;
            *reinterpret_cast<float2*>(Out + (size_t)m0 * VOCAB + n)       = v0;
            *reinterpret_cast<float2*>(Out + (size_t)(m0 + 8) * VOCAB + n) = v1;
        }
    }
}

// ---------------- tail: loss scalar + codes ----------------------------------
__global__ void commit_final(const float* __restrict__ Part, float* __restrict__ slot)
{
    if (threadIdx.x == 0 && blockIdx.x == 0) {
        float s = 0.f;
        for (int i = 0; i < NPOS / 64; i++) s += Part[i];
        *slot = 0.1f * s / ((float)NPOS * (float)DDIM);
    }
}

__global__ void write_codes(const int* __restrict__ codes, float* __restrict__ out)
{
    int n = blockIdx.x * blockDim.x + threadIdx.x;
    if (n < NPOS) out[n] = (float)codes[n];
}

// ---------------- launch ------------------------------------------------------
extern "C" void kernel_launch(void* const* d_in, const int* in_sizes, int n_in,
                              void* d_out, int out_size)
{
    (void)in_sizes; (void)n_in;
    const int*   x    = (const int*)  d_in[0];
    const float* tok  = (const float*)d_in[1];
    const float* ew1  = (const float*)d_in[2];
    const float* eb1  = (const float*)d_in[3];
    const float* ew2  = (const float*)d_in[4];
    const float* eb2  = (const float*)d_in[5];
    const float* ew3  = (const float*)d_in[6];
    const float* eb3  = (const float*)d_in[7];
    const float* elg  = (const float*)d_in[8];
    const float* elb  = (const float*)d_in[9];
    const float* cb   = (const float*)d_in[10];
    const float* dw1  = (const float*)d_in[11];
    const float* db1  = (const float*)d_in[12];
    const float* dw2  = (const float*)d_in[13];
    const float* db2  = (const float*)d_in[14];
    const float* dw3  = (const float*)d_in[15];
    const float* db3  = (const float*)d_in[16];
    const float* dlg  = (const float*)d_in[17];
    const float* dlb  = (const float*)d_in[18];
    const float* ow   = (const float*)d_in[19];
    const float* ob   = (const float*)d_in[20];
    float* out = (float*)d_out;

    float *z, *cn, *cp;
    int* codes;
    half *ebh,*ebm,*e1h,*e1m,*e2h,*e2m,*w1eh,*w1em,*w2eh,*w2em,*w3eh,*w3em;
    bf16 *zqhi,*zqlo,*d1hi,*d1lo,*d2hi,*d2lo,*ahi,*alo;
    bf16 *w1hi,*w1lo,*w2hi,*w2lo,*w3hi,*w3lo,*bhi,*blo;
    cudaGetSymbolAddress((void**)&z,     g_z);
    cudaGetSymbolAddress((void**)&codes, g_codes);
    cudaGetSymbolAddress((void**)&cn,    g_cnorm);
    cudaGetSymbolAddress((void**)&cp,    g_commit);
    cudaGetSymbolAddress((void**)&ebh,   g_ebh);
    cudaGetSymbolAddress((void**)&ebm,   g_ebm);
    cudaGetSymbolAddress((void**)&e1h,   g_e1h);
    cudaGetSymbolAddress((void**)&e1m,   g_e1m);
    cudaGetSymbolAddress((void**)&e2h,   g_e2h);
    cudaGetSymbolAddress((void**)&e2m,   g_e2m);
    cudaGetSymbolAddress((void**)&w1eh,  g_w1eh);
    cudaGetSymbolAddress((void**)&w1em,  g_w1em);
    cudaGetSymbolAddress((void**)&w2eh,  g_w2eh);
    cudaGetSymbolAddress((void**)&w2em,  g_w2em);
    cudaGetSymbolAddress((void**)&w3eh,  g_w3eh);
    cudaGetSymbolAddress((void**)&w3em,  g_w3em);
    cudaGetSymbolAddress((void**)&zqhi,  g_zqhi);
    cudaGetSymbolAddress((void**)&zqlo,  g_zqlo);
    cudaGetSymbolAddress((void**)&d1hi,  g_d1hi);
    cudaGetSymbolAddress((void**)&d1lo,  g_d1lo);
    cudaGetSymbolAddress((void**)&d2hi,  g_d2hi);
    cudaGetSymbolAddress((void**)&d2lo,  g_d2lo);
    cudaGetSymbolAddress((void**)&ahi,   g_ahi);
    cudaGetSymbolAddress((void**)&alo,   g_alo);
    cudaGetSymbolAddress((void**)&w1hi,  g_w1hi);
    cudaGetSymbolAddress((void**)&w1lo,  g_w1lo);
    cudaGetSymbolAddress((void**)&w2hi,  g_w2hi);
    cudaGetSymbolAddress((void**)&w2lo,  g_w2lo);
    cudaGetSymbolAddress((void**)&w3hi,  g_w3hi);
    cudaGetSymbolAddress((void**)&w3lo,  g_w3lo);
    cudaGetSymbolAddress((void**)&bhi,   g_bhi);
    cudaGetSymbolAddress((void**)&blo,   g_blo);

    cudaFuncSetAttribute((const void*)tconvh<128, 3, 256, false>,
                         cudaFuncAttributeMaxDynamicSharedMemorySize, TC_SMEM);
    cudaFuncSetAttribute((const void*)tconvh<256, 3, 256, false>,
                         cudaFuncAttributeMaxDynamicSharedMemorySize, TC_SMEM);
    cudaFuncSetAttribute((const void*)head_mma_ln,
                         cudaFuncAttributeMaxDynamicSharedMemorySize, TC_SMEM);
    cudaFuncSetAttribute((const void*)tconv< 64, 1, 256, true,  false, true,  false>,
                         cudaFuncAttributeMaxDynamicSharedMemorySize, TC_SMEM);
    cudaFuncSetAttribute((const void*)tconv<256, 3, 256, true,  false, true,  false>,
                         cudaFuncAttributeMaxDynamicSharedMemorySize, TC_SMEM);
    cudaFuncSetAttribute((const void*)tconv<256, 1, 128, true,  false, false, true >,
                         cudaFuncAttributeMaxDynamicSharedMemorySize, TC_SMEM);
    cudaFuncSetAttribute((const void*)logits_wide,
                         cudaFuncAttributeMaxDynamicSharedMemorySize, LGW_SMEM);

    // ---- side stream for independent prep work (fork-join, capture-safe) ----
    cudaStream_t s2;
    cudaStreamCreateWithFlags(&s2, cudaStreamNonBlocking);
    cudaEvent_t eFork, eEnc, eJoin, eFork2, eJoin2;
    cudaEventCreateWithFlags(&eFork,  cudaEventDisableTiming);
    cudaEventCreateWithFlags(&eEnc,   cudaEventDisableTiming);
    cudaEventCreateWithFlags(&eJoin,  cudaEventDisableTiming);
    cudaEventCreateWithFlags(&eFork2, cudaEventDisableTiming);
    cudaEventCreateWithFlags(&eJoin2, cudaEventDisableTiming);

    cudaEventRecord(eFork, 0);
    cudaStreamWaitEvent(s2, eFork, 0);
    // side stream FIRST: encoder weight packs (needed soonest)
    pack_split2h<128, 3, 256><<<(256*384)  / 256, 256, 0, s2>>>(ew1, w1eh, w1em);
    pack_split2h<256, 3, 256><<<(256*768)  / 256, 256, 0, s2>>>(ew2, w2eh, w2em);
    pack_split2h<256, 1,  64><<<(64*256)   / 256, 256, 0, s2>>>(ew3, w3eh, w3em);
    cudaEventRecord(eEnc, s2);
    // side stream SECOND: decoder/vocab packs + cnorm (needed much later)
    pack_split< 64, 1, 256>  <<<(256*64)   / 256, 256, 0, s2>>>(dw1, w1hi, w1lo);
    pack_split<256, 3, 256>  <<<(256*768)  / 256, 256, 0, s2>>>(dw2, w2hi, w2lo);
    pack_split<256, 1, 128>  <<<(128*256)  / 256, 256, 0, s2>>>(dw3, w3hi, w3lo);
    pack_split<128, 1, VOCAB><<<(VOCAB*128)/ 256, 256, 0, s2>>>(ow,  bhi,  blo);
    cnorm_kernel<<<1, 512, 0, s2>>>(cb, cn);
    cudaEventRecord(eJoin, s2);

    // ---- main stream: embedding (independent) then encoder ----
    embed_split2h<<<NPOS * 32 / 256, 256>>>(x, tok, ebh, ebm);
    cudaStreamWaitEvent(0, eEnc, 0);           // only encoder packs needed here
    tconvh<128, 3, 256, false><<<dim3(NPOS/128, 2), 512, TC_SMEM>>>(
        ebh, ebm, w1eh, w1em, eb1, nullptr, e1h, e1m);
    tconvh<256, 3, 256, false><<<dim3(NPOS/128, 2), 512, TC_SMEM>>>(
        e1h, e1m, w2eh, w2em, eb2, nullptr, e2h, e2m);
    head_mma_ln<<<NPOS/128, 256, TC_SMEM>>>(e2h, e2m, w3eh, w3em, eb3, elg, elb, z);

    // join remaining side work (cnorm + decoder packs) before first consumers
    cudaStreamWaitEvent(0, eJoin, 0);

    // ---- vector quantization ----
    vq_kernel<<<NPOS / 64, 256>>>(z, cb, cn, codes, cp);
    gather_zq_split<<<NPOS * 16 / 256, 256>>>(codes, cb, zqhi, zqlo);

    // ---- tail on side stream (depends only on VQ outputs) ----
    const long long NV = (long long)NPOS * VOCAB;   // 134217728
    cudaEventRecord(eFork2, 0);
    cudaStreamWaitEvent(s2, eFork2, 0);
    if ((long long)out_size >= NV + 1)
        commit_final<<<1, 32, 0, s2>>>(cp, out + NV);
    if ((long long)out_size >= NV + 1 + NPOS)
        write_codes<<<NPOS / 256, 256, 0, s2>>>(codes, out + NV + 1);
    cudaEventRecord(eJoin2, s2);

    // ---- decoder (bf16x3, 16-warp pipelined) ----
    tconv< 64, 1, 256, true,  false, true,  false><<<dim3(NPOS/128, 2), 512, TC_SMEM>>>(
        zqhi, zqlo, w1hi, w1lo, db1, nullptr, nullptr, nullptr, d1hi, d1lo);
    tconv<256, 3, 256, true,  false, true,  false><<<dim3(NPOS/128, 2), 512, TC_SMEM>>>(
        d1hi, d1lo, w2hi, w2lo, db2, nullptr, nullptr, nullptr, d2hi, d2lo);
    tconv<256, 1, 128, true,  false, false, true ><<<dim3(NPOS/128, 1), 512, TC_SMEM>>>(
        d2hi, d2lo, w3hi, w3lo, db3, dlg, dlb, nullptr, ahi, alo);

    // ---- vocab projection (wide full-K bf16x3, 16-warp) -> d_out ----
    logits_wide<<<dim3(NPOS/128, VOCAB/256), 512, LGW_SMEM>>>(
        ahi, alo, bhi, blo, ob, out);

    // join side-stream tail back into the main stream before capture ends
    cudaStreamWaitEvent(0, eJoin2, 0);

    cudaEventDestroy(eFork);
    cudaEventDestroy(eEnc);
    cudaEventDestroy(eJoin);
    cudaEventDestroy(eFork2);
    cudaEventDestroy(eJoin2);
    cudaStreamDestroy(s2);
}

// round 17
// speedup vs baseline: 1.1234x; 1.0054x over previous
#include <cuda_runtime.h>
#include <cuda_bf16.h>
#include <cuda_fp16.h>
#include <cstdint>

// Problem constants
#define NPOS   32768          // B*L = 8*4096
#define LSEQ   4096
#define EDIM   128
#define HDIM   256
#define DDIM   64
#define KCODE  512
#define VOCAB  4096
#define LN_EPS 1e-5f

typedef __nv_bfloat16 bf16;

#define LO_SCALE   2048.0f
#define LO_INV     (1.0f / 2048.0f)

// ---------------- scratch (static device globals; no allocation) -------------
__device__ float g_z  [NPOS * DDIM];    // z_e after LN
__device__ int   g_codes[NPOS];
__device__ float g_cnorm[KCODE];
__device__ float g_commit[NPOS / 64];
// encoder fp16 two-split activations (lo scaled by 2048)
__device__ __align__(16) half g_ebh[NPOS * EDIM];
__device__ __align__(16) half g_ebm[NPOS * EDIM];
__device__ __align__(16) half g_e1h[NPOS * HDIM];
__device__ __align__(16) half g_e1m[NPOS * HDIM];
__device__ __align__(16) half g_e2h[NPOS * HDIM];
__device__ __align__(16) half g_e2m[NPOS * HDIM];
// encoder fp16 two-split packed weights
__device__ __align__(16) half g_w1eh[HDIM * EDIM * 3];
__device__ __align__(16) half g_w1em[HDIM * EDIM * 3];
__device__ __align__(16) half g_w2eh[HDIM * HDIM * 3];
__device__ __align__(16) half g_w2em[HDIM * HDIM * 3];
__device__ __align__(16) half g_w3eh[DDIM * HDIM];
__device__ __align__(16) half g_w3em[DDIM * HDIM];
// codebook bf16 hi/lo split (decoder conv1 gathers through codes[])
__device__ __align__(16) bf16 g_cbhi[KCODE * DDIM];
__device__ __align__(16) bf16 g_cblo[KCODE * DDIM];
// decoder bf16 hi/lo split activations
__device__ __align__(16) bf16 g_d1hi[NPOS * HDIM];
__device__ __align__(16) bf16 g_d1lo[NPOS * HDIM];
__device__ __align__(16) bf16 g_d2hi[NPOS * HDIM];
__device__ __align__(16) bf16 g_d2lo[NPOS * HDIM];
__device__ __align__(16) bf16 g_ahi[NPOS * EDIM];
__device__ __align__(16) bf16 g_alo[NPOS * EDIM];
// decoder bf16 hi/lo split packed weights
__device__ __align__(16) bf16 g_w1hi[HDIM * DDIM];
__device__ __align__(16) bf16 g_w1lo[HDIM * DDIM];
__device__ __align__(16) bf16 g_w2hi[HDIM * HDIM * 3];
__device__ __align__(16) bf16 g_w2lo[HDIM * HDIM * 3];
__device__ __align__(16) bf16 g_w3hi[EDIM * HDIM];
__device__ __align__(16) bf16 g_w3lo[EDIM * HDIM];
__device__ __align__(16) bf16 g_bhi[VOCAB * EDIM];
__device__ __align__(16) bf16 g_blo[VOCAB * EDIM];

__device__ __forceinline__ uint32_t smem_to_u32(const void* smem_ptr) {
    uint32_t addr;
    asm("{ .reg .u64 tmp; cvta.to.shared.u64 tmp, %1; cvt.u32.u64 %0, tmp; }"
        : "=r"(addr) : "l"(smem_ptr));
    return addr;
}

__device__ __forceinline__ void cp_async16(uint32_t saddr, const void* gptr, int src_bytes) {
    asm volatile("cp.async.cg.shared.global [%0], [%1], 16, %2;"
                 :: "r"(saddr), "l"(gptr), "r"(src_bytes));
}

// fp16 two-split: x = h + (m/2048); m kept in normal fp16 range
__device__ __forceinline__ void split2h(float x, half& h, half& m) {
    h = __float2half_rn(x);
    m = __float2half_rn((x - __half2float(h)) * LO_SCALE);
}

// ---------------- embedding lookup with fused fp16 two-split ------------------
__global__ void embed_split2h(const int* __restrict__ x,
                              const float* __restrict__ tok,
                              half* __restrict__ H, half* __restrict__ M)
{
    int idx = blockIdx.x * blockDim.x + threadIdx.x;   // NPOS*32 float4s
    int n = idx >> 5;
    int j = idx & 31;
    int t = x[n];
    float4 v = reinterpret_cast<const float4*>(tok)[t * 32 + j];
    half h0,m0,h1,m1,h2,m2,h3,m3;
    split2h(v.x,h0,m0); split2h(v.y,h1,m1);
    split2h(v.z,h2,m2); split2h(v.w,h3,m3);
    __half2 p;
    p.x=h0; p.y=h1; reinterpret_cast<__half2*>(H)[n*64+j*2+0]=p;
    p.x=h2; p.y=h3; reinterpret_cast<__half2*>(H)[n*64+j*2+1]=p;
    p.x=m0; p.y=m1; reinterpret_cast<__half2*>(M)[n*64+j*2+0]=p;
    p.x=m2; p.y=m3; reinterpret_cast<__half2*>(M)[n*64+j*2+1]=p;
}

// ---------------- weight pack + splits ----------------------------------------
template<int CIN, int KW, int COUT>
__global__ void pack_split(const float* __restrict__ W,
                           bf16* __restrict__ Hi, bf16* __restrict__ Lo)
{
    int idx = blockIdx.x * blockDim.x + threadIdx.x;
    if (idx >= COUT * KW * CIN) return;
    int o   = idx / (KW * CIN);
    int rem = idx - o * (KW * CIN);
    int tap = rem / CIN;
    int ci  = rem - tap * CIN;
    float w = W[(size_t)o * CIN * KW + ci * KW + tap];
    bf16 h = __float2bfloat16(w);
    Hi[idx] = h;
    Lo[idx] = __float2bfloat16(w - __bfloat162float(h));
}

template<int CIN, int KW, int COUT>
__global__ void pack_split2h(const float* __restrict__ W,
                             half* __restrict__ H, half* __restrict__ M)
{
    int idx = blockIdx.x * blockDim.x + threadIdx.x;
    if (idx >= COUT * KW * CIN) return;
    int o   = idx / (KW * CIN);
    int rem = idx - o * (KW * CIN);
    int tap = rem / CIN;
    int ci  = rem - tap * CIN;
    float w = W[(size_t)o * CIN * KW + ci * KW + tap];
    half h, m;
    split2h(w, h, m);
    H[idx] = h; M[idx] = m;
}

// ---------------- codebook norms (no FMA: match sum(c*c)) --------------------
__global__ void cnorm_kernel(const float* __restrict__ CB, float* __restrict__ CN)
{
    int c = blockIdx.x * blockDim.x + threadIdx.x;
    if (c < KCODE) {
        float s = 0.f;
        for (int d = 0; d < DDIM; d++) {
            float v = CB[c * DDIM + d];
            s = __fadd_rn(s, __fmul_rn(v, v));
        }
        CN[c] = s;
    }
}

// ---------------- VQ: argmin over codes + commit-loss partials ---------------
__global__ void __launch_bounds__(256)
vq_kernel(const float* __restrict__ Z, const float* __restrict__ CB,
          const float* __restrict__ CN, int* __restrict__ Codes,
          float* __restrict__ CommitPart)
{
    __shared__ float Zt[64][66];
    __shared__ float Cs[64][66];
    __shared__ float znS[64];
    __shared__ float cvals[64];

    const int pm0 = blockIdx.x * 64;
    const int tid = threadIdx.x;
    const int tx = tid & 15, ty = tid >> 4;

#pragma unroll
    for (int i = 0; i < 16; i++) {
        int idx = tid + i * 256;
        int m = idx >> 6, d = idx & 63;
        Zt[d][m] = Z[(size_t)(pm0 + m) * 64 + d];
    }
    __syncthreads();

    if (tid < 64) {
        const int m = tid;
        float s = 0.f;
        for (int d = 0; d < 64; d++) {
            float v = Zt[d][m];
            s = __fadd_rn(s, __fmul_rn(v, v));
        }
        znS[m] = s;
    }
    __syncthreads();

    float zm[4];
#pragma unroll
    for (int i = 0; i < 4; i++) zm[i] = znS[ty * 4 + i];

    float minv[4]; int mini[4];
#pragma unroll
    for (int i = 0; i < 4; i++) { minv[i] = 3.4e38f; mini[i] = 0; }

    for (int c0 = 0; c0 < KCODE; c0 += 64) {
        __syncthreads();
#pragma unroll
        for (int i = 0; i < 16; i++) {
            int idx = tid + i * 256;
            int c = idx >> 6, d = idx & 63;
            Cs[d][c] = CB[(size_t)(c0 + c) * 64 + d];
        }
        __syncthreads();

        float dot[4][4];
#pragma unroll
        for (int i = 0; i < 4; i++)
#pragma unroll
            for (int j = 0; j < 4; j++) dot[i][j] = 0.f;
#pragma unroll
        for (int kk = 0; kk < 64; kk++) {
            float a[4], b[4];
#pragma unroll
            for (int i = 0; i < 4; i++) a[i] = Zt[kk][ty * 4 + i];
#pragma unroll
            for (int j = 0; j < 4; j++) b[j] = Cs[kk][tx * 4 + j];
#pragma unroll
            for (int i = 0; i < 4; i++)
#pragma unroll
                for (int j = 0; j < 4; j++)
                    dot[i][j] = fmaf(a[i], b[j], dot[i][j]);
        }
#pragma unroll
        for (int j = 0; j < 4; j++) {
            const int c = c0 + tx * 4 + j;
            const float cn = CN[c];
#pragma unroll
            for (int i = 0; i < 4; i++) {
                float t    = __fadd_rn(zm[i], -__fmul_rn(2.f, dot[i][j]));
                float dist = __fadd_rn(t, cn);
                if (dist < minv[i]) { minv[i] = dist; mini[i] = c; }
            }
        }
    }
    __syncthreads();

    float* redv = &Cs[0][0];
    int*   redi = reinterpret_cast<int*>(&Cs[0][0]) + 1024;
#pragma unroll
    for (int i = 0; i < 4; i++) {
        const int m = ty * 4 + i;
        redv[m * 16 + tx] = minv[i];
        redi[m * 16 + tx] = mini[i];
    }
    __syncthreads();
    if (tid < 64) {
        const int m = tid;
        float bv = redv[m * 16];
        int   bi = redi[m * 16];
        for (int t = 1; t < 16; t++) {
            float v = redv[m * 16 + t];
            int  ix = redi[m * 16 + t];
            if (v < bv || (v == bv && ix < bi)) { bv = v; bi = ix; }
        }
        Codes[pm0 + m] = bi;
        cvals[m] = bv;
    }
    __syncthreads();
    if (tid == 0) {
        float s = 0.f;
        for (int m = 0; m < 64; m++) s += cvals[m];
        CommitPart[blockIdx.x] = s;
    }
}

// ---------------- mma helpers -------------------------------------------------
__device__ __forceinline__ void ldsm_x4(uint32_t* r, uint32_t addr) {
    asm volatile("ldmatrix.sync.aligned.m8n8.x4.shared.b16 {%0,%1,%2,%3}, [%4];"
                 : "=r"(r[0]), "=r"(r[1]), "=r"(r[2]), "=r"(r[3]) : "r"(addr));
}
__device__ __forceinline__ void mma16816(float* d, const uint32_t* a,
                                         uint32_t b0, uint32_t b1) {
    asm volatile(
        "mma.sync.aligned.m16n8k16.row.col.f32.bf16.bf16.f32 "
        "{%0,%1,%2,%3}, {%4,%5,%6,%7}, {%8,%9}, {%0,%1,%2,%3};"
        : "+f"(d[0]), "+f"(d[1]), "+f"(d[2]), "+f"(d[3])
        : "r"(a[0]), "r"(a[1]), "r"(a[2]), "r"(a[3]), "r"(b0), "r"(b1));
}
__device__ __forceinline__ void mma16816h(float* d, const uint32_t* a,
                                          uint32_t b0, uint32_t b1) {
    asm volatile(
        "mma.sync.aligned.m16n8k16.row.col.f32.f16.f16.f32 "
        "{%0,%1,%2,%3}, {%4,%5,%6,%7}, {%8,%9}, {%0,%1,%2,%3};"
        : "+f"(d[0]), "+f"(d[1]), "+f"(d[2]), "+f"(d[3])
        : "r"(a[0]), "r"(a[1]), "r"(a[2]), "r"(a[3]), "r"(b0), "r"(b1));
}

// ---------------- generic bf16x3 (hi/lo) tensor conv, 16-warp version --------
// GATHER: A row p is fetched from Ahi[Codes[p]] (codebook gather, KW must be 1).
#define TC_SMEM 196608

template<int CIN, int KW, int COUT, bool RELU, bool WF32, bool WSPLIT, bool LNF, bool GATHER>
__global__ void __launch_bounds__(512)
tconv(const bf16* __restrict__ Ahi, const bf16* __restrict__ Alo,
      const bf16* __restrict__ Whi, const bf16* __restrict__ Wlo,
      const float* __restrict__ Bias,
      const float* __restrict__ LG, const float* __restrict__ LB,
      float* __restrict__ Yf, bf16* __restrict__ Yhi, bf16* __restrict__ Ylo,
      const int* __restrict__ GCodes)
{
    constexpr int KTOT = CIN * KW;
    constexpr int NCH  = KTOT / 64;
    constexpr int PAD  = (KW == 3) ? 1 : 0;

    extern __shared__ char smem[];
    const int tid = threadIdx.x;
    const int pm0 = blockIdx.x * 128;
    const int nv0 = blockIdx.y * 128;

    const int wid = tid >> 5, lane = tid & 31;
    const int wm = (wid >> 2) * 32;
    const int wn = (wid & 3) * 32;
    const int lr = lane & 7, lq = lane >> 3;

    float acc[2][4][4];
#pragma unroll
    for (int mi = 0; mi < 2; mi++)
#pragma unroll
        for (int ni = 0; ni < 4; ni++)
#pragma unroll
            for (int e = 0; e < 4; e++) acc[mi][ni][e] = 0.f;

    const uint4* A4h = reinterpret_cast<const uint4*>(Ahi);
    const uint4* A4l = reinterpret_cast<const uint4*>(Alo);
    const uint4* B4h = reinterpret_cast<const uint4*>(Whi);
    const uint4* B4l = reinterpret_cast<const uint4*>(Wlo);

    const uint32_t sb = smem_to_u32(smem);

    auto load_chunk = [&](int ch, int buf) {
        const uint32_t bo = (uint32_t)buf * 65536u;
        const int tap = (ch * 64) / CIN;
        const int ci0 = (ch * 64) % CIN;
#pragma unroll
        for (int i = 0; i < 2; i++) {
            int idx = tid + i * 512;
            int row = idx >> 3, c = idx & 7;
            int p = pm0 + row;
            bool ok = true;
            size_t gi;
            if (GATHER) {
                int t = GCodes[p];
                gi = (size_t)t * (CIN / 8) + (ci0 / 8) + c;
            } else {
                if (KW == 3) {
                    int ls = (p & (LSEQ - 1)) + tap - PAD;
                    ok = ((unsigned)ls < (unsigned)LSEQ);
                }
                gi = ok ? ((size_t)(p + tap - PAD) * (CIN / 8) + (ci0 / 8) + c) : 0;
            }
            int nb = ok ? 16 : 0;
            int pc = (c ^ row) & 7;
            uint32_t so = (uint32_t)(row * 128 + pc * 16);
            cp_async16(sb + bo + so,          A4h + gi, nb);
            cp_async16(sb + bo + 16384u + so, A4l + gi, nb);
        }
#pragma unroll
        for (int i = 0; i < 2; i++) {
            int idx = tid + i * 512;
            int row = idx >> 3, c = idx & 7;
            size_t gi = (size_t)(nv0 + row) * (KTOT / 8) + ch * 8 + c;
            int pc = (c ^ row) & 7;
            uint32_t so = (uint32_t)(row * 128 + pc * 16);
            cp_async16(sb + bo + 32768u + so, B4h + gi, 16);
            cp_async16(sb + bo + 49152u + so, B4l + gi, 16);
        }
        asm volatile("cp.async.commit_group;");
    };

    load_chunk(0, 0);
    if (1 < NCH) load_chunk(1, 1);

    for (int ch = 0; ch < NCH; ch++) {
        if (ch + 1 < NCH)
            asm volatile("cp.async.wait_group 1;");
        else
            asm volatile("cp.async.wait_group 0;");
        __syncthreads();
        if (ch + 2 < NCH) load_chunk(ch + 2, (ch + 2) % 3);

        const uint32_t bo = (uint32_t)(ch % 3) * 65536u;
        const uint32_t aHB = sb + bo;
        const uint32_t aLB = sb + bo + 16384u;
        const uint32_t bHB = sb + bo + 32768u;
        const uint32_t bLB = sb + bo + 49152u;
#pragma unroll
        for (int k16 = 0; k16 < 4; k16++) {
            const int kc0 = k16 * 2;
            uint32_t ah[2][4], al[2][4];
#pragma unroll
            for (int mi = 0; mi < 2; mi++) {
                int row = wm + mi * 16 + lr + (lq & 1) * 8;
                int kc  = kc0 + (lq >> 1);
                int pc  = (kc ^ row) & 7;
                ldsm_x4(ah[mi], aHB + row * 128 + pc * 16);
                ldsm_x4(al[mi], aLB + row * 128 + pc * 16);
            }
#pragma unroll
            for (int nc = 0; nc < 2; nc++) {
                uint32_t bh[4], bl[4];
                int row = wn + nc * 16 + lr + (lq >> 1) * 8;
                int kc  = kc0 + (lq & 1);
                int pc  = (kc ^ row) & 7;
                ldsm_x4(bh, bHB + row * 128 + pc * 16);
                ldsm_x4(bl, bLB + row * 128 + pc * 16);
                mma16816(acc[0][nc * 2 + 0], ah[0], bh[0], bh[1]);
                mma16816(acc[0][nc * 2 + 1], ah[0], bh[2], bh[3]);
                mma16816(acc[1][nc * 2 + 0], ah[1], bh[0], bh[1]);
                mma16816(acc[1][nc * 2 + 1], ah[1], bh[2], bh[3]);
                mma16816(acc[0][nc * 2 + 0], ah[0], bl[0], bl[1]);
                mma16816(acc[0][nc * 2 + 1], ah[0], bl[2], bl[3]);
                mma16816(acc[1][nc * 2 + 0], ah[1], bl[0], bl[1]);
                mma16816(acc[1][nc * 2 + 1], ah[1], bl[2], bl[3]);
                mma16816(acc[0][nc * 2 + 0], al[0], bh[0], bh[1]);
                mma16816(acc[0][nc * 2 + 1], al[0], bh[2], bh[3]);
                mma16816(acc[1][nc * 2 + 0], al[1], bh[0], bh[1]);
                mma16816(acc[1][nc * 2 + 1], al[1], bh[2], bh[3]);
            }
        }
    }

    const int gid = lane >> 2, tig = lane & 3;
#pragma unroll
    for (int mi = 0; mi < 2; mi++)
#pragma unroll
        for (int ni = 0; ni < 4; ni++) {
            const int n = nv0 + wn + ni * 8 + tig * 2;
            const float2 bv = *reinterpret_cast<const float2*>(Bias + n);
            acc[mi][ni][0] += bv.x;  acc[mi][ni][1] += bv.y;
            acc[mi][ni][2] += bv.x;  acc[mi][ni][3] += bv.y;
            if (RELU) {
#pragma unroll
                for (int e = 0; e < 4; e++) acc[mi][ni][e] = fmaxf(acc[mi][ni][e], 0.f);
            }
        }

    if (LNF) {
        float* red = reinterpret_cast<float*>(smem);
        __syncthreads();
        float ps[2][2];
#pragma unroll
        for (int mi = 0; mi < 2; mi++) { ps[mi][0] = 0.f; ps[mi][1] = 0.f; }
#pragma unroll
        for (int mi = 0; mi < 2; mi++)
#pragma unroll
            for (int ni = 0; ni < 4; ni++) {
                ps[mi][0] += acc[mi][ni][0] + acc[mi][ni][1];
                ps[mi][1] += acc[mi][ni][2] + acc[mi][ni][3];
            }
#pragma unroll
        for (int mi = 0; mi < 2; mi++)
#pragma unroll
            for (int h = 0; h < 2; h++) {
                ps[mi][h] += __shfl_xor_sync(0xffffffffu, ps[mi][h], 1);
                ps[mi][h] += __shfl_xor_sync(0xffffffffu, ps[mi][h], 2);
            }
        if (tig == 0) {
#pragma unroll
            for (int mi = 0; mi < 2; mi++)
#pragma unroll
                for (int h = 0; h < 2; h++) {
                    int row = wm + mi * 16 + gid + h * 8;
                    red[row * 4 + (wn >> 5)] = ps[mi][h];
                }
        }
        __syncthreads();
        float mu[2][2];
#pragma unroll
        for (int mi = 0; mi < 2; mi++)
#pragma unroll
            for (int h = 0; h < 2; h++) {
                int row = wm + mi * 16 + gid + h * 8;
                mu[mi][h] = (red[row * 4] + red[row * 4 + 1] +
                             red[row * 4 + 2] + red[row * 4 + 3]) * (1.f / 128.f);
            }
        float q[2][2];
#pragma unroll
        for (int mi = 0; mi < 2; mi++) { q[mi][0] = 0.f; q[mi][1] = 0.f; }
#pragma unroll
        for (int mi = 0; mi < 2; mi++)
#pragma unroll
            for (int ni = 0; ni < 4; ni++) {
                float d0 = acc[mi][ni][0] - mu[mi][0];
                float d1 = acc[mi][ni][1] - mu[mi][0];
                float d2 = acc[mi][ni][2] - mu[mi][1];
                float d3 = acc[mi][ni][3] - mu[mi][1];
                q[mi][0] += d0 * d0 + d1 * d1;
                q[mi][1] += d2 * d2 + d3 * d3;
            }
#pragma unroll
        for (int mi = 0; mi < 2; mi++)
#pragma unroll
            for (int h = 0; h < 2; h++) {
                q[mi][h] += __shfl_xor_sync(0xffffffffu, q[mi][h], 1);
                q[mi][h] += __shfl_xor_sync(0xffffffffu, q[mi][h], 2);
            }
        if (tig == 0) {
#pragma unroll
            for (int mi = 0; mi < 2; mi++)
#pragma unroll
                for (int h = 0; h < 2; h++) {
                    int row = wm + mi * 16 + gid + h * 8;
                    red[512 + row * 4 + (wn >> 5)] = q[mi][h];
                }
        }
        __syncthreads();
        float rs[2][2];
#pragma unroll
        for (int mi = 0; mi < 2; mi++)
#pragma unroll
            for (int h = 0; h < 2; h++) {
                int row = wm + mi * 16 + gid + h * 8;
                float var = (red[512 + row * 4] + red[512 + row * 4 + 1] +
                             red[512 + row * 4 + 2] + red[512 + row * 4 + 3]) * (1.f / 128.f);
                rs[mi][h] = rsqrtf(var + LN_EPS);
            }
#pragma unroll
        for (int mi = 0; mi < 2; mi++) {
            const int m0 = pm0 + wm + mi * 16 + gid;
#pragma unroll
            for (int ni = 0; ni < 4; ni++) {
                const int c = wn + ni * 8 + tig * 2;
                const float2 gv = *reinterpret_cast<const float2*>(LG + c);
                const float2 bb = *reinterpret_cast<const float2*>(LB + c);
                float y0 = (acc[mi][ni][0] - mu[mi][0]) * rs[mi][0] * gv.x + bb.x;
                float y1 = (acc[mi][ni][1] - mu[mi][0]) * rs[mi][0] * gv.y + bb.y;
                float y2 = (acc[mi][ni][2] - mu[mi][1]) * rs[mi][1] * gv.x + bb.x;
                float y3 = (acc[mi][ni][3] - mu[mi][1]) * rs[mi][1] * gv.y + bb.y;
                bf16 h0 = __float2bfloat16(y0), h1 = __float2bfloat16(y1);
                bf16 h2 = __float2bfloat16(y2), h3 = __float2bfloat16(y3);
                __nv_bfloat162 p0; p0.x = h0; p0.y = h1;
                __nv_bfloat162 p1; p1.x = h2; p1.y = h3;
                *reinterpret_cast<__nv_bfloat162*>(Yhi + (size_t)m0 * COUT + c)       = p0;
                *reinterpret_cast<__nv_bfloat162*>(Yhi + (size_t)(m0 + 8) * COUT + c) = p1;
                p0.x = __float2bfloat16(y0 - __bfloat162float(h0));
                p0.y = __float2bfloat16(y1 - __bfloat162float(h1));
                p1.x = __float2bfloat16(y2 - __bfloat162float(h2));
                p1.y = __float2bfloat16(y3 - __bfloat162float(h3));
                *reinterpret_cast<__nv_bfloat162*>(Ylo + (size_t)m0 * COUT + c)       = p0;
                *reinterpret_cast<__nv_bfloat162*>(Ylo + (size_t)(m0 + 8) * COUT + c) = p1;
            }
        }
        return;
    }

#pragma unroll
    for (int mi = 0; mi < 2; mi++) {
        const int m0 = pm0 + wm + mi * 16 + gid;
#pragma unroll
        for (int ni = 0; ni < 4; ni++) {
            const int n = nv0 + wn + ni * 8 + tig * 2;
            float v00 = acc[mi][ni][0];
            float v01 = acc[mi][ni][1];
            float v10 = acc[mi][ni][2];
            float v11 = acc[mi][ni][3];
            if (WF32) {
                float2 a0; a0.x = v00; a0.y = v01;
                float2 a1; a1.x = v10; a1.y = v11;
                *reinterpret_cast<float2*>(Yf + (size_t)m0 * COUT + n)       = a0;
                *reinterpret_cast<float2*>(Yf + (size_t)(m0 + 8) * COUT + n) = a1;
            }
            if (WSPLIT) {
                bf16 h00 = __float2bfloat16(v00), h01 = __float2bfloat16(v01);
                bf16 h10 = __float2bfloat16(v10), h11 = __float2bfloat16(v11);
                __nv_bfloat162 hh0; hh0.x = h00; hh0.y = h01;
                __nv_bfloat162 hh1; hh1.x = h10; hh1.y = h11;
                __nv_bfloat162 ll0;
                ll0.x = __float2bfloat16(v00 - __bfloat162float(h00));
                ll0.y = __float2bfloat16(v01 - __bfloat162float(h01));
                __nv_bfloat162 ll1;
                ll1.x = __float2bfloat16(v10 - __bfloat162float(h10));
                ll1.y = __float2bfloat16(v11 - __bfloat162float(h11));
                *reinterpret_cast<__nv_bfloat162*>(Yhi + (size_t)m0 * COUT + n)       = hh0;
                *reinterpret_cast<__nv_bfloat162*>(Yhi + (size_t)(m0 + 8) * COUT + n) = hh1;
                *reinterpret_cast<__nv_bfloat162*>(Ylo + (size_t)m0 * COUT + n)       = ll0;
                *reinterpret_cast<__nv_bfloat162*>(Ylo + (size_t)(m0 + 8) * COUT + n) = ll1;
            }
        }
    }
}

// ---------------- fp16 two-split tensor conv (encoder), 16-warp version ------
template<int CIN, int KW, int COUT, bool WF32>
__global__ void __launch_bounds__(512)
tconvh(const half* __restrict__ Ah, const half* __restrict__ Am,
       const half* __restrict__ Wh, const half* __restrict__ Wm,
       const float* __restrict__ Bias, float* __restrict__ Yf,
       half* __restrict__ Yh, half* __restrict__ Ym)
{
    constexpr int KTOT = CIN * KW;
    constexpr int NCH  = KTOT / 64;
    constexpr int PAD  = (KW == 3) ? 1 : 0;

    extern __shared__ char smem[];
    const int tid = threadIdx.x;
    const int pm0 = blockIdx.x * 128;
    const int nv0 = blockIdx.y * 128;

    const int wid = tid >> 5, lane = tid & 31;
    const int wm = (wid >> 2) * 32;
    const int wn = (wid & 3) * 32;
    const int lr = lane & 7, lq = lane >> 3;

    float acc1[2][4][4];
    float acc2[2][4][4];
#pragma unroll
    for (int mi = 0; mi < 2; mi++)
#pragma unroll
        for (int ni = 0; ni < 4; ni++)
#pragma unroll
            for (int e = 0; e < 4; e++) { acc1[mi][ni][e] = 0.f; acc2[mi][ni][e] = 0.f; }

    const uint4* A4h = reinterpret_cast<const uint4*>(Ah);
    const uint4* A4m = reinterpret_cast<const uint4*>(Am);
    const uint4* B4h = reinterpret_cast<const uint4*>(Wh);
    const uint4* B4m = reinterpret_cast<const uint4*>(Wm);

    const uint32_t sb = smem_to_u32(smem);

    auto load_chunk = [&](int ch, int buf) {
        const uint32_t bo = (uint32_t)buf * 65536u;
        const int tap = (ch * 64) / CIN;
        const int ci0 = (ch * 64) % CIN;
#pragma unroll
        for (int i = 0; i < 2; i++) {
            int idx = tid + i * 512;
            int row = idx >> 3, c = idx & 7;
            int p = pm0 + row;
            bool ok = true;
            if (KW == 3) {
                int ls = (p & (LSEQ - 1)) + tap - PAD;
                ok = ((unsigned)ls < (unsigned)LSEQ);
            }
            size_t gi = ok ? ((size_t)(p + tap - PAD) * (CIN / 8) + (ci0 / 8) + c) : 0;
            int nb = ok ? 16 : 0;
            int pc = (c ^ row) & 7;
            uint32_t so = (uint32_t)(row * 128 + pc * 16);
            cp_async16(sb + bo + so,          A4h + gi, nb);
            cp_async16(sb + bo + 16384u + so, A4m + gi, nb);
        }
#pragma unroll
        for (int i = 0; i < 2; i++) {
            int idx = tid + i * 512;
            int row = idx >> 3, c = idx & 7;
            size_t gi = (size_t)(nv0 + row) * (KTOT / 8) + ch * 8 + c;
            int pc = (c ^ row) & 7;
            uint32_t so = (uint32_t)(row * 128 + pc * 16);
            cp_async16(sb + bo + 32768u + so, B4h + gi, 16);
            cp_async16(sb + bo + 49152u + so, B4m + gi, 16);
        }
        asm volatile("cp.async.commit_group;");
    };

    load_chunk(0, 0);
    if (1 < NCH) load_chunk(1, 1);

    for (int ch = 0; ch < NCH; ch++) {
        if (ch + 1 < NCH)
            asm volatile("cp.async.wait_group 1;");
        else
            asm volatile("cp.async.wait_group 0;");
        __syncthreads();
        if (ch + 2 < NCH) load_chunk(ch + 2, (ch + 2) % 3);

        const uint32_t bo = (uint32_t)(ch % 3) * 65536u;
        const uint32_t aHB = sb + bo;
        const uint32_t aMB = sb + bo + 16384u;
        const uint32_t bHB = sb + bo + 32768u;
        const uint32_t bMB = sb + bo + 49152u;
#pragma unroll
        for (int k16 = 0; k16 < 4; k16++) {
            const int kc0 = k16 * 2;
            uint32_t ah[2][4], am[2][4];
#pragma unroll
            for (int mi = 0; mi < 2; mi++) {
                int row = wm + mi * 16 + lr + (lq & 1) * 8;
                int kc  = kc0 + (lq >> 1);
                int pc  = (kc ^ row) & 7;
                ldsm_x4(ah[mi], aHB + row * 128 + pc * 16);
                ldsm_x4(am[mi], aMB + row * 128 + pc * 16);
            }
#pragma unroll
            for (int nc = 0; nc < 2; nc++) {
                uint32_t bh[4], bm[4];
                int row = wn + nc * 16 + lr + (lq >> 1) * 8;
                int kc  = kc0 + (lq & 1);
                int pc  = (kc ^ row) & 7;
                ldsm_x4(bh, bHB + row * 128 + pc * 16);
                ldsm_x4(bm, bMB + row * 128 + pc * 16);
                mma16816h(acc1[0][nc * 2 + 0], ah[0], bh[0], bh[1]);
                mma16816h(acc1[0][nc * 2 + 1], ah[0], bh[2], bh[3]);
                mma16816h(acc1[1][nc * 2 + 0], ah[1], bh[0], bh[1]);
                mma16816h(acc1[1][nc * 2 + 1], ah[1], bh[2], bh[3]);
                mma16816h(acc2[0][nc * 2 + 0], ah[0], bm[0], bm[1]);
                mma16816h(acc2[0][nc * 2 + 1], ah[0], bm[2], bm[3]);
                mma16816h(acc2[1][nc * 2 + 0], ah[1], bm[0], bm[1]);
                mma16816h(acc2[1][nc * 2 + 1], ah[1], bm[2], bm[3]);
                mma16816h(acc2[0][nc * 2 + 0], am[0], bh[0], bh[1]);
                mma16816h(acc2[0][nc * 2 + 1], am[0], bh[2], bh[3]);
                mma16816h(acc2[1][nc * 2 + 0], am[1], bh[0], bh[1]);
                mma16816h(acc2[1][nc * 2 + 1], am[1], bh[2], bh[3]);
            }
        }
    }

    const int gid = lane >> 2, tig = lane & 3;
#pragma unroll
    for (int mi = 0; mi < 2; mi++) {
        const int m0 = pm0 + wm + mi * 16 + gid;
#pragma unroll
        for (int ni = 0; ni < 4; ni++) {
            const int n = nv0 + wn + ni * 8 + tig * 2;
            const float2 bv = *reinterpret_cast<const float2*>(Bias + n);
            float v00 = fmaxf(fmaf(acc2[mi][ni][0], LO_INV, acc1[mi][ni][0]) + bv.x, 0.f);
            float v01 = fmaxf(fmaf(acc2[mi][ni][1], LO_INV, acc1[mi][ni][1]) + bv.y, 0.f);
            float v10 = fmaxf(fmaf(acc2[mi][ni][2], LO_INV, acc1[mi][ni][2]) + bv.x, 0.f);
            float v11 = fmaxf(fmaf(acc2[mi][ni][3], LO_INV, acc1[mi][ni][3]) + bv.y, 0.f);
            if (WF32) {
                float2 a0; a0.x = v00; a0.y = v01;
                float2 a1; a1.x = v10; a1.y = v11;
                *reinterpret_cast<float2*>(Yf + (size_t)m0 * COUT + n)       = a0;
                *reinterpret_cast<float2*>(Yf + (size_t)(m0 + 8) * COUT + n) = a1;
            } else {
                half h00,m00,h01,m01,h10,m10,h11,m11;
                split2h(v00,h00,m00); split2h(v01,h01,m01);
                split2h(v10,h10,m10); split2h(v11,h11,m11);
                __half2 p0, p1;
                p0.x=h00; p0.y=h01; p1.x=h10; p1.y=h11;
                *reinterpret_cast<__half2*>(Yh + (size_t)m0 * COUT + n)       = p0;
                *reinterpret_cast<__half2*>(Yh + (size_t)(m0 + 8) * COUT + n) = p1;
                p0.x=m00; p0.y=m01; p1.x=m10; p1.y=m11;
                *reinterpret_cast<__half2*>(Ym + (size_t)m0 * COUT + n)       = p0;
                *reinterpret_cast<__half2*>(Ym + (size_t)(m0 + 8) * COUT + n) = p1;
            }
        }
    }
}

// ---------------- encoder head: fp16x3 GEMM [128x64, K=256] + fused LN(64) ---
__global__ void __launch_bounds__(256)
head_mma_ln(const half* __restrict__ Ah, const half* __restrict__ Am,
            const half* __restrict__ Wh, const half* __restrict__ Wm,
            const float* __restrict__ Bias,
            const float* __restrict__ G, const float* __restrict__ Bt,
            float* __restrict__ Z)
{
    extern __shared__ char smem[];
    const int tid = threadIdx.x;
    const int pm0 = blockIdx.x * 128;
    const uint32_t sb = smem_to_u32(smem);

    {
        const uint4* A4h = reinterpret_cast<const uint4*>(Ah);
        const uint4* A4m = reinterpret_cast<const uint4*>(Am);
#pragma unroll
        for (int i = 0; i < 16; i++) {
            int idx = tid + i * 256;
            int row = idx >> 5, c = idx & 31;
            int pc = (c & 24) | ((c ^ row) & 7);
            uint32_t so = (uint32_t)(row * 512 + pc * 16);
            size_t gi = (size_t)(pm0 + row) * 32 + c;
            cp_async16(sb + so,          A4h + gi, 16);
            cp_async16(sb + 65536u + so, A4m + gi, 16);
        }
        const uint4* B4h = reinterpret_cast<const uint4*>(Wh);
        const uint4* B4m = reinterpret_cast<const uint4*>(Wm);
#pragma unroll
        for (int i = 0; i < 8; i++) {
            int idx = tid + i * 256;
            int row = idx >> 5, c = idx & 31;
            int pc = (c & 24) | ((c ^ row) & 7);
            uint32_t so = (uint32_t)(row * 512 + pc * 16);
            size_t gi = (size_t)row * 32 + c;
            cp_async16(sb + 131072u + so, B4h + gi, 16);
            cp_async16(sb + 163840u + so, B4m + gi, 16);
        }
        asm volatile("cp.async.commit_group;");
    }

    const int wid = tid >> 5, lane = tid & 31;
    const int wm = wid * 16;
    const int lr = lane & 7, lq = lane >> 3;

    float acc1[8][4], acc2[8][4];
#pragma unroll
    for (int ni = 0; ni < 8; ni++)
#pragma unroll
        for (int e = 0; e < 4; e++) { acc1[ni][e] = 0.f; acc2[ni][e] = 0.f; }

    asm volatile("cp.async.wait_group 0;");
    __syncthreads();

#pragma unroll
    for (int k16 = 0; k16 < 16; k16++) {
        const int kc0 = k16 * 2;
        uint32_t ah[4], am[4];
        {
            int row = wm + lr + (lq & 1) * 8;
            int kc  = kc0 + (lq >> 1);
            int pc  = (kc & 24) | ((kc ^ row) & 7);
            ldsm_x4(ah, sb + row * 512 + pc * 16);
            ldsm_x4(am, sb + 65536u + row * 512 + pc * 16);
        }
#pragma unroll
        for (int nc = 0; nc < 4; nc++) {
            uint32_t bh[4], bm[4];
            int row = nc * 16 + lr + (lq >> 1) * 8;
            int kc  = kc0 + (lq & 1);
            int pc  = (kc & 24) | ((kc ^ row) & 7);
            ldsm_x4(bh, sb + 131072u + row * 512 + pc * 16);
            ldsm_x4(bm, sb + 163840u + row * 512 + pc * 16);
            mma16816h(acc1[nc * 2 + 0], ah, bh[0], bh[1]);
            mma16816h(acc1[nc * 2 + 1], ah, bh[2], bh[3]);
            mma16816h(acc2[nc * 2 + 0], ah, bm[0], bm[1]);
            mma16816h(acc2[nc * 2 + 1], ah, bm[2], bm[3]);
            mma16816h(acc2[nc * 2 + 0], am, bh[0], bh[1]);
            mma16816h(acc2[nc * 2 + 1], am, bh[2], bh[3]);
        }
    }

    const int gid = lane >> 2, tig = lane & 3;
    float v[8][4];
#pragma unroll
    for (int ni = 0; ni < 8; ni++) {
        const int n = ni * 8 + tig * 2;
        const float2 bv = *reinterpret_cast<const float2*>(Bias + n);
        v[ni][0] = fmaf(acc2[ni][0], LO_INV, acc1[ni][0]) + bv.x;
        v[ni][1] = fmaf(acc2[ni][1], LO_INV, acc1[ni][1]) + bv.y;
        v[ni][2] = fmaf(acc2[ni][2], LO_INV, acc1[ni][2]) + bv.x;
        v[ni][3] = fmaf(acc2[ni][3], LO_INV, acc1[ni][3]) + bv.y;
    }
    float s0 = 0.f, s1 = 0.f;
#pragma unroll
    for (int ni = 0; ni < 8; ni++) { s0 += v[ni][0] + v[ni][1]; s1 += v[ni][2] + v[ni][3]; }
    s0 += __shfl_xor_sync(0xffffffffu, s0, 1);  s0 += __shfl_xor_sync(0xffffffffu, s0, 2);
    s1 += __shfl_xor_sync(0xffffffffu, s1, 1);  s1 += __shfl_xor_sync(0xffffffffu, s1, 2);
    float mu0 = s0 * (1.f / 64.f), mu1 = s1 * (1.f / 64.f);
    float q0 = 0.f, q1 = 0.f;
#pragma unroll
    for (int ni = 0; ni < 8; ni++) {
        float d0 = v[ni][0] - mu0, d1 = v[ni][1] - mu0;
        float d2 = v[ni][2] - mu1, d3 = v[ni][3] - mu1;
        q0 += d0 * d0 + d1 * d1;
        q1 += d2 * d2 + d3 * d3;
    }
    q0 += __shfl_xor_sync(0xffffffffu, q0, 1);  q0 += __shfl_xor_sync(0xffffffffu, q0, 2);
    q1 += __shfl_xor_sync(0xffffffffu, q1, 1);  q1 += __shfl_xor_sync(0xffffffffu, q1, 2);
    float rs0 = rsqrtf(q0 * (1.f / 64.f) + LN_EPS);
    float rs1 = rsqrtf(q1 * (1.f / 64.f) + LN_EPS);

    const int r0 = pm0 + wm + gid, r1 = r0 + 8;
#pragma unroll
    for (int ni = 0; ni < 8; ni++) {
        const int c = ni * 8 + tig * 2;
        const float2 gv = *reinterpret_cast<const float2*>(G + c);
        const float2 bb = *reinterpret_cast<const float2*>(Bt + c);
        float2 o0, o1;
        o0.x = (v[ni][0] - mu0) * rs0 * gv.x + bb.x;
        o0.y = (v[ni][1] - mu0) * rs0 * gv.y + bb.y;
        o1.x = (v[ni][2] - mu1) * rs1 * gv.x + bb.x;
        o1.y = (v[ni][3] - mu1) * rs1 * gv.y + bb.y;
        *reinterpret_cast<float2*>(Z + (size_t)r0 * 64 + c) = o0;
        *reinterpret_cast<float2*>(Z + (size_t)r1 * 64 + c) = o1;
    }
}

// ---------------- wide full-K-resident bf16x3 logits GEMM, 16-warp -----------
#define LGW_SMEM 196608

__global__ void __launch_bounds__(512, 1)
logits_wide(const bf16* __restrict__ Ahi, const bf16* __restrict__ Alo,
            const bf16* __restrict__ Bhi, const bf16* __restrict__ Blo,
            const float* __restrict__ Bias, float* __restrict__ Out)
{
    extern __shared__ char smem[];
    const int tid = threadIdx.x;
    const int pm0 = blockIdx.x * 128;
    const int nv0 = blockIdx.y * 256;

    const uint32_t sb = smem_to_u32(smem);

    {
        const uint4* A4h = reinterpret_cast<const uint4*>(Ahi);
        const uint4* A4l = reinterpret_cast<const uint4*>(Alo);
#pragma unroll
        for (int i = 0; i < 4; i++) {
            int idx = tid + i * 512;
            int row = idx >> 4, c = idx & 15;
            int pc = (c & 8) | ((c ^ row) & 7);
            cp_async16(sb + (uint32_t)(row * 256 + pc * 16),
                       A4h + (size_t)(pm0 + row) * 16 + c, 16);
            cp_async16(sb + 32768u + (uint32_t)(row * 256 + pc * 16),
                       A4l + (size_t)(pm0 + row) * 16 + c, 16);
        }
        const uint4* B4h = reinterpret_cast<const uint4*>(Bhi);
        const uint4* B4l = reinterpret_cast<const uint4*>(Blo);
#pragma unroll
        for (int i = 0; i < 8; i++) {
            int idx = tid + i * 512;
            int row = idx >> 4, c = idx & 15;
            int pc = (c & 8) | ((c ^ row) & 7);
            cp_async16(sb + 65536u + (uint32_t)(row * 256 + pc * 16),
                       B4h + (size_t)(nv0 + row) * 16 + c, 16);
            cp_async16(sb + 131072u + (uint32_t)(row * 256 + pc * 16),
                       B4l + (size_t)(nv0 + row) * 16 + c, 16);
        }
        asm volatile("cp.async.commit_group;");
    }

    const int wid = tid >> 5, lane = tid & 31;
    const int wm = (wid >> 2) * 32;       // 0,32,64,96
    const int wn = (wid & 3) * 64;        // 0,64,128,192
    const int lr = lane & 7, lq = lane >> 3;

    float acc[2][8][4];
#pragma unroll
    for (int mi = 0; mi < 2; mi++)
#pragma unroll
        for (int ni = 0; ni < 8; ni++)
#pragma unroll
            for (int e = 0; e < 4; e++) acc[mi][ni][e] = 0.f;

    asm volatile("cp.async.wait_group 0;");
    __syncthreads();

#pragma unroll
    for (int k16 = 0; k16 < 8; k16++) {
        const int kc0 = k16 * 2;
        uint32_t ah[2][4], al[2][4];
#pragma unroll
        for (int mi = 0; mi < 2; mi++) {
            int row = wm + mi * 16 + lr + (lq & 1) * 8;
            int kc  = kc0 + (lq >> 1);
            int pc  = (kc & 8) | ((kc ^ row) & 7);
            ldsm_x4(ah[mi], sb + row * 256 + pc * 16);
            ldsm_x4(al[mi], sb + 32768u + row * 256 + pc * 16);
        }
#pragma unroll
        for (int nc = 0; nc < 4; nc++) {
            uint32_t bh[4], bl[4];
            int row = wn + nc * 16 + lr + (lq >> 1) * 8;
            int kc  = kc0 + (lq & 1);
            int pc  = (kc & 8) | ((kc ^ row) & 7);
            ldsm_x4(bh, sb + 65536u + row * 256 + pc * 16);
            ldsm_x4(bl, sb + 131072u + row * 256 + pc * 16);
            mma16816(acc[0][nc * 2 + 0], ah[0], bh[0], bh[1]);
            mma16816(acc[0][nc * 2 + 1], ah[0], bh[2], bh[3]);
            mma16816(acc[1][nc * 2 + 0], ah[1], bh[0], bh[1]);
            mma16816(acc[1][nc * 2 + 1], ah[1], bh[2], bh[3]);
            mma16816(acc[0][nc * 2 + 0], ah[0], bl[0], bl[1]);
            mma16816(acc[0][nc * 2 + 1], ah[0], bl[2], bl[3]);
            mma16816(acc[1][nc * 2 + 0], ah[1], bl[0], bl[1]);
            mma16816(acc[1][nc * 2 + 1], ah[1], bl[2], bl[3]);
            mma16816(acc[0][nc * 2 + 0], al[0], bh[0], bh[1]);
            mma16816(acc[0][nc * 2 + 1], al[0], bh[2], bh[3]);
            mma16816(acc[1][nc * 2 + 0], al[1], bh[0], bh[1]);
            mma16816(acc[1][nc * 2 + 1], al[1], bh[2], bh[3]);
        }
    }

    const int gid = lane >> 2, tig = lane & 3;
#pragma unroll
    for (int mi = 0; mi < 2; mi++) {
        const int m0 = pm0 + wm + mi * 16 + gid;
#pragma unroll
        for (int ni = 0; ni < 8; ni++) {
            const int n = nv0 + wn + ni * 8 + tig * 2;
            const float2 bv = *reinterpret_cast<const float2*>(Bias + n);
            float2 v0, v1;
            v0.x = acc[mi][ni][0] + bv.x;  v0.y = acc[mi][ni][1] + bv.y;
            v1.x = acc[mi][ni][2] + bv.x;  v1.y = acc[mi][ni][3] + bv.y;
            *reinterpret_cast<float2*>(Out + (size_t)m0 * VOCAB + n)       = v0;
            *reinterpret_cast<float2*>(Out + (size_t)(m0 + 8) * VOCAB + n) = v1;
        }
    }
}

// ---------------- tail: loss scalar + codes ----------------------------------
__global__ void commit_final(const float* __restrict__ Part, float* __restrict__ slot)
{
    if (threadIdx.x == 0 && blockIdx.x == 0) {
        float s = 0.f;
        for (int i = 0; i < NPOS / 64; i++) s += Part[i];
        *slot = 0.1f * s / ((float)NPOS * (float)DDIM);
    }
}

__global__ void write_codes(const int* __restrict__ codes, float* __restrict__ out)
{
    int n = blockIdx.x * blockDim.x + threadIdx.x;
    if (n < NPOS) out[n] = (float)codes[n];
}

// ---------------- launch ------------------------------------------------------
extern "C" void kernel_launch(void* const* d_in, const int* in_sizes, int n_in,
                              void* d_out, int out_size)
{
    (void)in_sizes; (void)n_in;
    const int*   x    = (const int*)  d_in[0];
    const float* tok  = (const float*)d_in[1];
    const float* ew1  = (const float*)d_in[2];
    const float* eb1  = (const float*)d_in[3];
    const float* ew2  = (const float*)d_in[4];
    const float* eb2  = (const float*)d_in[5];
    const float* ew3  = (const float*)d_in[6];
    const float* eb3  = (const float*)d_in[7];
    const float* elg  = (const float*)d_in[8];
    const float* elb  = (const float*)d_in[9];
    const float* cb   = (const float*)d_in[10];
    const float* dw1  = (const float*)d_in[11];
    const float* db1  = (const float*)d_in[12];
    const float* dw2  = (const float*)d_in[13];
    const float* db2  = (const float*)d_in[14];
    const float* dw3  = (const float*)d_in[15];
    const float* db3  = (const float*)d_in[16];
    const float* dlg  = (const float*)d_in[17];
    const float* dlb  = (const float*)d_in[18];
    const float* ow   = (const float*)d_in[19];
    const float* ob   = (const float*)d_in[20];
    float* out = (float*)d_out;

    float *z, *cn, *cp;
    int* codes;
    half *ebh,*ebm,*e1h,*e1m,*e2h,*e2m,*w1eh,*w1em,*w2eh,*w2em,*w3eh,*w3em;
    bf16 *cbhi,*cblo,*d1hi,*d1lo,*d2hi,*d2lo,*ahi,*alo;
    bf16 *w1hi,*w1lo,*w2hi,*w2lo,*w3hi,*w3lo,*bhi,*blo;
    cudaGetSymbolAddress((void**)&z,     g_z);
    cudaGetSymbolAddress((void**)&codes, g_codes);
    cudaGetSymbolAddress((void**)&cn,    g_cnorm);
    cudaGetSymbolAddress((void**)&cp,    g_commit);
    cudaGetSymbolAddress((void**)&ebh,   g_ebh);
    cudaGetSymbolAddress((void**)&ebm,   g_ebm);
    cudaGetSymbolAddress((void**)&e1h,   g_e1h);
    cudaGetSymbolAddress((void**)&e1m,   g_e1m);
    cudaGetSymbolAddress((void**)&e2h,   g_e2h);
    cudaGetSymbolAddress((void**)&e2m,   g_e2m);
    cudaGetSymbolAddress((void**)&w1eh,  g_w1eh);
    cudaGetSymbolAddress((void**)&w1em,  g_w1em);
    cudaGetSymbolAddress((void**)&w2eh,  g_w2eh);
    cudaGetSymbolAddress((void**)&w2em,  g_w2em);
    cudaGetSymbolAddress((void**)&w3eh,  g_w3eh);
    cudaGetSymbolAddress((void**)&w3em,  g_w3em);
    cudaGetSymbolAddress((void**)&cbhi,  g_cbhi);
    cudaGetSymbolAddress((void**)&cblo,  g_cblo);
    cudaGetSymbolAddress((void**)&d1hi,  g_d1hi);
    cudaGetSymbolAddress((void**)&d1lo,  g_d1lo);
    cudaGetSymbolAddress((void**)&d2hi,  g_d2hi);
    cudaGetSymbolAddress((void**)&d2lo,  g_d2lo);
    cudaGetSymbolAddress((void**)&ahi,   g_ahi);
    cudaGetSymbolAddress((void**)&alo,   g_alo);
    cudaGetSymbolAddress((void**)&w1hi,  g_w1hi);
    cudaGetSymbolAddress((void**)&w1lo,  g_w1lo);
    cudaGetSymbolAddress((void**)&w2hi,  g_w2hi);
    cudaGetSymbolAddress((void**)&w2lo,  g_w2lo);
    cudaGetSymbolAddress((void**)&w3hi,  g_w3hi);
    cudaGetSymbolAddress((void**)&w3lo,  g_w3lo);
    cudaGetSymbolAddress((void**)&bhi,   g_bhi);
    cudaGetSymbolAddress((void**)&blo,   g_blo);

    cudaFuncSetAttribute((const void*)tconvh<128, 3, 256, false>,
                         cudaFuncAttributeMaxDynamicSharedMemorySize, TC_SMEM);
    cudaFuncSetAttribute((const void*)tconvh<256, 3, 256, false>,
                         cudaFuncAttributeMaxDynamicSharedMemorySize, TC_SMEM);
    cudaFuncSetAttribute((const void*)head_mma_ln,
                         cudaFuncAttributeMaxDynamicSharedMemorySize, TC_SMEM);
    cudaFuncSetAttribute((const void*)tconv< 64, 1, 256, true,  false, true,  false, true >,
                         cudaFuncAttributeMaxDynamicSharedMemorySize, TC_SMEM);
    cudaFuncSetAttribute((const void*)tconv<256, 3, 256, true,  false, true,  false, false>,
                         cudaFuncAttributeMaxDynamicSharedMemorySize, TC_SMEM);
    cudaFuncSetAttribute((const void*)tconv<256, 1, 128, true,  false, false, true,  false>,
                         cudaFuncAttributeMaxDynamicSharedMemorySize, TC_SMEM);
    cudaFuncSetAttribute((const void*)logits_wide,
                         cudaFuncAttributeMaxDynamicSharedMemorySize, LGW_SMEM);

    // ---- side stream for independent prep work (fork-join, capture-safe) ----
    cudaStream_t s2;
    cudaStreamCreateWithFlags(&s2, cudaStreamNonBlocking);
    cudaEvent_t eFork, eEnc, eJoin, eFork2, eJoin2;
    cudaEventCreateWithFlags(&eFork,  cudaEventDisableTiming);
    cudaEventCreateWithFlags(&eEnc,   cudaEventDisableTiming);
    cudaEventCreateWithFlags(&eJoin,  cudaEventDisableTiming);
    cudaEventCreateWithFlags(&eFork2, cudaEventDisableTiming);
    cudaEventCreateWithFlags(&eJoin2, cudaEventDisableTiming);

    cudaEventRecord(eFork, 0);
    cudaStreamWaitEvent(s2, eFork, 0);
    // side stream FIRST: encoder weight packs (needed soonest)
    pack_split2h<128, 3, 256><<<(256*384)  / 256, 256, 0, s2>>>(ew1, w1eh, w1em);
    pack_split2h<256, 3, 256><<<(256*768)  / 256, 256, 0, s2>>>(ew2, w2eh, w2em);
    pack_split2h<256, 1,  64><<<(64*256)   / 256, 256, 0, s2>>>(ew3, w3eh, w3em);
    cudaEventRecord(eEnc, s2);
    // side stream SECOND: decoder/vocab packs + codebook split + cnorm
    pack_split< 64, 1, KCODE><<<(KCODE*64) / 256, 256, 0, s2>>>(cb,  cbhi, cblo);
    pack_split< 64, 1, 256>  <<<(256*64)   / 256, 256, 0, s2>>>(dw1, w1hi, w1lo);
    pack_split<256, 3, 256>  <<<(256*768)  / 256, 256, 0, s2>>>(dw2, w2hi, w2lo);
    pack_split<256, 1, 128>  <<<(128*256)  / 256, 256, 0, s2>>>(dw3, w3hi, w3lo);
    pack_split<128, 1, VOCAB><<<(VOCAB*128)/ 256, 256, 0, s2>>>(ow,  bhi,  blo);
    cnorm_kernel<<<1, 512, 0, s2>>>(cb, cn);
    cudaEventRecord(eJoin, s2);

    // ---- main stream: embedding (independent) then encoder ----
    embed_split2h<<<NPOS * 32 / 256, 256>>>(x, tok, ebh, ebm);
    cudaStreamWaitEvent(0, eEnc, 0);           // only encoder packs needed here
    tconvh<128, 3, 256, false><<<dim3(NPOS/128, 2), 512, TC_SMEM>>>(
        ebh, ebm, w1eh, w1em, eb1, nullptr, e1h, e1m);
    tconvh<256, 3, 256, false><<<dim3(NPOS/128, 2), 512, TC_SMEM>>>(
        e1h, e1m, w2eh, w2em, eb2, nullptr, e2h, e2m);
    head_mma_ln<<<NPOS/128, 256, TC_SMEM>>>(e2h, e2m, w3eh, w3em, eb3, elg, elb, z);

    // join remaining side work (cnorm + decoder packs + codebook split)
    cudaStreamWaitEvent(0, eJoin, 0);

    // ---- vector quantization (codes only; decoder gathers via codes) ----
    vq_kernel<<<NPOS / 64, 256>>>(z, cb, cn, codes, cp);

    // ---- tail on side stream (depends only on VQ outputs) ----
    const long long NV = (long long)NPOS * VOCAB;   // 134217728
    cudaEventRecord(eFork2, 0);
    cudaStreamWaitEvent(s2, eFork2, 0);
    if ((long long)out_size >= NV + 1)
        commit_final<<<1, 32, 0, s2>>>(cp, out + NV);
    if ((long long)out_size >= NV + 1 + NPOS)
        write_codes<<<NPOS / 256, 256, 0, s2>>>(codes, out + NV + 1);
    cudaEventRecord(eJoin2, s2);

    // ---- decoder (bf16x3, 16-warp pipelined; conv1 gathers codebook rows) ----
    tconv< 64, 1, 256, true,  false, true,  false, true ><<<dim3(NPOS/128, 2), 512, TC_SMEM>>>(
        cbhi, cblo, w1hi, w1lo, db1, nullptr, nullptr, nullptr, d1hi, d1lo, codes);
    tconv<256, 3, 256, true,  false, true,  false, false><<<dim3(NPOS/128, 2), 512, TC_SMEM>>>(
        d1hi, d1lo, w2hi, w2lo, db2, nullptr, nullptr, nullptr, d2hi, d2lo, nullptr);
    tconv<256, 1, 128, true,  false, false, true,  false><<<dim3(NPOS/128, 1), 512, TC_SMEM>>>(
        d2hi, d2lo, w3hi, w3lo, db3, dlg, dlb, nullptr, ahi, alo, nullptr);

    // ---- vocab projection (wide full-K bf16x3, 16-warp) -> d_out ----
    logits_wide<<<dim3(NPOS/128, VOCAB/256), 512, LGW_SMEM>>>(
        ahi, alo, bhi, blo, ob, out);

    // join side-stream tail back into the main stream before capture ends
    cudaStreamWaitEvent(0, eJoin2, 0);

    cudaEventDestroy(eFork);
    cudaEventDestroy(eEnc);
    cudaEventDestroy(eJoin);
    cudaEventDestroy(eFork2);
    cudaEventDestroy(eJoin2);
    cudaStreamDestroy(s2);
}